// round 5
// baseline (speedup 1.0000x reference)
#include <cuda_runtime.h>

// ---------------------------------------------------------------------------
// GraphPooling: 3-layer GAT (single head) + final projection, fp32.
// Round 5: double-buffered SGEMM with fused alpha epilogue + merged
//          attention/aggregation kernel (warp per node, shfl-broadcast).
// ---------------------------------------------------------------------------

#define NMAX 50000
#define EMAX 800000
#define FMAX 128

__device__ float g_hbuf  [NMAX * FMAX];
__device__ float g_actbuf[NMAX * FMAX];
__device__ float g_as   [NMAX];
__device__ float g_ad   [NMAX];
__device__ float g_ew   [EMAX];           // raw edge scores (CSR order)
__device__ int   g_csrc [EMAX];
__device__ int   g_rp   [NMAX + 1];
__device__ int   g_cur  [NMAX];
__device__ int   g_cnt  [NMAX];
__device__ float g_ST   [64 * 512];

__device__ __forceinline__ float leaky02(float v) { return v > 0.f ? v : 0.2f * v; }

// ---------------------------------------------------------------------------
// Double-buffered SGEMM: C[M,Ncols] = A[M,K] @ B[K,Ncols].
// If ALPHA: also emits oas[r] = C_row . avs, oad[r] = C_row . avd
// (requires BN == Ncols, grid.y == 1).
// ---------------------------------------------------------------------------
template<int BM, int BN, int BK, int TM, int TN, bool ALPHA>
__global__ void __launch_bounds__((BM/TM)*(BN/TN))
sgemm_kernel(const float* __restrict__ A, const float* __restrict__ B,
             float* __restrict__ C,
             const float* __restrict__ avs, const float* __restrict__ avd,
             float* __restrict__ oas, float* __restrict__ oad,
             int M, int Ncols, int K)
{
    constexpr int THREADS = (BM/TM) * (BN/TN);
    constexpr int TCOLS   = BN / TN;
    constexpr int A_PER   = (BM * BK / 4) / THREADS;
    constexpr int B_PER   = (BK * BN / 4) / THREADS;

    __shared__ float As[2][BK][BM];
    __shared__ float Bs[2][BK][BN];

    const int tid  = threadIdx.x;
    const int m0   = blockIdx.x * BM;
    const int n0   = blockIdx.y * BN;
    const int tcol = tid % TCOLS;
    const int trow = tid / TCOLS;

    float4 areg[A_PER], breg[B_PER];
    float acc[TM][TN];
#pragma unroll
    for (int i = 0; i < TM; i++)
#pragma unroll
        for (int j = 0; j < TN; j++) acc[i][j] = 0.f;

    // ---- load tile 0 into registers ----
#pragma unroll
    for (int i = 0; i < A_PER; i++) {
        int idx = tid + i * THREADS;
        int row = idx / (BK / 4);
        int kq  = idx % (BK / 4);
        int gr  = m0 + row;
        areg[i] = make_float4(0.f, 0.f, 0.f, 0.f);
        if (gr < M) areg[i] = *(const float4*)(A + (size_t)gr * K + kq * 4);
    }
#pragma unroll
    for (int i = 0; i < B_PER; i++) {
        int idx = tid + i * THREADS;
        int row = idx / (BN / 4);
        int c4  = idx % (BN / 4);
        breg[i] = *(const float4*)(B + (size_t)row * Ncols + n0 + c4 * 4);
    }
    // ---- store tile 0 to smem buf 0 ----
#pragma unroll
    for (int i = 0; i < A_PER; i++) {
        int idx = tid + i * THREADS;
        int row = idx / (BK / 4);
        int kq  = idx % (BK / 4);
        As[0][kq*4+0][row] = areg[i].x;
        As[0][kq*4+1][row] = areg[i].y;
        As[0][kq*4+2][row] = areg[i].z;
        As[0][kq*4+3][row] = areg[i].w;
    }
#pragma unroll
    for (int i = 0; i < B_PER; i++) {
        int idx = tid + i * THREADS;
        int row = idx / (BN / 4);
        int c4  = idx % (BN / 4);
        *(float4*)&Bs[0][row][c4 * 4] = breg[i];
    }
    __syncthreads();

    const int T = K / BK;
    for (int t = 0; t < T; t++) {
        int buf = t & 1;
        // prefetch next tile to registers
        if (t + 1 < T) {
            int k0 = (t + 1) * BK;
#pragma unroll
            for (int i = 0; i < A_PER; i++) {
                int idx = tid + i * THREADS;
                int row = idx / (BK / 4);
                int kq  = idx % (BK / 4);
                int gr  = m0 + row;
                areg[i] = make_float4(0.f, 0.f, 0.f, 0.f);
                if (gr < M) areg[i] = *(const float4*)(A + (size_t)gr * K + k0 + kq * 4);
            }
#pragma unroll
            for (int i = 0; i < B_PER; i++) {
                int idx = tid + i * THREADS;
                int row = idx / (BN / 4);
                int c4  = idx % (BN / 4);
                breg[i] = *(const float4*)(B + (size_t)(k0 + row) * Ncols + n0 + c4 * 4);
            }
        }
        // compute current tile
#pragma unroll
        for (int kk = 0; kk < BK; kk++) {
            float ar[TM], br[TN];
#pragma unroll
            for (int q = 0; q < TM / 4; q++) {
                float4 a = *(const float4*)&As[buf][kk][trow * TM + q * 4];
                ar[q*4+0] = a.x; ar[q*4+1] = a.y; ar[q*4+2] = a.z; ar[q*4+3] = a.w;
            }
#pragma unroll
            for (int q = 0; q < TN / 4; q++) {
                float4 b = *(const float4*)&Bs[buf][kk][tcol * TN + q * 4];
                br[q*4+0] = b.x; br[q*4+1] = b.y; br[q*4+2] = b.z; br[q*4+3] = b.w;
            }
#pragma unroll
            for (int i = 0; i < TM; i++)
#pragma unroll
                for (int j = 0; j < TN; j++)
                    acc[i][j] = fmaf(ar[i], br[j], acc[i][j]);
        }
        // stage next tile into the other smem buffer
        if (t + 1 < T) {
            int nb = buf ^ 1;
#pragma unroll
            for (int i = 0; i < A_PER; i++) {
                int idx = tid + i * THREADS;
                int row = idx / (BK / 4);
                int kq  = idx % (BK / 4);
                As[nb][kq*4+0][row] = areg[i].x;
                As[nb][kq*4+1][row] = areg[i].y;
                As[nb][kq*4+2][row] = areg[i].z;
                As[nb][kq*4+3][row] = areg[i].w;
            }
#pragma unroll
            for (int i = 0; i < B_PER; i++) {
                int idx = tid + i * THREADS;
                int row = idx / (BN / 4);
                int c4  = idx % (BN / 4);
                *(float4*)&Bs[nb][row][c4 * 4] = breg[i];
            }
            __syncthreads();
        }
    }

    // ---- epilogue: store C (+ fused alpha dots) ----
    float ps[TM], pd[TM];
#pragma unroll
    for (int i = 0; i < TM; i++) { ps[i] = 0.f; pd[i] = 0.f; }

#pragma unroll
    for (int i = 0; i < TM; i++) {
        int gr = m0 + trow * TM + i;
        if (gr < M) {
#pragma unroll
            for (int q = 0; q < TN / 4; q++) {
                float4 v = make_float4(acc[i][q*4+0], acc[i][q*4+1],
                                       acc[i][q*4+2], acc[i][q*4+3]);
                *(float4*)(C + (size_t)gr * Ncols + n0 + tcol * TN + q * 4) = v;
            }
        }
        if (ALPHA) {
#pragma unroll
            for (int j = 0; j < TN; j++) {
                float vs = __ldg(&avs[tcol * TN + j]);
                float vd = __ldg(&avd[tcol * TN + j]);
                ps[i] = fmaf(acc[i][j], vs, ps[i]);
                pd[i] = fmaf(acc[i][j], vd, pd[i]);
            }
        }
    }
    if (ALPHA) {
        // reduce across the TCOLS lanes of each row group (lane-aligned)
#pragma unroll
        for (int off = 1; off < TCOLS; off <<= 1) {
#pragma unroll
            for (int i = 0; i < TM; i++) {
                ps[i] += __shfl_xor_sync(0xffffffffu, ps[i], off);
                pd[i] += __shfl_xor_sync(0xffffffffu, pd[i], off);
            }
        }
        if (tcol == 0) {
#pragma unroll
            for (int i = 0; i < TM; i++) {
                int gr = m0 + trow * TM + i;
                if (gr < M) { oas[gr] = ps[i]; oad[gr] = pd[i]; }
            }
        }
    }
}

// ---------------------------------------------------------------------------
// CSR build
// ---------------------------------------------------------------------------
__global__ void zero_cnt_kernel(int* __restrict__ cnt, int N)
{
    int i = blockIdx.x * blockDim.x + threadIdx.x;
    if (i < N) cnt[i] = 0;
}

__global__ void hist_kernel(const int* __restrict__ ei, int* __restrict__ cnt, int E)
{
    int e = blockIdx.x * blockDim.x + threadIdx.x;
    if (e < E) atomicAdd(&cnt[ei[E + e]], 1);
}

__global__ void __launch_bounds__(1024)
scan_kernel(const int* __restrict__ cnt, int* __restrict__ rp,
            int* __restrict__ cur, int N)
{
    __shared__ int sh[1024];
    int t = threadIdx.x;
    int IT = (N + 1023) / 1024;
    int base = t * IT;

    int sum = 0;
    for (int k = 0; k < IT; k++) {
        int idx = base + k;
        if (idx < N) sum += cnt[idx];
    }
    sh[t] = sum;
    __syncthreads();
    for (int off = 1; off < 1024; off <<= 1) {
        int v = (t >= off) ? sh[t - off] : 0;
        __syncthreads();
        sh[t] += v;
        __syncthreads();
    }
    int run = sh[t] - sum;
    for (int k = 0; k < IT; k++) {
        int idx = base + k;
        if (idx < N) {
            rp[idx]  = run;
            cur[idx] = run;
            run += cnt[idx];
        }
    }
    if (t == 1023) rp[N] = sh[1023];
}

__global__ void scatter_kernel(const int* __restrict__ ei, int* __restrict__ cur,
                               int* __restrict__ csrc, int E)
{
    int e = blockIdx.x * blockDim.x + threadIdx.x;
    if (e < E) {
        int d = ei[E + e];
        int pos = atomicAdd(&cur[d], 1);
        csrc[pos] = ei[e];
    }
}

// ---------------------------------------------------------------------------
// Merged attention + aggregation. One warp per node.
// Phase 1: raw scores -> ew[], running max.
// Phase 2: 32-edge chunks; each lane exponentiates one edge, then a
//          shfl-broadcast inner loop gathers h[src] rows into registers.
// Fused: self-loop, 1/den, bias, activation.
// ---------------------------------------------------------------------------
template<int F>
__global__ void attn_agg_kernel(const int* __restrict__ rp,
                                const int* __restrict__ csrc,
                                const float* __restrict__ as_,
                                const float* __restrict__ ad_,
                                float* __restrict__ ew,
                                const float* __restrict__ h,
                                const float* __restrict__ bias,
                                float* __restrict__ out, int N, int do_leaky)
{
    constexpr int LPN = F / 4;   // lanes carrying features
    int node = (blockIdx.x * blockDim.x + threadIdx.x) >> 5;
    int lane = threadIdx.x & 31;
    if (node >= N) return;

    int j0 = rp[node], j1 = rp[node + 1];
    float add   = ad_[node];
    float vself = leaky02(as_[node] + add);
    float mx = vself;

    for (int j = j0 + lane; j < j1; j += 32) {
        float v = leaky02(__ldg(&as_[csrc[j]]) + add);
        ew[j] = v;
        mx = fmaxf(mx, v);
    }
#pragma unroll
    for (int o = 16; o; o >>= 1)
        mx = fmaxf(mx, __shfl_xor_sync(0xffffffffu, mx, o));

    float ws = expf(vself - mx);

    float ax = 0.f, ay = 0.f, az = 0.f, aw = 0.f;
    if (lane < LPN) {
        float4 hv = *(const float4*)(h + (size_t)node * F + lane * 4);
        ax = ws * hv.x; ay = ws * hv.y; az = ws * hv.z; aw = ws * hv.w;
    }

    float sum = 0.f;
    for (int c = j0; c < j1; c += 32) {
        int jj = c + lane;
        float w = 0.f;
        int   s = 0;
        if (jj < j1) {
            w = expf(ew[jj] - mx);
            s = csrc[jj];
        }
        sum += w;
        int cnt = min(32, j1 - c);
        for (int k = 0; k < cnt; k++) {
            float wk = __shfl_sync(0xffffffffu, w, k);
            int   sk = __shfl_sync(0xffffffffu, s, k);
            if (lane < LPN) {
                float4 v = *(const float4*)(h + (size_t)sk * F + lane * 4);
                ax = fmaf(wk, v.x, ax);
                ay = fmaf(wk, v.y, ay);
                az = fmaf(wk, v.z, az);
                aw = fmaf(wk, v.w, aw);
            }
        }
    }
#pragma unroll
    for (int o = 16; o; o >>= 1)
        sum += __shfl_xor_sync(0xffffffffu, sum, o);

    if (lane < LPN) {
        float inv = 1.f / (sum + ws);
        float4 b = *(const float4*)(bias + lane * 4);
        float4 o;
        o.x = ax * inv + b.x;
        o.y = ay * inv + b.y;
        o.z = az * inv + b.z;
        o.w = aw * inv + b.w;
        if (do_leaky) {
            o.x = o.x > 0.f ? o.x : 0.1f * o.x;
            o.y = o.y > 0.f ? o.y : 0.1f * o.y;
            o.z = o.z > 0.f ? o.z : 0.1f * o.z;
            o.w = o.w > 0.f ? o.w : 0.1f * o.w;
        }
        *(float4*)(out + (size_t)node * F + lane * 4) = o;
    }
}

__global__ void transpose_S_kernel(const float* __restrict__ S, float* __restrict__ ST)
{
    int i = blockIdx.x * blockDim.x + threadIdx.x;
    if (i < 64 * 512) {
        int k = i / 512, n = i % 512;
        ST[i] = S[n * 64 + k];
    }
}

// ---------------------------------------------------------------------------
// Host
// ---------------------------------------------------------------------------
static inline int cdiv(int a, int b) { return (a + b - 1) / b; }

extern "C" void kernel_launch(void* const* d_in, const int* in_sizes, int n_in,
                              void* d_out, int out_size)
{
    const float* x   = (const float*)d_in[0];
    const int*   ei  = (const int*)d_in[1];   // int32 (JAX x64 disabled)
    const float* W1  = (const float*)d_in[2];
    const float* a1s = (const float*)d_in[3];
    const float* a1d = (const float*)d_in[4];
    const float* b1  = (const float*)d_in[5];
    const float* W2  = (const float*)d_in[6];
    const float* a2s = (const float*)d_in[7];
    const float* a2d = (const float*)d_in[8];
    const float* b2  = (const float*)d_in[9];
    const float* W3  = (const float*)d_in[10];
    const float* a3s = (const float*)d_in[11];
    const float* a3d = (const float*)d_in[12];
    const float* b3  = (const float*)d_in[13];
    const float* S   = (const float*)d_in[14];

    int N = in_sizes[0] / 128;
    int E = in_sizes[1] / 2;

    float *hb, *actb, *pas, *pad_, *pew, *pst;
    int *pcsrc, *prp, *pcur, *pcnt;
    cudaGetSymbolAddress((void**)&hb,    g_hbuf);
    cudaGetSymbolAddress((void**)&actb,  g_actbuf);
    cudaGetSymbolAddress((void**)&pas,   g_as);
    cudaGetSymbolAddress((void**)&pad_,  g_ad);
    cudaGetSymbolAddress((void**)&pew,   g_ew);
    cudaGetSymbolAddress((void**)&pst,   g_ST);
    cudaGetSymbolAddress((void**)&pcsrc, g_csrc);
    cudaGetSymbolAddress((void**)&prp,   g_rp);
    cudaGetSymbolAddress((void**)&pcur,  g_cur);
    cudaGetSymbolAddress((void**)&pcnt,  g_cnt);

    // --- CSR build ---
    zero_cnt_kernel<<<cdiv(N,256), 256>>>(pcnt, N);
    hist_kernel<<<cdiv(E,256), 256>>>(ei, pcnt, E);
    scan_kernel<<<1, 1024>>>(pcnt, prp, pcur, N);
    scatter_kernel<<<cdiv(E,256), 256>>>(ei, pcur, pcsrc, E);

    transpose_S_kernel<<<cdiv(64*512,256), 256>>>(S, pst);

    int gm = cdiv(N, 128);
    int gw = cdiv(N * 32, 256);

    // --- layer 1 ---
    sgemm_kernel<128,128,16,8,8,true><<<dim3(gm,1), 256>>>(x, W1, hb, a1s, a1d,
                                                           pas, pad_, N, 128, 128);
    attn_agg_kernel<128><<<gw, 256>>>(prp, pcsrc, pas, pad_, pew, hb, b1, actb, N, 1);

    // --- layer 2 ---
    sgemm_kernel<128,128,16,8,8,true><<<dim3(gm,1), 256>>>(actb, W2, hb, a2s, a2d,
                                                           pas, pad_, N, 128, 128);
    attn_agg_kernel<128><<<gw, 256>>>(prp, pcsrc, pas, pad_, pew, hb, b2, actb, N, 1);

    // --- layer 3 (F=64, no inter-layer activation) ---
    sgemm_kernel<128,64,16,8,8,true><<<dim3(gm,1), 128>>>(actb, W3, hb, a3s, a3d,
                                                          pas, pad_, N, 64, 128);
    attn_agg_kernel<64><<<gw, 256>>>(prp, pcsrc, pas, pad_, pew, hb, b3, actb, N, 0);

    // --- final projection: [N,64] @ [64,512] ---
    sgemm_kernel<128,128,16,8,8,false><<<dim3(gm,4), 256>>>(actb, pst, (float*)d_out,
                                                            nullptr, nullptr,
                                                            nullptr, nullptr,
                                                            N, 512, 64);
}

// round 6
// speedup vs baseline: 1.0794x; 1.0794x over previous
#include <cuda_runtime.h>

// ---------------------------------------------------------------------------
// GraphPooling: 3-layer GAT (single head) + final projection, fp32.
// Round 6: round-4 structure (CSR two-kernel edge phase, single-buffer SGEMM)
//          + fused alpha-dot epilogue in the SGEMM (deletes alpha_kernel).
// ---------------------------------------------------------------------------

#define NMAX 50000
#define EMAX 800000
#define FMAX 128

__device__ float g_hbuf  [NMAX * FMAX];
__device__ float g_actbuf[NMAX * FMAX];
__device__ float g_as   [NMAX];
__device__ float g_ad   [NMAX];
__device__ float g_den  [NMAX];
__device__ float g_wself[NMAX];
__device__ float g_ew   [EMAX];
__device__ int   g_csrc [EMAX];
__device__ int   g_rp   [NMAX + 1];
__device__ int   g_cur  [NMAX];
__device__ int   g_cnt  [NMAX];
__device__ float g_ST   [64 * 512];

__device__ __forceinline__ float leaky02(float v) { return v > 0.f ? v : 0.2f * v; }

// ---------------------------------------------------------------------------
// SGEMM: C[M,Ncols] = A[M,K] @ B[K,Ncols], 128-wide register tiling.
// If ALPHA: also emits oas[r] = C_row . avs, oad[r] = C_row . avd
// (requires BN == Ncols, grid.y == 1).
// ---------------------------------------------------------------------------
template<int BM, int BN, int BK, int TM, int TN, bool ALPHA>
__global__ void __launch_bounds__((BM/TM)*(BN/TN))
sgemm_kernel(const float* __restrict__ A, const float* __restrict__ B,
             float* __restrict__ C,
             const float* __restrict__ avs, const float* __restrict__ avd,
             float* __restrict__ oas, float* __restrict__ oad,
             int M, int Ncols, int K)
{
    constexpr int THREADS = (BM/TM) * (BN/TN);
    constexpr int TCOLS   = BN / TN;
    __shared__ float As[BK][BM];
    __shared__ float Bs[BK][BN];

    const int tid  = threadIdx.x;
    const int m0   = blockIdx.x * BM;
    const int n0   = blockIdx.y * BN;
    const int tcol = tid % TCOLS;
    const int trow = tid / TCOLS;

    float acc[TM][TN];
#pragma unroll
    for (int i = 0; i < TM; i++)
#pragma unroll
        for (int j = 0; j < TN; j++) acc[i][j] = 0.f;

    constexpr int A_PER = (BM * BK / 4) / THREADS;
    constexpr int B_PER = (BK * BN / 4) / THREADS;

    for (int k0 = 0; k0 < K; k0 += BK) {
#pragma unroll
        for (int i = 0; i < A_PER; i++) {
            int idx = tid + i * THREADS;
            int row = idx / (BK / 4);
            int kq  = idx % (BK / 4);
            int gr  = m0 + row;
            float4 v = make_float4(0.f, 0.f, 0.f, 0.f);
            if (gr < M) v = *(const float4*)(A + (size_t)gr * K + k0 + kq * 4);
            As[kq*4+0][row] = v.x;
            As[kq*4+1][row] = v.y;
            As[kq*4+2][row] = v.z;
            As[kq*4+3][row] = v.w;
        }
#pragma unroll
        for (int i = 0; i < B_PER; i++) {
            int idx = tid + i * THREADS;
            int row = idx / (BN / 4);
            int c4  = idx % (BN / 4);
            float4 v = *(const float4*)(B + (size_t)(k0 + row) * Ncols + n0 + c4 * 4);
            *(float4*)&Bs[row][c4 * 4] = v;
        }
        __syncthreads();

#pragma unroll
        for (int kk = 0; kk < BK; kk++) {
            float ar[TM], br[TN];
#pragma unroll
            for (int q = 0; q < TM / 4; q++) {
                float4 a = *(const float4*)&As[kk][trow * TM + q * 4];
                ar[q*4+0] = a.x; ar[q*4+1] = a.y; ar[q*4+2] = a.z; ar[q*4+3] = a.w;
            }
#pragma unroll
            for (int q = 0; q < TN / 4; q++) {
                float4 b = *(const float4*)&Bs[kk][tcol * TN + q * 4];
                br[q*4+0] = b.x; br[q*4+1] = b.y; br[q*4+2] = b.z; br[q*4+3] = b.w;
            }
#pragma unroll
            for (int i = 0; i < TM; i++)
#pragma unroll
                for (int j = 0; j < TN; j++)
                    acc[i][j] = fmaf(ar[i], br[j], acc[i][j]);
        }
        __syncthreads();
    }

    // ---- epilogue: store C (+ fused alpha dots) ----
    float ps[TM], pd[TM];
#pragma unroll
    for (int i = 0; i < TM; i++) { ps[i] = 0.f; pd[i] = 0.f; }

#pragma unroll
    for (int i = 0; i < TM; i++) {
        int gr = m0 + trow * TM + i;
        if (gr < M) {
#pragma unroll
            for (int q = 0; q < TN / 4; q++) {
                float4 v = make_float4(acc[i][q*4+0], acc[i][q*4+1],
                                       acc[i][q*4+2], acc[i][q*4+3]);
                *(float4*)(C + (size_t)gr * Ncols + n0 + tcol * TN + q * 4) = v;
            }
        }
        if (ALPHA) {
#pragma unroll
            for (int j = 0; j < TN; j++) {
                float vs = __ldg(&avs[tcol * TN + j]);
                float vd = __ldg(&avd[tcol * TN + j]);
                ps[i] = fmaf(acc[i][j], vs, ps[i]);
                pd[i] = fmaf(acc[i][j], vd, pd[i]);
            }
        }
    }
    if (ALPHA) {
#pragma unroll
        for (int off = 1; off < TCOLS; off <<= 1) {
#pragma unroll
            for (int i = 0; i < TM; i++) {
                ps[i] += __shfl_xor_sync(0xffffffffu, ps[i], off);
                pd[i] += __shfl_xor_sync(0xffffffffu, pd[i], off);
            }
        }
        if (tcol == 0) {
#pragma unroll
            for (int i = 0; i < TM; i++) {
                int gr = m0 + trow * TM + i;
                if (gr < M) { oas[gr] = ps[i]; oad[gr] = pd[i]; }
            }
        }
    }
}

// ---------------------------------------------------------------------------
// CSR build
// ---------------------------------------------------------------------------
__global__ void zero_cnt_kernel(int* __restrict__ cnt, int N)
{
    int i = blockIdx.x * blockDim.x + threadIdx.x;
    if (i < N) cnt[i] = 0;
}

__global__ void hist_kernel(const int* __restrict__ ei, int* __restrict__ cnt, int E)
{
    int e = blockIdx.x * blockDim.x + threadIdx.x;
    if (e < E) atomicAdd(&cnt[ei[E + e]], 1);
}

__global__ void __launch_bounds__(1024)
scan_kernel(const int* __restrict__ cnt, int* __restrict__ rp,
            int* __restrict__ cur, int N)
{
    __shared__ int sh[1024];
    int t = threadIdx.x;
    int IT = (N + 1023) / 1024;
    int base = t * IT;

    int sum = 0;
    for (int k = 0; k < IT; k++) {
        int idx = base + k;
        if (idx < N) sum += cnt[idx];
    }
    sh[t] = sum;
    __syncthreads();
    for (int off = 1; off < 1024; off <<= 1) {
        int v = (t >= off) ? sh[t - off] : 0;
        __syncthreads();
        sh[t] += v;
        __syncthreads();
    }
    int run = sh[t] - sum;
    for (int k = 0; k < IT; k++) {
        int idx = base + k;
        if (idx < N) {
            rp[idx]  = run;
            cur[idx] = run;
            run += cnt[idx];
        }
    }
    if (t == 1023) rp[N] = sh[1023];
}

__global__ void scatter_kernel(const int* __restrict__ ei, int* __restrict__ cur,
                               int* __restrict__ csrc, int E)
{
    int e = blockIdx.x * blockDim.x + threadIdx.x;
    if (e < E) {
        int d = ei[E + e];
        int pos = atomicAdd(&cur[d], 1);
        csrc[pos] = ei[e];
    }
}

// ---------------------------------------------------------------------------
// Per-node softmax over incoming edges (CSR). One warp per node.
// ---------------------------------------------------------------------------
__global__ void node_attn_kernel(const int* __restrict__ rp,
                                 const int* __restrict__ csrc,
                                 const float* __restrict__ as_,
                                 const float* __restrict__ ad_,
                                 float* __restrict__ ew,
                                 float* __restrict__ den,
                                 float* __restrict__ wself, int N)
{
    int node = (blockIdx.x * blockDim.x + threadIdx.x) >> 5;
    int lane = threadIdx.x & 31;
    if (node >= N) return;

    int j0 = rp[node], j1 = rp[node + 1];
    float add   = ad_[node];
    float vself = leaky02(as_[node] + add);
    float mx = vself;

    for (int j = j0 + lane; j < j1; j += 32) {
        float v = leaky02(as_[csrc[j]] + add);
        ew[j] = v;
        mx = fmaxf(mx, v);
    }
#pragma unroll
    for (int o = 16; o; o >>= 1)
        mx = fmaxf(mx, __shfl_xor_sync(0xffffffffu, mx, o));

    float sum = 0.f;
    for (int j = j0 + lane; j < j1; j += 32) {
        float w = expf(ew[j] - mx);
        ew[j] = w;
        sum += w;
    }
#pragma unroll
    for (int o = 16; o; o >>= 1)
        sum += __shfl_xor_sync(0xffffffffu, sum, o);

    if (lane == 0) {
        float ws = expf(vself - mx);
        den[node]   = sum + ws;
        wself[node] = ws;
    }
}

// ---------------------------------------------------------------------------
// CSR aggregation, fused with self-loop, normalization, bias, activation.
// ---------------------------------------------------------------------------
template<int F>
__global__ void agg_csr_kernel(const int* __restrict__ rp,
                               const int* __restrict__ csrc,
                               const float* __restrict__ ew,
                               const float* __restrict__ den,
                               const float* __restrict__ wself,
                               const float* __restrict__ h,
                               const float* __restrict__ bias,
                               float* __restrict__ out, int N, int do_leaky)
{
    constexpr int LPN = F / 4;
    constexpr int NPW = 32 / LPN;
    int lane = threadIdx.x & 31;
    int sub  = lane / LPN;
    int l    = lane % LPN;
    int node = ((blockIdx.x * blockDim.x + threadIdx.x) >> 5) * NPW + sub;
    if (node >= N) return;

    float ws = wself[node];
    float4 hv = *(const float4*)(h + (size_t)node * F + l * 4);
    float ax = ws * hv.x, ay = ws * hv.y, az = ws * hv.z, aw = ws * hv.w;

    int j0 = rp[node], j1 = rp[node + 1];
    for (int j = j0; j < j1; j++) {
        int   s = __ldg(&csrc[j]);
        float w = __ldg(&ew[j]);
        float4 v = *(const float4*)(h + (size_t)s * F + l * 4);
        ax = fmaf(w, v.x, ax);
        ay = fmaf(w, v.y, ay);
        az = fmaf(w, v.z, az);
        aw = fmaf(w, v.w, aw);
    }

    float inv = 1.f / den[node];
    float4 b = *(const float4*)(bias + l * 4);
    float4 o;
    o.x = ax * inv + b.x;
    o.y = ay * inv + b.y;
    o.z = az * inv + b.z;
    o.w = aw * inv + b.w;
    if (do_leaky) {
        o.x = o.x > 0.f ? o.x : 0.1f * o.x;
        o.y = o.y > 0.f ? o.y : 0.1f * o.y;
        o.z = o.z > 0.f ? o.z : 0.1f * o.z;
        o.w = o.w > 0.f ? o.w : 0.1f * o.w;
    }
    *(float4*)(out + (size_t)node * F + l * 4) = o;
}

__global__ void transpose_S_kernel(const float* __restrict__ S, float* __restrict__ ST)
{
    int i = blockIdx.x * blockDim.x + threadIdx.x;
    if (i < 64 * 512) {
        int k = i / 512, n = i % 512;
        ST[i] = S[n * 64 + k];
    }
}

// ---------------------------------------------------------------------------
// Host
// ---------------------------------------------------------------------------
static inline int cdiv(int a, int b) { return (a + b - 1) / b; }

extern "C" void kernel_launch(void* const* d_in, const int* in_sizes, int n_in,
                              void* d_out, int out_size)
{
    const float* x   = (const float*)d_in[0];
    const int*   ei  = (const int*)d_in[1];   // int32 (JAX x64 disabled)
    const float* W1  = (const float*)d_in[2];
    const float* a1s = (const float*)d_in[3];
    const float* a1d = (const float*)d_in[4];
    const float* b1  = (const float*)d_in[5];
    const float* W2  = (const float*)d_in[6];
    const float* a2s = (const float*)d_in[7];
    const float* a2d = (const float*)d_in[8];
    const float* b2  = (const float*)d_in[9];
    const float* W3  = (const float*)d_in[10];
    const float* a3s = (const float*)d_in[11];
    const float* a3d = (const float*)d_in[12];
    const float* b3  = (const float*)d_in[13];
    const float* S   = (const float*)d_in[14];

    int N = in_sizes[0] / 128;
    int E = in_sizes[1] / 2;

    float *hb, *actb, *pas, *pad_, *pden, *pws, *pew, *pst;
    int *pcsrc, *prp, *pcur, *pcnt;
    cudaGetSymbolAddress((void**)&hb,    g_hbuf);
    cudaGetSymbolAddress((void**)&actb,  g_actbuf);
    cudaGetSymbolAddress((void**)&pas,   g_as);
    cudaGetSymbolAddress((void**)&pad_,  g_ad);
    cudaGetSymbolAddress((void**)&pden,  g_den);
    cudaGetSymbolAddress((void**)&pws,   g_wself);
    cudaGetSymbolAddress((void**)&pew,   g_ew);
    cudaGetSymbolAddress((void**)&pst,   g_ST);
    cudaGetSymbolAddress((void**)&pcsrc, g_csrc);
    cudaGetSymbolAddress((void**)&prp,   g_rp);
    cudaGetSymbolAddress((void**)&pcur,  g_cur);
    cudaGetSymbolAddress((void**)&pcnt,  g_cnt);

    // --- CSR build ---
    zero_cnt_kernel<<<cdiv(N,256), 256>>>(pcnt, N);
    hist_kernel<<<cdiv(E,256), 256>>>(ei, pcnt, E);
    scan_kernel<<<1, 1024>>>(pcnt, prp, pcur, N);
    scatter_kernel<<<cdiv(E,256), 256>>>(ei, pcur, pcsrc, E);

    transpose_S_kernel<<<cdiv(64*512,256), 256>>>(S, pst);

    int gm = cdiv(N, 128);
    int gw = cdiv(N * 32, 256);

    // --- layer 1 ---
    sgemm_kernel<128,128,16,8,8,true><<<dim3(gm,1), 256>>>(x, W1, hb, a1s, a1d,
                                                           pas, pad_, N, 128, 128);
    node_attn_kernel<<<gw, 256>>>(prp, pcsrc, pas, pad_, pew, pden, pws, N);
    agg_csr_kernel<128><<<gw, 256>>>(prp, pcsrc, pew, pden, pws, hb, b1, actb, N, 1);

    // --- layer 2 ---
    sgemm_kernel<128,128,16,8,8,true><<<dim3(gm,1), 256>>>(actb, W2, hb, a2s, a2d,
                                                           pas, pad_, N, 128, 128);
    node_attn_kernel<<<gw, 256>>>(prp, pcsrc, pas, pad_, pew, pden, pws, N);
    agg_csr_kernel<128><<<gw, 256>>>(prp, pcsrc, pew, pden, pws, hb, b2, actb, N, 1);

    // --- layer 3 (F=64, no inter-layer activation) ---
    sgemm_kernel<128,64,16,8,8,true><<<dim3(gm,1), 128>>>(actb, W3, hb, a3s, a3d,
                                                          pas, pad_, N, 64, 128);
    node_attn_kernel<<<gw, 256>>>(prp, pcsrc, pas, pad_, pew, pden, pws, N);
    agg_csr_kernel<64><<<cdiv(N*16,256), 256>>>(prp, pcsrc, pew, pden, pws, hb, b3,
                                                actb, N, 0);

    // --- final projection: [N,64] @ [64,512] ---
    sgemm_kernel<128,128,16,8,8,false><<<dim3(gm,4), 256>>>(actb, pst, (float*)d_out,
                                                            nullptr, nullptr,
                                                            nullptr, nullptr,
                                                            N, 512, 64);
}

// round 7
// speedup vs baseline: 1.1462x; 1.0619x over previous
#include <cuda_runtime.h>
#include <cstdint>

// ---------------------------------------------------------------------------
// GraphPooling: 3-layer GAT (single head) + final projection.
// Round 7: all GEMMs on tensor cores (mma.sync m16n8k8 tf32, 3xTF32
//          error-compensated) with fused alpha epilogue.
//          Edge phase / CSR build unchanged from round 6 (428us config).
// ---------------------------------------------------------------------------

#define NMAX 50000
#define EMAX 800000
#define FMAX 128

__device__ float g_hbuf  [NMAX * FMAX];
__device__ float g_actbuf[NMAX * FMAX];
__device__ float g_as   [NMAX];
__device__ float g_ad   [NMAX];
__device__ float g_den  [NMAX];
__device__ float g_wself[NMAX];
__device__ float g_ew   [EMAX];
__device__ int   g_csrc [EMAX];
__device__ int   g_rp   [NMAX + 1];
__device__ int   g_cur  [NMAX];
__device__ int   g_cnt  [NMAX];
__device__ float g_ST   [64 * 512];

__device__ __forceinline__ float leaky02(float v) { return v > 0.f ? v : 0.2f * v; }

__device__ __forceinline__ uint32_t f2tf32(float f) {
    uint32_t u;
    asm("cvt.rna.tf32.f32 %0, %1;" : "=r"(u) : "f"(f));
    return u;
}

__device__ __forceinline__ void mma_tf32(float c[4],
                                         uint32_t a0, uint32_t a1, uint32_t a2, uint32_t a3,
                                         uint32_t b0, uint32_t b1) {
    asm("mma.sync.aligned.m16n8k8.row.col.f32.tf32.tf32.f32 "
        "{%0,%1,%2,%3}, {%4,%5,%6,%7}, {%8,%9}, {%0,%1,%2,%3};"
        : "+f"(c[0]), "+f"(c[1]), "+f"(c[2]), "+f"(c[3])
        : "r"(a0), "r"(a1), "r"(a2), "r"(a3), "r"(b0), "r"(b1));
}

// ---------------------------------------------------------------------------
// Tensor-core GEMM (3xTF32): C[M,Ncols] = A[M,K] @ B[K,Ncols].
// If ALPHA: also emits oas[r] = C_row.avs, oad[r] = C_row.avd
// (requires BN == Ncols, grid.y == 1). K must be a multiple of BK.
// ---------------------------------------------------------------------------
template<int BM, int BN, int BK, int WM, int WN, bool ALPHA>
__global__ void __launch_bounds__(256)
mma_gemm_kernel(const float* __restrict__ A, const float* __restrict__ B,
                float* __restrict__ C,
                const float* __restrict__ avs, const float* __restrict__ avd,
                float* __restrict__ oas, float* __restrict__ oad,
                int M, int Ncols, int K)
{
    constexpr int WARPS_M = BM / WM;
    constexpr int WARPS_N = BN / WN;
    static_assert(WARPS_M * WARPS_N == 8, "8 warps");
    constexpr int MT = WM / 16;
    constexpr int NT = WN / 8;
    constexpr int AS_STRIDE = BK + 4;   // 20 for BK=16: conflict-free fragment loads
    constexpr int BS_STRIDE = BN + 8;   // (stride % 32 == 8): conflict-free

    __shared__ float As_hi[BM][AS_STRIDE], As_lo[BM][AS_STRIDE];
    __shared__ float Bs_hi[BK][BS_STRIDE], Bs_lo[BK][BS_STRIDE];
    __shared__ float red_s[ALPHA ? BM : 1], red_d[ALPHA ? BM : 1];

    const int tid  = threadIdx.x;
    const int lane = tid & 31;
    const int warp = tid >> 5;
    const int wm   = (warp / WARPS_N) * WM;
    const int wn   = (warp % WARPS_N) * WN;
    const int m0   = blockIdx.x * BM;
    const int n0   = blockIdx.y * BN;
    const int gid  = lane >> 2;   // groupID (row group)
    const int tig  = lane & 3;    // thread-in-group (col group)

    if (ALPHA) {
        for (int i = tid; i < BM; i += 256) { red_s[i] = 0.f; red_d[i] = 0.f; }
    }

    float c[MT][NT][4];
#pragma unroll
    for (int i = 0; i < MT; i++)
#pragma unroll
        for (int j = 0; j < NT; j++) {
            c[i][j][0] = 0.f; c[i][j][1] = 0.f; c[i][j][2] = 0.f; c[i][j][3] = 0.f;
        }

    constexpr int A_PER = (BM * BK / 4) / 256;
    constexpr int B_PER = (BK * BN / 4) / 256;

    for (int k0 = 0; k0 < K; k0 += BK) {
        __syncthreads();
        // ---- load A tile, split hi/lo ----
#pragma unroll
        for (int i = 0; i < A_PER; i++) {
            int idx = tid + i * 256;
            int row = idx / (BK / 4);
            int kq  = idx % (BK / 4);
            int gr  = m0 + row;
            float4 v = make_float4(0.f, 0.f, 0.f, 0.f);
            if (gr < M) v = *(const float4*)(A + (size_t)gr * K + k0 + kq * 4);
            float4 hi, lo;
            hi.x = __uint_as_float(f2tf32(v.x)); lo.x = __uint_as_float(f2tf32(v.x - hi.x));
            hi.y = __uint_as_float(f2tf32(v.y)); lo.y = __uint_as_float(f2tf32(v.y - hi.y));
            hi.z = __uint_as_float(f2tf32(v.z)); lo.z = __uint_as_float(f2tf32(v.z - hi.z));
            hi.w = __uint_as_float(f2tf32(v.w)); lo.w = __uint_as_float(f2tf32(v.w - hi.w));
            *(float4*)&As_hi[row][kq * 4] = hi;
            *(float4*)&As_lo[row][kq * 4] = lo;
        }
        // ---- load B tile, split hi/lo ----
#pragma unroll
        for (int i = 0; i < B_PER; i++) {
            int idx = tid + i * 256;
            int row = idx / (BN / 4);
            int c4  = idx % (BN / 4);
            float4 v = *(const float4*)(B + (size_t)(k0 + row) * Ncols + n0 + c4 * 4);
            float4 hi, lo;
            hi.x = __uint_as_float(f2tf32(v.x)); lo.x = __uint_as_float(f2tf32(v.x - hi.x));
            hi.y = __uint_as_float(f2tf32(v.y)); lo.y = __uint_as_float(f2tf32(v.y - hi.y));
            hi.z = __uint_as_float(f2tf32(v.z)); lo.z = __uint_as_float(f2tf32(v.z - hi.z));
            hi.w = __uint_as_float(f2tf32(v.w)); lo.w = __uint_as_float(f2tf32(v.w - hi.w));
            *(float4*)&Bs_hi[row][c4 * 4] = hi;
            *(float4*)&Bs_lo[row][c4 * 4] = lo;
        }
        __syncthreads();

#pragma unroll
        for (int ks = 0; ks < BK; ks += 8) {
            uint32_t ah[MT][4], al[MT][4];
#pragma unroll
            for (int mt = 0; mt < MT; mt++) {
                int r = wm + mt * 16 + gid;
                ah[mt][0] = __float_as_uint(As_hi[r    ][ks + tig    ]);
                ah[mt][1] = __float_as_uint(As_hi[r + 8][ks + tig    ]);
                ah[mt][2] = __float_as_uint(As_hi[r    ][ks + tig + 4]);
                ah[mt][3] = __float_as_uint(As_hi[r + 8][ks + tig + 4]);
                al[mt][0] = __float_as_uint(As_lo[r    ][ks + tig    ]);
                al[mt][1] = __float_as_uint(As_lo[r + 8][ks + tig    ]);
                al[mt][2] = __float_as_uint(As_lo[r    ][ks + tig + 4]);
                al[mt][3] = __float_as_uint(As_lo[r + 8][ks + tig + 4]);
            }
#pragma unroll
            for (int nt = 0; nt < NT; nt++) {
                int cc = wn + nt * 8 + gid;
                uint32_t bh0 = __float_as_uint(Bs_hi[ks + tig    ][cc]);
                uint32_t bh1 = __float_as_uint(Bs_hi[ks + tig + 4][cc]);
                uint32_t bl0 = __float_as_uint(Bs_lo[ks + tig    ][cc]);
                uint32_t bl1 = __float_as_uint(Bs_lo[ks + tig + 4][cc]);
#pragma unroll
                for (int mt = 0; mt < MT; mt++) {
                    mma_tf32(c[mt][nt], ah[mt][0], ah[mt][1], ah[mt][2], ah[mt][3], bh0, bh1);
                    mma_tf32(c[mt][nt], al[mt][0], al[mt][1], al[mt][2], al[mt][3], bh0, bh1);
                    mma_tf32(c[mt][nt], ah[mt][0], ah[mt][1], ah[mt][2], ah[mt][3], bl0, bl1);
                }
            }
        }
    }

    // ---- epilogue: store C (+ fused alpha dots) ----
#pragma unroll
    for (int mt = 0; mt < MT; mt++) {
        int r0l = wm + mt * 16 + gid;
        int r1l = r0l + 8;
        int gr0 = m0 + r0l;
        int gr1 = m0 + r1l;
        float ps0 = 0.f, pd0 = 0.f, ps1 = 0.f, pd1 = 0.f;
#pragma unroll
        for (int nt = 0; nt < NT; nt++) {
            int cb = wn + nt * 8 + tig * 2;
            if (gr0 < M) {
                float2 v = make_float2(c[mt][nt][0], c[mt][nt][1]);
                *(float2*)(C + (size_t)gr0 * Ncols + n0 + cb) = v;
            }
            if (gr1 < M) {
                float2 v = make_float2(c[mt][nt][2], c[mt][nt][3]);
                *(float2*)(C + (size_t)gr1 * Ncols + n0 + cb) = v;
            }
            if (ALPHA) {
                float s0 = __ldg(&avs[cb]), s1 = __ldg(&avs[cb + 1]);
                float d0 = __ldg(&avd[cb]), d1 = __ldg(&avd[cb + 1]);
                ps0 = fmaf(c[mt][nt][0], s0, fmaf(c[mt][nt][1], s1, ps0));
                pd0 = fmaf(c[mt][nt][0], d0, fmaf(c[mt][nt][1], d1, pd0));
                ps1 = fmaf(c[mt][nt][2], s0, fmaf(c[mt][nt][3], s1, ps1));
                pd1 = fmaf(c[mt][nt][2], d0, fmaf(c[mt][nt][3], d1, pd1));
            }
        }
        if (ALPHA) {
#pragma unroll
            for (int off = 1; off < 4; off <<= 1) {
                ps0 += __shfl_xor_sync(0xffffffffu, ps0, off);
                pd0 += __shfl_xor_sync(0xffffffffu, pd0, off);
                ps1 += __shfl_xor_sync(0xffffffffu, ps1, off);
                pd1 += __shfl_xor_sync(0xffffffffu, pd1, off);
            }
            if (tig == 0) {
                atomicAdd(&red_s[r0l], ps0);
                atomicAdd(&red_d[r0l], pd0);
                atomicAdd(&red_s[r1l], ps1);
                atomicAdd(&red_d[r1l], pd1);
            }
        }
    }
    if (ALPHA) {
        __syncthreads();
        for (int i = tid; i < BM; i += 256) {
            int gr = m0 + i;
            if (gr < M) { oas[gr] = red_s[i]; oad[gr] = red_d[i]; }
        }
    }
}

// ---------------------------------------------------------------------------
// CSR build
// ---------------------------------------------------------------------------
__global__ void zero_cnt_kernel(int* __restrict__ cnt, int N)
{
    int i = blockIdx.x * blockDim.x + threadIdx.x;
    if (i < N) cnt[i] = 0;
}

__global__ void hist_kernel(const int* __restrict__ ei, int* __restrict__ cnt, int E)
{
    int e = blockIdx.x * blockDim.x + threadIdx.x;
    if (e < E) atomicAdd(&cnt[ei[E + e]], 1);
}

__global__ void __launch_bounds__(1024)
scan_kernel(const int* __restrict__ cnt, int* __restrict__ rp,
            int* __restrict__ cur, int N)
{
    __shared__ int sh[1024];
    int t = threadIdx.x;
    int IT = (N + 1023) / 1024;
    int base = t * IT;

    int sum = 0;
    for (int k = 0; k < IT; k++) {
        int idx = base + k;
        if (idx < N) sum += cnt[idx];
    }
    sh[t] = sum;
    __syncthreads();
    for (int off = 1; off < 1024; off <<= 1) {
        int v = (t >= off) ? sh[t - off] : 0;
        __syncthreads();
        sh[t] += v;
        __syncthreads();
    }
    int run = sh[t] - sum;
    for (int k = 0; k < IT; k++) {
        int idx = base + k;
        if (idx < N) {
            rp[idx]  = run;
            cur[idx] = run;
            run += cnt[idx];
        }
    }
    if (t == 1023) rp[N] = sh[1023];
}

__global__ void scatter_kernel(const int* __restrict__ ei, int* __restrict__ cur,
                               int* __restrict__ csrc, int E)
{
    int e = blockIdx.x * blockDim.x + threadIdx.x;
    if (e < E) {
        int d = ei[E + e];
        int pos = atomicAdd(&cur[d], 1);
        csrc[pos] = ei[e];
    }
}

// ---------------------------------------------------------------------------
// Per-node softmax over incoming edges (CSR). One warp per node.
// ---------------------------------------------------------------------------
__global__ void node_attn_kernel(const int* __restrict__ rp,
                                 const int* __restrict__ csrc,
                                 const float* __restrict__ as_,
                                 const float* __restrict__ ad_,
                                 float* __restrict__ ew,
                                 float* __restrict__ den,
                                 float* __restrict__ wself, int N)
{
    int node = (blockIdx.x * blockDim.x + threadIdx.x) >> 5;
    int lane = threadIdx.x & 31;
    if (node >= N) return;

    int j0 = rp[node], j1 = rp[node + 1];
    float add   = ad_[node];
    float vself = leaky02(as_[node] + add);
    float mx = vself;

    for (int j = j0 + lane; j < j1; j += 32) {
        float v = leaky02(as_[csrc[j]] + add);
        ew[j] = v;
        mx = fmaxf(mx, v);
    }
#pragma unroll
    for (int o = 16; o; o >>= 1)
        mx = fmaxf(mx, __shfl_xor_sync(0xffffffffu, mx, o));

    float sum = 0.f;
    for (int j = j0 + lane; j < j1; j += 32) {
        float w = expf(ew[j] - mx);
        ew[j] = w;
        sum += w;
    }
#pragma unroll
    for (int o = 16; o; o >>= 1)
        sum += __shfl_xor_sync(0xffffffffu, sum, o);

    if (lane == 0) {
        float ws = expf(vself - mx);
        den[node]   = sum + ws;
        wself[node] = ws;
    }
}

// ---------------------------------------------------------------------------
// CSR aggregation, fused with self-loop, normalization, bias, activation.
// ---------------------------------------------------------------------------
template<int F>
__global__ void agg_csr_kernel(const int* __restrict__ rp,
                               const int* __restrict__ csrc,
                               const float* __restrict__ ew,
                               const float* __restrict__ den,
                               const float* __restrict__ wself,
                               const float* __restrict__ h,
                               const float* __restrict__ bias,
                               float* __restrict__ out, int N, int do_leaky)
{
    constexpr int LPN = F / 4;
    constexpr int NPW = 32 / LPN;
    int lane = threadIdx.x & 31;
    int sub  = lane / LPN;
    int l    = lane % LPN;
    int node = ((blockIdx.x * blockDim.x + threadIdx.x) >> 5) * NPW + sub;
    if (node >= N) return;

    float ws = wself[node];
    float4 hv = *(const float4*)(h + (size_t)node * F + l * 4);
    float ax = ws * hv.x, ay = ws * hv.y, az = ws * hv.z, aw = ws * hv.w;

    int j0 = rp[node], j1 = rp[node + 1];
    for (int j = j0; j < j1; j++) {
        int   s = __ldg(&csrc[j]);
        float w = __ldg(&ew[j]);
        float4 v = *(const float4*)(h + (size_t)s * F + l * 4);
        ax = fmaf(w, v.x, ax);
        ay = fmaf(w, v.y, ay);
        az = fmaf(w, v.z, az);
        aw = fmaf(w, v.w, aw);
    }

    float inv = 1.f / den[node];
    float4 b = *(const float4*)(bias + l * 4);
    float4 o;
    o.x = ax * inv + b.x;
    o.y = ay * inv + b.y;
    o.z = az * inv + b.z;
    o.w = aw * inv + b.w;
    if (do_leaky) {
        o.x = o.x > 0.f ? o.x : 0.1f * o.x;
        o.y = o.y > 0.f ? o.y : 0.1f * o.y;
        o.z = o.z > 0.f ? o.z : 0.1f * o.z;
        o.w = o.w > 0.f ? o.w : 0.1f * o.w;
    }
    *(float4*)(out + (size_t)node * F + l * 4) = o;
}

__global__ void transpose_S_kernel(const float* __restrict__ S, float* __restrict__ ST)
{
    int i = blockIdx.x * blockDim.x + threadIdx.x;
    if (i < 64 * 512) {
        int k = i / 512, n = i % 512;
        ST[i] = S[n * 64 + k];
    }
}

// ---------------------------------------------------------------------------
// Host
// ---------------------------------------------------------------------------
static inline int cdiv(int a, int b) { return (a + b - 1) / b; }

extern "C" void kernel_launch(void* const* d_in, const int* in_sizes, int n_in,
                              void* d_out, int out_size)
{
    const float* x   = (const float*)d_in[0];
    const int*   ei  = (const int*)d_in[1];   // int32 (JAX x64 disabled)
    const float* W1  = (const float*)d_in[2];
    const float* a1s = (const float*)d_in[3];
    const float* a1d = (const float*)d_in[4];
    const float* b1  = (const float*)d_in[5];
    const float* W2  = (const float*)d_in[6];
    const float* a2s = (const float*)d_in[7];
    const float* a2d = (const float*)d_in[8];
    const float* b2  = (const float*)d_in[9];
    const float* W3  = (const float*)d_in[10];
    const float* a3s = (const float*)d_in[11];
    const float* a3d = (const float*)d_in[12];
    const float* b3  = (const float*)d_in[13];
    const float* S   = (const float*)d_in[14];

    int N = in_sizes[0] / 128;
    int E = in_sizes[1] / 2;

    float *hb, *actb, *pas, *pad_, *pden, *pws, *pew, *pst;
    int *pcsrc, *prp, *pcur, *pcnt;
    cudaGetSymbolAddress((void**)&hb,    g_hbuf);
    cudaGetSymbolAddress((void**)&actb,  g_actbuf);
    cudaGetSymbolAddress((void**)&pas,   g_as);
    cudaGetSymbolAddress((void**)&pad_,  g_ad);
    cudaGetSymbolAddress((void**)&pden,  g_den);
    cudaGetSymbolAddress((void**)&pws,   g_wself);
    cudaGetSymbolAddress((void**)&pew,   g_ew);
    cudaGetSymbolAddress((void**)&pst,   g_ST);
    cudaGetSymbolAddress((void**)&pcsrc, g_csrc);
    cudaGetSymbolAddress((void**)&prp,   g_rp);
    cudaGetSymbolAddress((void**)&pcur,  g_cur);
    cudaGetSymbolAddress((void**)&pcnt,  g_cnt);

    // --- CSR build ---
    zero_cnt_kernel<<<cdiv(N,256), 256>>>(pcnt, N);
    hist_kernel<<<cdiv(E,256), 256>>>(ei, pcnt, E);
    scan_kernel<<<1, 1024>>>(pcnt, prp, pcur, N);
    scatter_kernel<<<cdiv(E,256), 256>>>(ei, pcur, pcsrc, E);

    transpose_S_kernel<<<cdiv(64*512,256), 256>>>(S, pst);

    int gm = cdiv(N, 128);
    int gw = cdiv(N * 32, 256);

    // --- layer 1 ---
    mma_gemm_kernel<128,128,16,64,32,true><<<dim3(gm,1), 256>>>(
        x, W1, hb, a1s, a1d, pas, pad_, N, 128, 128);
    node_attn_kernel<<<gw, 256>>>(prp, pcsrc, pas, pad_, pew, pden, pws, N);
    agg_csr_kernel<128><<<gw, 256>>>(prp, pcsrc, pew, pden, pws, hb, b1, actb, N, 1);

    // --- layer 2 ---
    mma_gemm_kernel<128,128,16,64,32,true><<<dim3(gm,1), 256>>>(
        actb, W2, hb, a2s, a2d, pas, pad_, N, 128, 128);
    node_attn_kernel<<<gw, 256>>>(prp, pcsrc, pas, pad_, pew, pden, pws, N);
    agg_csr_kernel<128><<<gw, 256>>>(prp, pcsrc, pew, pden, pws, hb, b2, actb, N, 1);

    // --- layer 3 (F=64, no inter-layer activation) ---
    mma_gemm_kernel<128,64,16,32,32,true><<<dim3(gm,1), 256>>>(
        actb, W3, hb, a3s, a3d, pas, pad_, N, 64, 128);
    node_attn_kernel<<<gw, 256>>>(prp, pcsrc, pas, pad_, pew, pden, pws, N);
    agg_csr_kernel<64><<<cdiv(N*16,256), 256>>>(prp, pcsrc, pew, pden, pws, hb, b3,
                                                actb, N, 0);

    // --- final projection: [N,64] @ [64,512] ---
    mma_gemm_kernel<128,128,16,64,32,false><<<dim3(gm,4), 256>>>(
        actb, pst, (float*)d_out, nullptr, nullptr, nullptr, nullptr, N, 512, 64);
}

// round 8
// speedup vs baseline: 1.1933x; 1.0410x over previous
#include <cuda_runtime.h>
#include <cstdint>

// ---------------------------------------------------------------------------
// GraphPooling: 3-layer GAT (single head) + final projection.
// Round 8: 2-stage pipelined 3xTF32 tensor GEMM (register prefetch +
//          double-buffered smem, dynamic smem) with fused alpha epilogue;
//          vectorized CSR build. Edge phase unchanged.
// ---------------------------------------------------------------------------

#define NMAX 50000
#define EMAX 800000
#define FMAX 128

__device__ float g_hbuf  [NMAX * FMAX];
__device__ float g_actbuf[NMAX * FMAX];
__device__ float g_as   [NMAX];
__device__ float g_ad   [NMAX];
__device__ float g_den  [NMAX];
__device__ float g_wself[NMAX];
__device__ float g_ew   [EMAX];
__device__ int   g_csrc [EMAX];
__device__ int   g_rp   [NMAX + 1];
__device__ int   g_cur  [NMAX];
__device__ int   g_cnt  [NMAX];
__device__ float g_ST   [64 * 512];

__device__ __forceinline__ float leaky02(float v) { return v > 0.f ? v : 0.2f * v; }

__device__ __forceinline__ uint32_t f2tf32(float f) {
    uint32_t u;
    asm("cvt.rna.tf32.f32 %0, %1;" : "=r"(u) : "f"(f));
    return u;
}

__device__ __forceinline__ void mma_tf32(float c[4],
                                         uint32_t a0, uint32_t a1, uint32_t a2, uint32_t a3,
                                         uint32_t b0, uint32_t b1) {
    asm("mma.sync.aligned.m16n8k8.row.col.f32.tf32.tf32.f32 "
        "{%0,%1,%2,%3}, {%4,%5,%6,%7}, {%8,%9}, {%0,%1,%2,%3};"
        : "+f"(c[0]), "+f"(c[1]), "+f"(c[2]), "+f"(c[3])
        : "r"(a0), "r"(a1), "r"(a2), "r"(a3), "r"(b0), "r"(b1));
}

// ---------------------------------------------------------------------------
// Pipelined tensor-core GEMM (3xTF32): C[M,Ncols] = A[M,K] @ B[K,Ncols].
// 2-stage smem double buffer + register prefetch.
// If ALPHA: also emits oas[r] = C_row.avs, oad[r] = C_row.avd
// (requires BN == Ncols, grid.y == 1). K must be a multiple of BK.
// Dynamic smem layout: As_hi[2][BM][ASS] As_lo[...] Bs_hi[2][BK][BSS] Bs_lo[...]
//                      red_s[BM] red_d[BM]
// ---------------------------------------------------------------------------
template<int BM, int BN, int BK, int WM, int WN, bool ALPHA>
__global__ void __launch_bounds__(256)
mma_gemm_kernel(const float* __restrict__ A, const float* __restrict__ B,
                float* __restrict__ C,
                const float* __restrict__ avs, const float* __restrict__ avd,
                float* __restrict__ oas, float* __restrict__ oad,
                int M, int Ncols, int K)
{
    constexpr int WARPS_N = BN / WN;
    static_assert((BM / WM) * (BN / WN) == 8, "8 warps");
    constexpr int MT  = WM / 16;
    constexpr int NT  = WN / 8;
    constexpr int ASS = BK + 4;    // A smem stride (20 for BK=16)
    constexpr int BSS = BN + 8;    // B smem stride
    constexpr int A_PER = (BM * BK / 4) / 256;
    constexpr int B_PER = (BK * BN / 4) / 256;

    extern __shared__ float sm[];
    float* As_hi = sm;                              // 2*BM*ASS
    float* As_lo = As_hi + 2 * BM * ASS;
    float* Bs_hi = As_lo + 2 * BM * ASS;            // 2*BK*BSS
    float* Bs_lo = Bs_hi + 2 * BK * BSS;
    float* red_s = Bs_lo + 2 * BK * BSS;            // BM
    float* red_d = red_s + BM;

    const int tid  = threadIdx.x;
    const int lane = tid & 31;
    const int warp = tid >> 5;
    const int wm   = (warp / WARPS_N) * WM;
    const int wn   = (warp % WARPS_N) * WN;
    const int m0   = blockIdx.x * BM;
    const int n0   = blockIdx.y * BN;
    const int gid  = lane >> 2;
    const int tig  = lane & 3;

    if (ALPHA) {
        for (int i = tid; i < BM; i += 256) { red_s[i] = 0.f; red_d[i] = 0.f; }
    }

    float c[MT][NT][4];
#pragma unroll
    for (int i = 0; i < MT; i++)
#pragma unroll
        for (int j = 0; j < NT; j++) {
            c[i][j][0] = 0.f; c[i][j][1] = 0.f; c[i][j][2] = 0.f; c[i][j][3] = 0.f;
        }

    // per-thread load coordinates
    int a_row[A_PER], a_kq[A_PER], b_row[B_PER], b_c4[B_PER];
#pragma unroll
    for (int i = 0; i < A_PER; i++) {
        int idx = tid + i * 256;
        a_row[i] = idx / (BK / 4);
        a_kq[i]  = idx % (BK / 4);
    }
#pragma unroll
    for (int i = 0; i < B_PER; i++) {
        int idx = tid + i * 256;
        b_row[i] = idx / (BN / 4);
        b_c4[i]  = idx % (BN / 4);
    }

    float4 areg[A_PER], breg[B_PER];

    auto load_tile = [&](int k0) {
#pragma unroll
        for (int i = 0; i < A_PER; i++) {
            int gr = m0 + a_row[i];
            areg[i] = make_float4(0.f, 0.f, 0.f, 0.f);
            if (gr < M) areg[i] = *(const float4*)(A + (size_t)gr * K + k0 + a_kq[i] * 4);
        }
#pragma unroll
        for (int i = 0; i < B_PER; i++)
            breg[i] = *(const float4*)(B + (size_t)(k0 + b_row[i]) * Ncols + n0 + b_c4[i] * 4);
    };

    auto store_tile = [&](int st) {
#pragma unroll
        for (int i = 0; i < A_PER; i++) {
            float* hp = &As_hi[(st * BM + a_row[i]) * ASS + a_kq[i] * 4];
            float* lp = &As_lo[(st * BM + a_row[i]) * ASS + a_kq[i] * 4];
            float4 v = areg[i];
            float hx = __uint_as_float(f2tf32(v.x));
            float hy = __uint_as_float(f2tf32(v.y));
            float hz = __uint_as_float(f2tf32(v.z));
            float hw = __uint_as_float(f2tf32(v.w));
            *(float4*)hp = make_float4(hx, hy, hz, hw);
            *(float4*)lp = make_float4(__uint_as_float(f2tf32(v.x - hx)),
                                       __uint_as_float(f2tf32(v.y - hy)),
                                       __uint_as_float(f2tf32(v.z - hz)),
                                       __uint_as_float(f2tf32(v.w - hw)));
        }
#pragma unroll
        for (int i = 0; i < B_PER; i++) {
            float* hp = &Bs_hi[(st * BK + b_row[i]) * BSS + b_c4[i] * 4];
            float* lp = &Bs_lo[(st * BK + b_row[i]) * BSS + b_c4[i] * 4];
            float4 v = breg[i];
            float hx = __uint_as_float(f2tf32(v.x));
            float hy = __uint_as_float(f2tf32(v.y));
            float hz = __uint_as_float(f2tf32(v.z));
            float hw = __uint_as_float(f2tf32(v.w));
            *(float4*)hp = make_float4(hx, hy, hz, hw);
            *(float4*)lp = make_float4(__uint_as_float(f2tf32(v.x - hx)),
                                       __uint_as_float(f2tf32(v.y - hy)),
                                       __uint_as_float(f2tf32(v.z - hz)),
                                       __uint_as_float(f2tf32(v.w - hw)));
        }
    };

    // prologue
    load_tile(0);
    store_tile(0);
    __syncthreads();

    const int T = K / BK;
    for (int t = 0; t < T; t++) {
        int buf = t & 1;
        if (t + 1 < T) load_tile((t + 1) * BK);   // prefetch overlaps mma below

#pragma unroll
        for (int ks = 0; ks < BK; ks += 8) {
            uint32_t ah[MT][4], al[MT][4];
#pragma unroll
            for (int mt = 0; mt < MT; mt++) {
                int r = (buf * BM + wm + mt * 16 + gid) * ASS;
                ah[mt][0] = __float_as_uint(As_hi[r           + ks + tig    ]);
                ah[mt][1] = __float_as_uint(As_hi[r + 8 * ASS + ks + tig    ]);
                ah[mt][2] = __float_as_uint(As_hi[r           + ks + tig + 4]);
                ah[mt][3] = __float_as_uint(As_hi[r + 8 * ASS + ks + tig + 4]);
                al[mt][0] = __float_as_uint(As_lo[r           + ks + tig    ]);
                al[mt][1] = __float_as_uint(As_lo[r + 8 * ASS + ks + tig    ]);
                al[mt][2] = __float_as_uint(As_lo[r           + ks + tig + 4]);
                al[mt][3] = __float_as_uint(As_lo[r + 8 * ASS + ks + tig + 4]);
            }
#pragma unroll
            for (int nt = 0; nt < NT; nt++) {
                int cc = wn + nt * 8 + gid;
                int rb0 = (buf * BK + ks + tig)     * BSS + cc;
                int rb1 = (buf * BK + ks + tig + 4) * BSS + cc;
                uint32_t bh0 = __float_as_uint(Bs_hi[rb0]);
                uint32_t bh1 = __float_as_uint(Bs_hi[rb1]);
                uint32_t bl0 = __float_as_uint(Bs_lo[rb0]);
                uint32_t bl1 = __float_as_uint(Bs_lo[rb1]);
#pragma unroll
                for (int mt = 0; mt < MT; mt++) {
                    mma_tf32(c[mt][nt], ah[mt][0], ah[mt][1], ah[mt][2], ah[mt][3], bh0, bh1);
                    mma_tf32(c[mt][nt], al[mt][0], al[mt][1], al[mt][2], al[mt][3], bh0, bh1);
                    mma_tf32(c[mt][nt], ah[mt][0], ah[mt][1], ah[mt][2], ah[mt][3], bl0, bl1);
                }
            }
        }

        if (t + 1 < T) {
            store_tile(buf ^ 1);
            __syncthreads();
        }
    }

    // ---- epilogue: store C (+ fused alpha dots) ----
#pragma unroll
    for (int mt = 0; mt < MT; mt++) {
        int r0l = wm + mt * 16 + gid;
        int r1l = r0l + 8;
        int gr0 = m0 + r0l;
        int gr1 = m0 + r1l;
        float ps0 = 0.f, pd0 = 0.f, ps1 = 0.f, pd1 = 0.f;
#pragma unroll
        for (int nt = 0; nt < NT; nt++) {
            int cb = wn + nt * 8 + tig * 2;
            if (gr0 < M) {
                float2 v = make_float2(c[mt][nt][0], c[mt][nt][1]);
                *(float2*)(C + (size_t)gr0 * Ncols + n0 + cb) = v;
            }
            if (gr1 < M) {
                float2 v = make_float2(c[mt][nt][2], c[mt][nt][3]);
                *(float2*)(C + (size_t)gr1 * Ncols + n0 + cb) = v;
            }
            if (ALPHA) {
                float s0 = __ldg(&avs[cb]), s1 = __ldg(&avs[cb + 1]);
                float d0 = __ldg(&avd[cb]), d1 = __ldg(&avd[cb + 1]);
                ps0 = fmaf(c[mt][nt][0], s0, fmaf(c[mt][nt][1], s1, ps0));
                pd0 = fmaf(c[mt][nt][0], d0, fmaf(c[mt][nt][1], d1, pd0));
                ps1 = fmaf(c[mt][nt][2], s0, fmaf(c[mt][nt][3], s1, ps1));
                pd1 = fmaf(c[mt][nt][2], d0, fmaf(c[mt][nt][3], d1, pd1));
            }
        }
        if (ALPHA) {
#pragma unroll
            for (int off = 1; off < 4; off <<= 1) {
                ps0 += __shfl_xor_sync(0xffffffffu, ps0, off);
                pd0 += __shfl_xor_sync(0xffffffffu, pd0, off);
                ps1 += __shfl_xor_sync(0xffffffffu, ps1, off);
                pd1 += __shfl_xor_sync(0xffffffffu, pd1, off);
            }
            if (tig == 0) {
                atomicAdd(&red_s[r0l], ps0);
                atomicAdd(&red_d[r0l], pd0);
                atomicAdd(&red_s[r1l], ps1);
                atomicAdd(&red_d[r1l], pd1);
            }
        }
    }
    if (ALPHA) {
        __syncthreads();
        for (int i = tid; i < BM; i += 256) {
            int gr = m0 + i;
            if (gr < M) { oas[gr] = red_s[i]; oad[gr] = red_d[i]; }
        }
    }
}

// smem bytes for a given instantiation
static inline int mma_smem_bytes(int BM, int BN, int BK) {
    int ASS = BK + 4, BSS = BN + 8;
    return (4 * BM * ASS + 4 * BK * BSS + 2 * BM) * 4;
}

// ---------------------------------------------------------------------------
// CSR build (vectorized)
// ---------------------------------------------------------------------------
__global__ void zero_cnt_kernel(int* __restrict__ cnt, int N)
{
    int i = blockIdx.x * blockDim.x + threadIdx.x;
    if (i < N) cnt[i] = 0;
}

__global__ void hist_kernel(const int* __restrict__ ei, int* __restrict__ cnt, int E)
{
    int i = (blockIdx.x * blockDim.x + threadIdx.x) * 4;
    if (i + 3 < E) {
        int4 d = *(const int4*)(ei + E + i);
        atomicAdd(&cnt[d.x], 1);
        atomicAdd(&cnt[d.y], 1);
        atomicAdd(&cnt[d.z], 1);
        atomicAdd(&cnt[d.w], 1);
    } else {
        for (int e = i; e < E; e++) atomicAdd(&cnt[ei[E + e]], 1);
    }
}

__global__ void __launch_bounds__(1024)
scan_kernel(const int* __restrict__ cnt, int* __restrict__ rp,
            int* __restrict__ cur, int N)
{
    __shared__ int sh[1024];
    int t = threadIdx.x;
    int IT = (N + 1023) / 1024;
    int base = t * IT;

    int sum = 0;
    for (int k = 0; k < IT; k++) {
        int idx = base + k;
        if (idx < N) sum += cnt[idx];
    }
    sh[t] = sum;
    __syncthreads();
    for (int off = 1; off < 1024; off <<= 1) {
        int v = (t >= off) ? sh[t - off] : 0;
        __syncthreads();
        sh[t] += v;
        __syncthreads();
    }
    int run = sh[t] - sum;
    for (int k = 0; k < IT; k++) {
        int idx = base + k;
        if (idx < N) {
            rp[idx]  = run;
            cur[idx] = run;
            run += cnt[idx];
        }
    }
    if (t == 1023) rp[N] = sh[1023];
}

__global__ void scatter_kernel(const int* __restrict__ ei, int* __restrict__ cur,
                               int* __restrict__ csrc, int E)
{
    int i = (blockIdx.x * blockDim.x + threadIdx.x) * 4;
    if (i + 3 < E) {
        int4 s = *(const int4*)(ei + i);
        int4 d = *(const int4*)(ei + E + i);
        csrc[atomicAdd(&cur[d.x], 1)] = s.x;
        csrc[atomicAdd(&cur[d.y], 1)] = s.y;
        csrc[atomicAdd(&cur[d.z], 1)] = s.z;
        csrc[atomicAdd(&cur[d.w], 1)] = s.w;
    } else {
        for (int e = i; e < E; e++)
            csrc[atomicAdd(&cur[ei[E + e]], 1)] = ei[e];
    }
}

// ---------------------------------------------------------------------------
// Per-node softmax over incoming edges (CSR). One warp per node.
// ---------------------------------------------------------------------------
__global__ void node_attn_kernel(const int* __restrict__ rp,
                                 const int* __restrict__ csrc,
                                 const float* __restrict__ as_,
                                 const float* __restrict__ ad_,
                                 float* __restrict__ ew,
                                 float* __restrict__ den,
                                 float* __restrict__ wself, int N)
{
    int node = (blockIdx.x * blockDim.x + threadIdx.x) >> 5;
    int lane = threadIdx.x & 31;
    if (node >= N) return;

    int j0 = rp[node], j1 = rp[node + 1];
    float add   = ad_[node];
    float vself = leaky02(as_[node] + add);
    float mx = vself;

    for (int j = j0 + lane; j < j1; j += 32) {
        float v = leaky02(as_[csrc[j]] + add);
        ew[j] = v;
        mx = fmaxf(mx, v);
    }
#pragma unroll
    for (int o = 16; o; o >>= 1)
        mx = fmaxf(mx, __shfl_xor_sync(0xffffffffu, mx, o));

    float sum = 0.f;
    for (int j = j0 + lane; j < j1; j += 32) {
        float w = expf(ew[j] - mx);
        ew[j] = w;
        sum += w;
    }
#pragma unroll
    for (int o = 16; o; o >>= 1)
        sum += __shfl_xor_sync(0xffffffffu, sum, o);

    if (lane == 0) {
        float ws = expf(vself - mx);
        den[node]   = sum + ws;
        wself[node] = ws;
    }
}

// ---------------------------------------------------------------------------
// CSR aggregation, fused with self-loop, normalization, bias, activation.
// ---------------------------------------------------------------------------
template<int F>
__global__ void agg_csr_kernel(const int* __restrict__ rp,
                               const int* __restrict__ csrc,
                               const float* __restrict__ ew,
                               const float* __restrict__ den,
                               const float* __restrict__ wself,
                               const float* __restrict__ h,
                               const float* __restrict__ bias,
                               float* __restrict__ out, int N, int do_leaky)
{
    constexpr int LPN = F / 4;
    constexpr int NPW = 32 / LPN;
    int lane = threadIdx.x & 31;
    int sub  = lane / LPN;
    int l    = lane % LPN;
    int node = ((blockIdx.x * blockDim.x + threadIdx.x) >> 5) * NPW + sub;
    if (node >= N) return;

    float ws = wself[node];
    float4 hv = *(const float4*)(h + (size_t)node * F + l * 4);
    float ax = ws * hv.x, ay = ws * hv.y, az = ws * hv.z, aw = ws * hv.w;

    int j0 = rp[node], j1 = rp[node + 1];
    for (int j = j0; j < j1; j++) {
        int   s = __ldg(&csrc[j]);
        float w = __ldg(&ew[j]);
        float4 v = *(const float4*)(h + (size_t)s * F + l * 4);
        ax = fmaf(w, v.x, ax);
        ay = fmaf(w, v.y, ay);
        az = fmaf(w, v.z, az);
        aw = fmaf(w, v.w, aw);
    }

    float inv = 1.f / den[node];
    float4 b = *(const float4*)(bias + l * 4);
    float4 o;
    o.x = ax * inv + b.x;
    o.y = ay * inv + b.y;
    o.z = az * inv + b.z;
    o.w = aw * inv + b.w;
    if (do_leaky) {
        o.x = o.x > 0.f ? o.x : 0.1f * o.x;
        o.y = o.y > 0.f ? o.y : 0.1f * o.y;
        o.z = o.z > 0.f ? o.z : 0.1f * o.z;
        o.w = o.w > 0.f ? o.w : 0.1f * o.w;
    }
    *(float4*)(out + (size_t)node * F + l * 4) = o;
}

__global__ void transpose_S_kernel(const float* __restrict__ S, float* __restrict__ ST)
{
    int i = blockIdx.x * blockDim.x + threadIdx.x;
    if (i < 64 * 512) {
        int k = i / 512, n = i % 512;
        ST[i] = S[n * 64 + k];
    }
}

// ---------------------------------------------------------------------------
// Host
// ---------------------------------------------------------------------------
static inline int cdiv(int a, int b) { return (a + b - 1) / b; }

extern "C" void kernel_launch(void* const* d_in, const int* in_sizes, int n_in,
                              void* d_out, int out_size)
{
    const float* x   = (const float*)d_in[0];
    const int*   ei  = (const int*)d_in[1];   // int32 (JAX x64 disabled)
    const float* W1  = (const float*)d_in[2];
    const float* a1s = (const float*)d_in[3];
    const float* a1d = (const float*)d_in[4];
    const float* b1  = (const float*)d_in[5];
    const float* W2  = (const float*)d_in[6];
    const float* a2s = (const float*)d_in[7];
    const float* a2d = (const float*)d_in[8];
    const float* b2  = (const float*)d_in[9];
    const float* W3  = (const float*)d_in[10];
    const float* a3s = (const float*)d_in[11];
    const float* a3d = (const float*)d_in[12];
    const float* b3  = (const float*)d_in[13];
    const float* S   = (const float*)d_in[14];

    int N = in_sizes[0] / 128;
    int E = in_sizes[1] / 2;

    float *hb, *actb, *pas, *pad_, *pden, *pws, *pew, *pst;
    int *pcsrc, *prp, *pcur, *pcnt;
    cudaGetSymbolAddress((void**)&hb,    g_hbuf);
    cudaGetSymbolAddress((void**)&actb,  g_actbuf);
    cudaGetSymbolAddress((void**)&pas,   g_as);
    cudaGetSymbolAddress((void**)&pad_,  g_ad);
    cudaGetSymbolAddress((void**)&pden,  g_den);
    cudaGetSymbolAddress((void**)&pws,   g_wself);
    cudaGetSymbolAddress((void**)&pew,   g_ew);
    cudaGetSymbolAddress((void**)&pst,   g_ST);
    cudaGetSymbolAddress((void**)&pcsrc, g_csrc);
    cudaGetSymbolAddress((void**)&prp,   g_rp);
    cudaGetSymbolAddress((void**)&pcur,  g_cur);
    cudaGetSymbolAddress((void**)&pcnt,  g_cnt);

    // dynamic smem sizes per instantiation
    const int smem128 = mma_smem_bytes(128, 128, 16);   // ~76.8 KB
    const int smem64  = mma_smem_bytes(128, 64, 16);    // ~60.4 KB
    cudaFuncSetAttribute(mma_gemm_kernel<128,128,16,64,32,true>,
                         cudaFuncAttributeMaxDynamicSharedMemorySize, smem128);
    cudaFuncSetAttribute(mma_gemm_kernel<128,128,16,64,32,false>,
                         cudaFuncAttributeMaxDynamicSharedMemorySize, smem128);
    cudaFuncSetAttribute(mma_gemm_kernel<128,64,16,32,32,true>,
                         cudaFuncAttributeMaxDynamicSharedMemorySize, smem64);

    // --- CSR build ---
    zero_cnt_kernel<<<cdiv(N,256), 256>>>(pcnt, N);
    hist_kernel<<<cdiv(cdiv(E,4),256), 256>>>(ei, pcnt, E);
    scan_kernel<<<1, 1024>>>(pcnt, prp, pcur, N);
    scatter_kernel<<<cdiv(cdiv(E,4),256), 256>>>(ei, pcur, pcsrc, E);

    transpose_S_kernel<<<cdiv(64*512,256), 256>>>(S, pst);

    int gm = cdiv(N, 128);
    int gw = cdiv(N * 32, 256);

    // --- layer 1 ---
    mma_gemm_kernel<128,128,16,64,32,true><<<dim3(gm,1), 256, smem128>>>(
        x, W1, hb, a1s, a1d, pas, pad_, N, 128, 128);
    node_attn_kernel<<<gw, 256>>>(prp, pcsrc, pas, pad_, pew, pden, pws, N);
    agg_csr_kernel<128><<<gw, 256>>>(prp, pcsrc, pew, pden, pws, hb, b1, actb, N, 1);

    // --- layer 2 ---
    mma_gemm_kernel<128,128,16,64,32,true><<<dim3(gm,1), 256, smem128>>>(
        actb, W2, hb, a2s, a2d, pas, pad_, N, 128, 128);
    node_attn_kernel<<<gw, 256>>>(prp, pcsrc, pas, pad_, pew, pden, pws, N);
    agg_csr_kernel<128><<<gw, 256>>>(prp, pcsrc, pew, pden, pws, hb, b2, actb, N, 1);

    // --- layer 3 (F=64, no inter-layer activation) ---
    mma_gemm_kernel<128,64,16,32,32,true><<<dim3(gm,1), 256, smem64>>>(
        actb, W3, hb, a3s, a3d, pas, pad_, N, 64, 128);
    node_attn_kernel<<<gw, 256>>>(prp, pcsrc, pas, pad_, pew, pden, pws, N);
    agg_csr_kernel<64><<<cdiv(N*16,256), 256>>>(prp, pcsrc, pew, pden, pws, hb, b3,
                                                actb, N, 0);

    // --- final projection: [N,64] @ [64,512] ---
    mma_gemm_kernel<128,128,16,64,32,false><<<dim3(gm,4), 256, smem128>>>(
        actb, pst, (float*)d_out, nullptr, nullptr, nullptr, nullptr, N, 512, 64);
}

// round 9
// speedup vs baseline: 1.4270x; 1.1959x over previous
#include <cuda_runtime.h>
#include <cuda_bf16.h>
#include <cstdint>

// ---------------------------------------------------------------------------
// GraphPooling: 3-layer GAT (single head) + final projection.
// Round 9: GEMMs use mma.sync m16n8k16 bf16 with 3-term (hi/lo) error
//          compensation — half the mma instructions of 3xTF32 at better
//          precision. Static smem again. agg_csr unrolled x4.
// ---------------------------------------------------------------------------

#define NMAX 50000
#define EMAX 800000
#define FMAX 128

__device__ float g_hbuf  [NMAX * FMAX];
__device__ float g_actbuf[NMAX * FMAX];
__device__ float g_as   [NMAX];
__device__ float g_ad   [NMAX];
__device__ float g_den  [NMAX];
__device__ float g_wself[NMAX];
__device__ float g_ew   [EMAX];
__device__ int   g_csrc [EMAX];
__device__ int   g_rp   [NMAX + 1];
__device__ int   g_cur  [NMAX];
__device__ int   g_cnt  [NMAX];
__device__ float g_ST   [64 * 512];

__device__ __forceinline__ float leaky02(float v) { return v > 0.f ? v : 0.2f * v; }

__device__ __forceinline__ uint32_t pack_bf16x2(float f0, float f1) {
    __nv_bfloat162 h = __floats2bfloat162_rn(f0, f1);
    return *reinterpret_cast<uint32_t*>(&h);
}

__device__ __forceinline__ void split_bf(float v, float& hi, float& lo) {
    __nv_bfloat16 h = __float2bfloat16_rn(v);
    hi = __bfloat162float(h);
    lo = v - hi;
}

__device__ __forceinline__ void mma_bf16(float c[4],
                                         uint32_t a0, uint32_t a1, uint32_t a2, uint32_t a3,
                                         uint32_t b0, uint32_t b1) {
    asm("mma.sync.aligned.m16n8k16.row.col.f32.bf16.bf16.f32 "
        "{%0,%1,%2,%3}, {%4,%5,%6,%7}, {%8,%9}, {%0,%1,%2,%3};"
        : "+f"(c[0]), "+f"(c[1]), "+f"(c[2]), "+f"(c[3])
        : "r"(a0), "r"(a1), "r"(a2), "r"(a3), "r"(b0), "r"(b1));
}

// ---------------------------------------------------------------------------
// Tensor GEMM (3xBF16, m16n8k16): C[M,Ncols] = A[M,K] @ B[K,Ncols].
// 2-stage smem double buffer + register prefetch. K % 16 == 0.
// Smem tiles hold bf16x2-packed hi/lo words (k-pairs for both A and B).
// If ALPHA: also emits oas/oad row dots (needs BN == Ncols, grid.y == 1).
// ---------------------------------------------------------------------------
template<int BM, int BN, int WM, int WN, bool ALPHA>
__global__ void __launch_bounds__(256)
mma_gemm_kernel(const float* __restrict__ A, const float* __restrict__ B,
                float* __restrict__ C,
                const float* __restrict__ avs, const float* __restrict__ avd,
                float* __restrict__ oas, float* __restrict__ oad,
                int M, int Ncols, int K)
{
    constexpr int BK = 16;
    constexpr int WARPS_N = BN / WN;
    static_assert((BM / WM) * (BN / WN) == 8, "8 warps");
    constexpr int MT = WM / 16;
    constexpr int NT = WN / 8;
    constexpr int ASS = BK / 2 + 4;           // A stride in 32-bit words (12)
    constexpr int BSS = BN + 8;               // B stride in 32-bit words
    constexpr int A_ITEMS = BM * (BK / 4);    // float4 loads for A (512)
    constexpr int A_PER   = A_ITEMS / 256;    // 2
    constexpr int B_ITEMS = (BK / 2) * (BN / 4);  // k-pair x col-quad

    __shared__ uint32_t As_hi[2 * BM * ASS], As_lo[2 * BM * ASS];
    __shared__ uint32_t Bs_hi[2 * (BK / 2) * BSS], Bs_lo[2 * (BK / 2) * BSS];
    __shared__ float red_s[ALPHA ? BM : 1], red_d[ALPHA ? BM : 1];

    const int tid  = threadIdx.x;
    const int lane = tid & 31;
    const int warp = tid >> 5;
    const int wm   = (warp / WARPS_N) * WM;
    const int wn   = (warp % WARPS_N) * WN;
    const int m0   = blockIdx.x * BM;
    const int n0   = blockIdx.y * BN;
    const int gid  = lane >> 2;
    const int tig  = lane & 3;

    if (ALPHA) {
        for (int i = tid; i < BM; i += 256) { red_s[i] = 0.f; red_d[i] = 0.f; }
    }

    float c[MT][NT][4];
#pragma unroll
    for (int i = 0; i < MT; i++)
#pragma unroll
        for (int j = 0; j < NT; j++) {
            c[i][j][0] = 0.f; c[i][j][1] = 0.f; c[i][j][2] = 0.f; c[i][j][3] = 0.f;
        }

    // load coordinates
    const int a_row = tid / (BK / 4) ;        // reused with +64 offset for i=1
    const int a_kq  = tid % (BK / 4);
    const int b_kp  = tid / (BN / 4);
    const int b_c4  = tid % (BN / 4);
    const bool b_act = (tid < B_ITEMS);

    float4 areg[A_PER], breg0, breg1;

    auto load_tile = [&](int k0) {
#pragma unroll
        for (int i = 0; i < A_PER; i++) {
            int row = a_row + i * (256 / (BK / 4));
            int gr  = m0 + row;
            areg[i] = make_float4(0.f, 0.f, 0.f, 0.f);
            if (gr < M) areg[i] = *(const float4*)(A + (size_t)gr * K + k0 + a_kq * 4);
        }
        if (b_act) {
            int gk = k0 + 2 * b_kp;
            breg0 = *(const float4*)(B + (size_t)gk * Ncols + n0 + b_c4 * 4);
            breg1 = *(const float4*)(B + (size_t)(gk + 1) * Ncols + n0 + b_c4 * 4);
        }
    };

    auto store_tile = [&](int st) {
#pragma unroll
        for (int i = 0; i < A_PER; i++) {
            int row = a_row + i * (256 / (BK / 4));
            float4 v = areg[i];
            float h0, l0, h1, l1, h2, l2, h3, l3;
            split_bf(v.x, h0, l0); split_bf(v.y, h1, l1);
            split_bf(v.z, h2, l2); split_bf(v.w, h3, l3);
            uint32_t* hp = &As_hi[(st * BM + row) * ASS + a_kq * 2];
            uint32_t* lp = &As_lo[(st * BM + row) * ASS + a_kq * 2];
            *(uint2*)hp = make_uint2(pack_bf16x2(h0, h1), pack_bf16x2(h2, h3));
            *(uint2*)lp = make_uint2(pack_bf16x2(l0, l1), pack_bf16x2(l2, l3));
        }
        if (b_act) {
            float h0a, l0a, h1a, l1a, h2a, l2a, h3a, l3a;
            float h0b, l0b, h1b, l1b, h2b, l2b, h3b, l3b;
            split_bf(breg0.x, h0a, l0a); split_bf(breg0.y, h1a, l1a);
            split_bf(breg0.z, h2a, l2a); split_bf(breg0.w, h3a, l3a);
            split_bf(breg1.x, h0b, l0b); split_bf(breg1.y, h1b, l1b);
            split_bf(breg1.z, h2b, l2b); split_bf(breg1.w, h3b, l3b);
            uint32_t* hp = &Bs_hi[(st * (BK / 2) + b_kp) * BSS + b_c4 * 4];
            uint32_t* lp = &Bs_lo[(st * (BK / 2) + b_kp) * BSS + b_c4 * 4];
            *(uint4*)hp = make_uint4(pack_bf16x2(h0a, h0b), pack_bf16x2(h1a, h1b),
                                     pack_bf16x2(h2a, h2b), pack_bf16x2(h3a, h3b));
            *(uint4*)lp = make_uint4(pack_bf16x2(l0a, l0b), pack_bf16x2(l1a, l1b),
                                     pack_bf16x2(l2a, l2b), pack_bf16x2(l3a, l3b));
        }
    };

    load_tile(0);
    store_tile(0);
    __syncthreads();

    const int T = K / BK;
    for (int t = 0; t < T; t++) {
        int buf = t & 1;
        if (t + 1 < T) load_tile((t + 1) * BK);

        uint32_t ah[MT][4], al[MT][4];
#pragma unroll
        for (int mt = 0; mt < MT; mt++) {
            int r = (buf * BM + wm + mt * 16 + gid) * ASS;
            ah[mt][0] = As_hi[r           + tig    ];
            ah[mt][1] = As_hi[r + 8 * ASS + tig    ];
            ah[mt][2] = As_hi[r           + tig + 4];
            ah[mt][3] = As_hi[r + 8 * ASS + tig + 4];
            al[mt][0] = As_lo[r           + tig    ];
            al[mt][1] = As_lo[r + 8 * ASS + tig    ];
            al[mt][2] = As_lo[r           + tig + 4];
            al[mt][3] = As_lo[r + 8 * ASS + tig + 4];
        }
#pragma unroll
        for (int nt = 0; nt < NT; nt++) {
            int cc = wn + nt * 8 + gid;
            int rb0 = (buf * (BK / 2) + tig)     * BSS + cc;
            int rb1 = (buf * (BK / 2) + tig + 4) * BSS + cc;
            uint32_t bh0 = Bs_hi[rb0], bh1 = Bs_hi[rb1];
            uint32_t bl0 = Bs_lo[rb0], bl1 = Bs_lo[rb1];
#pragma unroll
            for (int mt = 0; mt < MT; mt++) {
                mma_bf16(c[mt][nt], ah[mt][0], ah[mt][1], ah[mt][2], ah[mt][3], bh0, bh1);
                mma_bf16(c[mt][nt], al[mt][0], al[mt][1], al[mt][2], al[mt][3], bh0, bh1);
                mma_bf16(c[mt][nt], ah[mt][0], ah[mt][1], ah[mt][2], ah[mt][3], bl0, bl1);
            }
        }

        if (t + 1 < T) {
            store_tile(buf ^ 1);
            __syncthreads();
        }
    }

    // ---- epilogue: store C (+ fused alpha dots) ----
#pragma unroll
    for (int mt = 0; mt < MT; mt++) {
        int r0l = wm + mt * 16 + gid;
        int r1l = r0l + 8;
        int gr0 = m0 + r0l;
        int gr1 = m0 + r1l;
        float ps0 = 0.f, pd0 = 0.f, ps1 = 0.f, pd1 = 0.f;
#pragma unroll
        for (int nt = 0; nt < NT; nt++) {
            int cb = wn + nt * 8 + tig * 2;
            if (gr0 < M) {
                float2 v = make_float2(c[mt][nt][0], c[mt][nt][1]);
                *(float2*)(C + (size_t)gr0 * Ncols + n0 + cb) = v;
            }
            if (gr1 < M) {
                float2 v = make_float2(c[mt][nt][2], c[mt][nt][3]);
                *(float2*)(C + (size_t)gr1 * Ncols + n0 + cb) = v;
            }
            if (ALPHA) {
                float s0 = __ldg(&avs[cb]), s1 = __ldg(&avs[cb + 1]);
                float d0 = __ldg(&avd[cb]), d1 = __ldg(&avd[cb + 1]);
                ps0 = fmaf(c[mt][nt][0], s0, fmaf(c[mt][nt][1], s1, ps0));
                pd0 = fmaf(c[mt][nt][0], d0, fmaf(c[mt][nt][1], d1, pd0));
                ps1 = fmaf(c[mt][nt][2], s0, fmaf(c[mt][nt][3], s1, ps1));
                pd1 = fmaf(c[mt][nt][2], d0, fmaf(c[mt][nt][3], d1, pd1));
            }
        }
        if (ALPHA) {
#pragma unroll
            for (int off = 1; off < 4; off <<= 1) {
                ps0 += __shfl_xor_sync(0xffffffffu, ps0, off);
                pd0 += __shfl_xor_sync(0xffffffffu, pd0, off);
                ps1 += __shfl_xor_sync(0xffffffffu, ps1, off);
                pd1 += __shfl_xor_sync(0xffffffffu, pd1, off);
            }
            if (tig == 0) {
                atomicAdd(&red_s[r0l], ps0);
                atomicAdd(&red_d[r0l], pd0);
                atomicAdd(&red_s[r1l], ps1);
                atomicAdd(&red_d[r1l], pd1);
            }
        }
    }
    if (ALPHA) {
        __syncthreads();
        for (int i = tid; i < BM; i += 256) {
            int gr = m0 + i;
            if (gr < M) { oas[gr] = red_s[i]; oad[gr] = red_d[i]; }
        }
    }
}

// ---------------------------------------------------------------------------
// CSR build (vectorized)
// ---------------------------------------------------------------------------
__global__ void zero_cnt_kernel(int* __restrict__ cnt, int N)
{
    int i = blockIdx.x * blockDim.x + threadIdx.x;
    if (i < N) cnt[i] = 0;
}

__global__ void hist_kernel(const int* __restrict__ ei, int* __restrict__ cnt, int E)
{
    int i = (blockIdx.x * blockDim.x + threadIdx.x) * 4;
    if (i + 3 < E) {
        int4 d = *(const int4*)(ei + E + i);
        atomicAdd(&cnt[d.x], 1);
        atomicAdd(&cnt[d.y], 1);
        atomicAdd(&cnt[d.z], 1);
        atomicAdd(&cnt[d.w], 1);
    } else {
        for (int e = i; e < E; e++) atomicAdd(&cnt[ei[E + e]], 1);
    }
}

__global__ void __launch_bounds__(1024)
scan_kernel(const int* __restrict__ cnt, int* __restrict__ rp,
            int* __restrict__ cur, int N)
{
    __shared__ int sh[1024];
    int t = threadIdx.x;
    int IT = (N + 1023) / 1024;
    int base = t * IT;

    int sum = 0;
    for (int k = 0; k < IT; k++) {
        int idx = base + k;
        if (idx < N) sum += cnt[idx];
    }
    sh[t] = sum;
    __syncthreads();
    for (int off = 1; off < 1024; off <<= 1) {
        int v = (t >= off) ? sh[t - off] : 0;
        __syncthreads();
        sh[t] += v;
        __syncthreads();
    }
    int run = sh[t] - sum;
    for (int k = 0; k < IT; k++) {
        int idx = base + k;
        if (idx < N) {
            rp[idx]  = run;
            cur[idx] = run;
            run += cnt[idx];
        }
    }
    if (t == 1023) rp[N] = sh[1023];
}

__global__ void scatter_kernel(const int* __restrict__ ei, int* __restrict__ cur,
                               int* __restrict__ csrc, int E)
{
    int i = (blockIdx.x * blockDim.x + threadIdx.x) * 4;
    if (i + 3 < E) {
        int4 s = *(const int4*)(ei + i);
        int4 d = *(const int4*)(ei + E + i);
        csrc[atomicAdd(&cur[d.x], 1)] = s.x;
        csrc[atomicAdd(&cur[d.y], 1)] = s.y;
        csrc[atomicAdd(&cur[d.z], 1)] = s.z;
        csrc[atomicAdd(&cur[d.w], 1)] = s.w;
    } else {
        for (int e = i; e < E; e++)
            csrc[atomicAdd(&cur[ei[E + e]], 1)] = ei[e];
    }
}

// ---------------------------------------------------------------------------
// Per-node softmax over incoming edges (CSR). One warp per node.
// ---------------------------------------------------------------------------
__global__ void node_attn_kernel(const int* __restrict__ rp,
                                 const int* __restrict__ csrc,
                                 const float* __restrict__ as_,
                                 const float* __restrict__ ad_,
                                 float* __restrict__ ew,
                                 float* __restrict__ den,
                                 float* __restrict__ wself, int N)
{
    int node = (blockIdx.x * blockDim.x + threadIdx.x) >> 5;
    int lane = threadIdx.x & 31;
    if (node >= N) return;

    int j0 = rp[node], j1 = rp[node + 1];
    float add   = ad_[node];
    float vself = leaky02(as_[node] + add);
    float mx = vself;

    for (int j = j0 + lane; j < j1; j += 32) {
        float v = leaky02(as_[csrc[j]] + add);
        ew[j] = v;
        mx = fmaxf(mx, v);
    }
#pragma unroll
    for (int o = 16; o; o >>= 1)
        mx = fmaxf(mx, __shfl_xor_sync(0xffffffffu, mx, o));

    float sum = 0.f;
    for (int j = j0 + lane; j < j1; j += 32) {
        float w = expf(ew[j] - mx);
        ew[j] = w;
        sum += w;
    }
#pragma unroll
    for (int o = 16; o; o >>= 1)
        sum += __shfl_xor_sync(0xffffffffu, sum, o);

    if (lane == 0) {
        float ws = expf(vself - mx);
        den[node]   = sum + ws;
        wself[node] = ws;
    }
}

// ---------------------------------------------------------------------------
// CSR aggregation (x4 unrolled gather), fused self-loop/norm/bias/activation.
// ---------------------------------------------------------------------------
template<int F>
__global__ void agg_csr_kernel(const int* __restrict__ rp,
                               const int* __restrict__ csrc,
                               const float* __restrict__ ew,
                               const float* __restrict__ den,
                               const float* __restrict__ wself,
                               const float* __restrict__ h,
                               const float* __restrict__ bias,
                               float* __restrict__ out, int N, int do_leaky)
{
    constexpr int LPN = F / 4;
    constexpr int NPW = 32 / LPN;
    int lane = threadIdx.x & 31;
    int sub  = lane / LPN;
    int l    = lane % LPN;
    int node = ((blockIdx.x * blockDim.x + threadIdx.x) >> 5) * NPW + sub;
    if (node >= N) return;

    float ws = wself[node];
    float4 hv = *(const float4*)(h + (size_t)node * F + l * 4);
    float ax = ws * hv.x, ay = ws * hv.y, az = ws * hv.z, aw = ws * hv.w;

    int j0 = rp[node], j1 = rp[node + 1];
    int j = j0;
    for (; j + 3 < j1; j += 4) {
        int   s0 = __ldg(&csrc[j]),     s1 = __ldg(&csrc[j + 1]);
        int   s2 = __ldg(&csrc[j + 2]), s3 = __ldg(&csrc[j + 3]);
        float w0 = __ldg(&ew[j]),       w1 = __ldg(&ew[j + 1]);
        float w2 = __ldg(&ew[j + 2]),   w3 = __ldg(&ew[j + 3]);
        float4 v0 = *(const float4*)(h + (size_t)s0 * F + l * 4);
        float4 v1 = *(const float4*)(h + (size_t)s1 * F + l * 4);
        float4 v2 = *(const float4*)(h + (size_t)s2 * F + l * 4);
        float4 v3 = *(const float4*)(h + (size_t)s3 * F + l * 4);
        ax = fmaf(w0, v0.x, fmaf(w1, v1.x, fmaf(w2, v2.x, fmaf(w3, v3.x, ax))));
        ay = fmaf(w0, v0.y, fmaf(w1, v1.y, fmaf(w2, v2.y, fmaf(w3, v3.y, ay))));
        az = fmaf(w0, v0.z, fmaf(w1, v1.z, fmaf(w2, v2.z, fmaf(w3, v3.z, az))));
        aw = fmaf(w0, v0.w, fmaf(w1, v1.w, fmaf(w2, v2.w, fmaf(w3, v3.w, aw))));
    }
    for (; j < j1; j++) {
        int   s = __ldg(&csrc[j]);
        float w = __ldg(&ew[j]);
        float4 v = *(const float4*)(h + (size_t)s * F + l * 4);
        ax = fmaf(w, v.x, ax);
        ay = fmaf(w, v.y, ay);
        az = fmaf(w, v.z, az);
        aw = fmaf(w, v.w, aw);
    }

    float inv = 1.f / den[node];
    float4 b = *(const float4*)(bias + l * 4);
    float4 o;
    o.x = ax * inv + b.x;
    o.y = ay * inv + b.y;
    o.z = az * inv + b.z;
    o.w = aw * inv + b.w;
    if (do_leaky) {
        o.x = o.x > 0.f ? o.x : 0.1f * o.x;
        o.y = o.y > 0.f ? o.y : 0.1f * o.y;
        o.z = o.z > 0.f ? o.z : 0.1f * o.z;
        o.w = o.w > 0.f ? o.w : 0.1f * o.w;
    }
    *(float4*)(out + (size_t)node * F + l * 4) = o;
}

__global__ void transpose_S_kernel(const float* __restrict__ S, float* __restrict__ ST)
{
    int i = blockIdx.x * blockDim.x + threadIdx.x;
    if (i < 64 * 512) {
        int k = i / 512, n = i % 512;
        ST[i] = S[n * 64 + k];
    }
}

// ---------------------------------------------------------------------------
// Host
// ---------------------------------------------------------------------------
static inline int cdiv(int a, int b) { return (a + b - 1) / b; }

extern "C" void kernel_launch(void* const* d_in, const int* in_sizes, int n_in,
                              void* d_out, int out_size)
{
    const float* x   = (const float*)d_in[0];
    const int*   ei  = (const int*)d_in[1];   // int32 (JAX x64 disabled)
    const float* W1  = (const float*)d_in[2];
    const float* a1s = (const float*)d_in[3];
    const float* a1d = (const float*)d_in[4];
    const float* b1  = (const float*)d_in[5];
    const float* W2  = (const float*)d_in[6];
    const float* a2s = (const float*)d_in[7];
    const float* a2d = (const float*)d_in[8];
    const float* b2  = (const float*)d_in[9];
    const float* W3  = (const float*)d_in[10];
    const float* a3s = (const float*)d_in[11];
    const float* a3d = (const float*)d_in[12];
    const float* b3  = (const float*)d_in[13];
    const float* S   = (const float*)d_in[14];

    int N = in_sizes[0] / 128;
    int E = in_sizes[1] / 2;

    float *hb, *actb, *pas, *pad_, *pden, *pws, *pew, *pst;
    int *pcsrc, *prp, *pcur, *pcnt;
    cudaGetSymbolAddress((void**)&hb,    g_hbuf);
    cudaGetSymbolAddress((void**)&actb,  g_actbuf);
    cudaGetSymbolAddress((void**)&pas,   g_as);
    cudaGetSymbolAddress((void**)&pad_,  g_ad);
    cudaGetSymbolAddress((void**)&pden,  g_den);
    cudaGetSymbolAddress((void**)&pws,   g_wself);
    cudaGetSymbolAddress((void**)&pew,   g_ew);
    cudaGetSymbolAddress((void**)&pst,   g_ST);
    cudaGetSymbolAddress((void**)&pcsrc, g_csrc);
    cudaGetSymbolAddress((void**)&prp,   g_rp);
    cudaGetSymbolAddress((void**)&pcur,  g_cur);
    cudaGetSymbolAddress((void**)&pcnt,  g_cnt);

    // --- CSR build ---
    zero_cnt_kernel<<<cdiv(N,256), 256>>>(pcnt, N);
    hist_kernel<<<cdiv(cdiv(E,4),256), 256>>>(ei, pcnt, E);
    scan_kernel<<<1, 1024>>>(pcnt, prp, pcur, N);
    scatter_kernel<<<cdiv(cdiv(E,4),256), 256>>>(ei, pcur, pcsrc, E);

    transpose_S_kernel<<<cdiv(64*512,256), 256>>>(S, pst);

    int gm = cdiv(N, 128);
    int gw = cdiv(N * 32, 256);

    // --- layer 1 ---
    mma_gemm_kernel<128,128,64,32,true><<<dim3(gm,1), 256>>>(
        x, W1, hb, a1s, a1d, pas, pad_, N, 128, 128);
    node_attn_kernel<<<gw, 256>>>(prp, pcsrc, pas, pad_, pew, pden, pws, N);
    agg_csr_kernel<128><<<gw, 256>>>(prp, pcsrc, pew, pden, pws, hb, b1, actb, N, 1);

    // --- layer 2 ---
    mma_gemm_kernel<128,128,64,32,true><<<dim3(gm,1), 256>>>(
        actb, W2, hb, a2s, a2d, pas, pad_, N, 128, 128);
    node_attn_kernel<<<gw, 256>>>(prp, pcsrc, pas, pad_, pew, pden, pws, N);
    agg_csr_kernel<128><<<gw, 256>>>(prp, pcsrc, pew, pden, pws, hb, b2, actb, N, 1);

    // --- layer 3 (F=64, no inter-layer activation) ---
    mma_gemm_kernel<128,64,32,32,true><<<dim3(gm,1), 256>>>(
        actb, W3, hb, a3s, a3d, pas, pad_, N, 64, 128);
    node_attn_kernel<<<gw, 256>>>(prp, pcsrc, pas, pad_, pew, pden, pws, N);
    agg_csr_kernel<64><<<cdiv(N*16,256), 256>>>(prp, pcsrc, pew, pden, pws, hb, b3,
                                                actb, N, 0);

    // --- final projection: [N,64] @ [64,512] ---
    mma_gemm_kernel<128,128,64,32,false><<<dim3(gm,4), 256>>>(
        actb, pst, (float*)d_out, nullptr, nullptr, nullptr, nullptr, N, 512, 64);
}

// round 10
// speedup vs baseline: 1.4452x; 1.0127x over previous
#include <cuda_runtime.h>
#include <cuda_bf16.h>
#include <cstdint>

// ---------------------------------------------------------------------------
// GraphPooling: 3-layer GAT (single head) + final projection.
// Round 10: fused attention+aggregation (analytic softmax max: monotone
//           leaky => max over scores = leaky(max over as + ad)); one
//           warp-per-node kernel, smem-staged edge weights. bf16 3-term
//           tensor GEMMs unchanged from round 9.
// ---------------------------------------------------------------------------

#define NMAX 50000
#define EMAX 800000
#define FMAX 128

__device__ float g_hbuf  [NMAX * FMAX];
__device__ float g_actbuf[NMAX * FMAX];
__device__ float g_as   [NMAX];
__device__ float g_ad   [NMAX];
__device__ int   g_csrc [EMAX];
__device__ int   g_rp   [NMAX + 1];
__device__ int   g_cur  [NMAX];
__device__ int   g_cnt  [NMAX];
__device__ float g_ST   [64 * 512];

__device__ __forceinline__ float leaky02(float v) { return v > 0.f ? v : 0.2f * v; }

__device__ __forceinline__ uint32_t pack_bf16x2(float f0, float f1) {
    __nv_bfloat162 h = __floats2bfloat162_rn(f0, f1);
    return *reinterpret_cast<uint32_t*>(&h);
}

__device__ __forceinline__ void split_bf(float v, float& hi, float& lo) {
    __nv_bfloat16 h = __float2bfloat16_rn(v);
    hi = __bfloat162float(h);
    lo = v - hi;
}

__device__ __forceinline__ void mma_bf16(float c[4],
                                         uint32_t a0, uint32_t a1, uint32_t a2, uint32_t a3,
                                         uint32_t b0, uint32_t b1) {
    asm("mma.sync.aligned.m16n8k16.row.col.f32.bf16.bf16.f32 "
        "{%0,%1,%2,%3}, {%4,%5,%6,%7}, {%8,%9}, {%0,%1,%2,%3};"
        : "+f"(c[0]), "+f"(c[1]), "+f"(c[2]), "+f"(c[3])
        : "r"(a0), "r"(a1), "r"(a2), "r"(a3), "r"(b0), "r"(b1));
}

// ---------------------------------------------------------------------------
// Tensor GEMM (3xBF16, m16n8k16): C[M,Ncols] = A[M,K] @ B[K,Ncols].
// 2-stage smem double buffer + register prefetch. K % 16 == 0.
// If ALPHA: also emits oas/oad row dots (needs BN == Ncols, grid.y == 1).
// ---------------------------------------------------------------------------
template<int BM, int BN, int WM, int WN, bool ALPHA>
__global__ void __launch_bounds__(256)
mma_gemm_kernel(const float* __restrict__ A, const float* __restrict__ B,
                float* __restrict__ C,
                const float* __restrict__ avs, const float* __restrict__ avd,
                float* __restrict__ oas, float* __restrict__ oad,
                int M, int Ncols, int K)
{
    constexpr int BK = 16;
    constexpr int WARPS_N = BN / WN;
    static_assert((BM / WM) * (BN / WN) == 8, "8 warps");
    constexpr int MT = WM / 16;
    constexpr int NT = WN / 8;
    constexpr int ASS = BK / 2 + 4;
    constexpr int BSS = BN + 8;
    constexpr int A_PER = (BM * (BK / 4)) / 256;
    constexpr int B_ITEMS = (BK / 2) * (BN / 4);

    __shared__ uint32_t As_hi[2 * BM * ASS], As_lo[2 * BM * ASS];
    __shared__ uint32_t Bs_hi[2 * (BK / 2) * BSS], Bs_lo[2 * (BK / 2) * BSS];
    __shared__ float red_s[ALPHA ? BM : 1], red_d[ALPHA ? BM : 1];

    const int tid  = threadIdx.x;
    const int lane = tid & 31;
    const int warp = tid >> 5;
    const int wm   = (warp / WARPS_N) * WM;
    const int wn   = (warp % WARPS_N) * WN;
    const int m0   = blockIdx.x * BM;
    const int n0   = blockIdx.y * BN;
    const int gid  = lane >> 2;
    const int tig  = lane & 3;

    if (ALPHA) {
        for (int i = tid; i < BM; i += 256) { red_s[i] = 0.f; red_d[i] = 0.f; }
    }

    float c[MT][NT][4];
#pragma unroll
    for (int i = 0; i < MT; i++)
#pragma unroll
        for (int j = 0; j < NT; j++) {
            c[i][j][0] = 0.f; c[i][j][1] = 0.f; c[i][j][2] = 0.f; c[i][j][3] = 0.f;
        }

    const int a_row = tid / (BK / 4);
    const int a_kq  = tid % (BK / 4);
    const int b_kp  = tid / (BN / 4);
    const int b_c4  = tid % (BN / 4);
    const bool b_act = (tid < B_ITEMS);

    float4 areg[A_PER], breg0, breg1;

    auto load_tile = [&](int k0) {
#pragma unroll
        for (int i = 0; i < A_PER; i++) {
            int row = a_row + i * (256 / (BK / 4));
            int gr  = m0 + row;
            areg[i] = make_float4(0.f, 0.f, 0.f, 0.f);
            if (gr < M) areg[i] = *(const float4*)(A + (size_t)gr * K + k0 + a_kq * 4);
        }
        if (b_act) {
            int gk = k0 + 2 * b_kp;
            breg0 = *(const float4*)(B + (size_t)gk * Ncols + n0 + b_c4 * 4);
            breg1 = *(const float4*)(B + (size_t)(gk + 1) * Ncols + n0 + b_c4 * 4);
        }
    };

    auto store_tile = [&](int st) {
#pragma unroll
        for (int i = 0; i < A_PER; i++) {
            int row = a_row + i * (256 / (BK / 4));
            float4 v = areg[i];
            float h0, l0, h1, l1, h2, l2, h3, l3;
            split_bf(v.x, h0, l0); split_bf(v.y, h1, l1);
            split_bf(v.z, h2, l2); split_bf(v.w, h3, l3);
            uint32_t* hp = &As_hi[(st * BM + row) * ASS + a_kq * 2];
            uint32_t* lp = &As_lo[(st * BM + row) * ASS + a_kq * 2];
            *(uint2*)hp = make_uint2(pack_bf16x2(h0, h1), pack_bf16x2(h2, h3));
            *(uint2*)lp = make_uint2(pack_bf16x2(l0, l1), pack_bf16x2(l2, l3));
        }
        if (b_act) {
            float h0a, l0a, h1a, l1a, h2a, l2a, h3a, l3a;
            float h0b, l0b, h1b, l1b, h2b, l2b, h3b, l3b;
            split_bf(breg0.x, h0a, l0a); split_bf(breg0.y, h1a, l1a);
            split_bf(breg0.z, h2a, l2a); split_bf(breg0.w, h3a, l3a);
            split_bf(breg1.x, h0b, l0b); split_bf(breg1.y, h1b, l1b);
            split_bf(breg1.z, h2b, l2b); split_bf(breg1.w, h3b, l3b);
            uint32_t* hp = &Bs_hi[(st * (BK / 2) + b_kp) * BSS + b_c4 * 4];
            uint32_t* lp = &Bs_lo[(st * (BK / 2) + b_kp) * BSS + b_c4 * 4];
            *(uint4*)hp = make_uint4(pack_bf16x2(h0a, h0b), pack_bf16x2(h1a, h1b),
                                     pack_bf16x2(h2a, h2b), pack_bf16x2(h3a, h3b));
            *(uint4*)lp = make_uint4(pack_bf16x2(l0a, l0b), pack_bf16x2(l1a, l1b),
                                     pack_bf16x2(l2a, l2b), pack_bf16x2(l3a, l3b));
        }
    };

    load_tile(0);
    store_tile(0);
    __syncthreads();

    const int T = K / BK;
    for (int t = 0; t < T; t++) {
        int buf = t & 1;
        if (t + 1 < T) load_tile((t + 1) * BK);

        uint32_t ah[MT][4], al[MT][4];
#pragma unroll
        for (int mt = 0; mt < MT; mt++) {
            int r = (buf * BM + wm + mt * 16 + gid) * ASS;
            ah[mt][0] = As_hi[r           + tig    ];
            ah[mt][1] = As_hi[r + 8 * ASS + tig    ];
            ah[mt][2] = As_hi[r           + tig + 4];
            ah[mt][3] = As_hi[r + 8 * ASS + tig + 4];
            al[mt][0] = As_lo[r           + tig    ];
            al[mt][1] = As_lo[r + 8 * ASS + tig    ];
            al[mt][2] = As_lo[r           + tig + 4];
            al[mt][3] = As_lo[r + 8 * ASS + tig + 4];
        }
#pragma unroll
        for (int nt = 0; nt < NT; nt++) {
            int cc = wn + nt * 8 + gid;
            int rb0 = (buf * (BK / 2) + tig)     * BSS + cc;
            int rb1 = (buf * (BK / 2) + tig + 4) * BSS + cc;
            uint32_t bh0 = Bs_hi[rb0], bh1 = Bs_hi[rb1];
            uint32_t bl0 = Bs_lo[rb0], bl1 = Bs_lo[rb1];
#pragma unroll
            for (int mt = 0; mt < MT; mt++) {
                mma_bf16(c[mt][nt], ah[mt][0], ah[mt][1], ah[mt][2], ah[mt][3], bh0, bh1);
                mma_bf16(c[mt][nt], al[mt][0], al[mt][1], al[mt][2], al[mt][3], bh0, bh1);
                mma_bf16(c[mt][nt], ah[mt][0], ah[mt][1], ah[mt][2], ah[mt][3], bl0, bl1);
            }
        }

        if (t + 1 < T) {
            store_tile(buf ^ 1);
            __syncthreads();
        }
    }

    // ---- epilogue: store C (+ fused alpha dots) ----
#pragma unroll
    for (int mt = 0; mt < MT; mt++) {
        int r0l = wm + mt * 16 + gid;
        int r1l = r0l + 8;
        int gr0 = m0 + r0l;
        int gr1 = m0 + r1l;
        float ps0 = 0.f, pd0 = 0.f, ps1 = 0.f, pd1 = 0.f;
#pragma unroll
        for (int nt = 0; nt < NT; nt++) {
            int cb = wn + nt * 8 + tig * 2;
            if (gr0 < M) {
                float2 v = make_float2(c[mt][nt][0], c[mt][nt][1]);
                *(float2*)(C + (size_t)gr0 * Ncols + n0 + cb) = v;
            }
            if (gr1 < M) {
                float2 v = make_float2(c[mt][nt][2], c[mt][nt][3]);
                *(float2*)(C + (size_t)gr1 * Ncols + n0 + cb) = v;
            }
            if (ALPHA) {
                float s0 = __ldg(&avs[cb]), s1 = __ldg(&avs[cb + 1]);
                float d0 = __ldg(&avd[cb]), d1 = __ldg(&avd[cb + 1]);
                ps0 = fmaf(c[mt][nt][0], s0, fmaf(c[mt][nt][1], s1, ps0));
                pd0 = fmaf(c[mt][nt][0], d0, fmaf(c[mt][nt][1], d1, pd0));
                ps1 = fmaf(c[mt][nt][2], s0, fmaf(c[mt][nt][3], s1, ps1));
                pd1 = fmaf(c[mt][nt][2], d0, fmaf(c[mt][nt][3], d1, pd1));
            }
        }
        if (ALPHA) {
#pragma unroll
            for (int off = 1; off < 4; off <<= 1) {
                ps0 += __shfl_xor_sync(0xffffffffu, ps0, off);
                pd0 += __shfl_xor_sync(0xffffffffu, pd0, off);
                ps1 += __shfl_xor_sync(0xffffffffu, ps1, off);
                pd1 += __shfl_xor_sync(0xffffffffu, pd1, off);
            }
            if (tig == 0) {
                atomicAdd(&red_s[r0l], ps0);
                atomicAdd(&red_d[r0l], pd0);
                atomicAdd(&red_s[r1l], ps1);
                atomicAdd(&red_d[r1l], pd1);
            }
        }
    }
    if (ALPHA) {
        __syncthreads();
        for (int i = tid; i < BM; i += 256) {
            int gr = m0 + i;
            if (gr < M) { oas[gr] = red_s[i]; oad[gr] = red_d[i]; }
        }
    }
}

// ---------------------------------------------------------------------------
// CSR build (vectorized)
// ---------------------------------------------------------------------------
__global__ void zero_cnt_kernel(int* __restrict__ cnt, int N)
{
    int i = blockIdx.x * blockDim.x + threadIdx.x;
    if (i < N) cnt[i] = 0;
}

__global__ void hist_kernel(const int* __restrict__ ei, int* __restrict__ cnt, int E)
{
    int i = (blockIdx.x * blockDim.x + threadIdx.x) * 4;
    if (i + 3 < E) {
        int4 d = *(const int4*)(ei + E + i);
        atomicAdd(&cnt[d.x], 1);
        atomicAdd(&cnt[d.y], 1);
        atomicAdd(&cnt[d.z], 1);
        atomicAdd(&cnt[d.w], 1);
    } else {
        for (int e = i; e < E; e++) atomicAdd(&cnt[ei[E + e]], 1);
    }
}

__global__ void __launch_bounds__(1024)
scan_kernel(const int* __restrict__ cnt, int* __restrict__ rp,
            int* __restrict__ cur, int N)
{
    __shared__ int sh[1024];
    int t = threadIdx.x;
    int IT = (N + 1023) / 1024;
    int base = t * IT;

    int sum = 0;
    for (int k = 0; k < IT; k++) {
        int idx = base + k;
        if (idx < N) sum += cnt[idx];
    }
    sh[t] = sum;
    __syncthreads();
    for (int off = 1; off < 1024; off <<= 1) {
        int v = (t >= off) ? sh[t - off] : 0;
        __syncthreads();
        sh[t] += v;
        __syncthreads();
    }
    int run = sh[t] - sum;
    for (int k = 0; k < IT; k++) {
        int idx = base + k;
        if (idx < N) {
            rp[idx]  = run;
            cur[idx] = run;
            run += cnt[idx];
        }
    }
    if (t == 1023) rp[N] = sh[1023];
}

__global__ void scatter_kernel(const int* __restrict__ ei, int* __restrict__ cur,
                               int* __restrict__ csrc, int E)
{
    int i = (blockIdx.x * blockDim.x + threadIdx.x) * 4;
    if (i + 3 < E) {
        int4 s = *(const int4*)(ei + i);
        int4 d = *(const int4*)(ei + E + i);
        csrc[atomicAdd(&cur[d.x], 1)] = s.x;
        csrc[atomicAdd(&cur[d.y], 1)] = s.y;
        csrc[atomicAdd(&cur[d.z], 1)] = s.z;
        csrc[atomicAdd(&cur[d.w], 1)] = s.w;
    } else {
        for (int e = i; e < E; e++)
            csrc[atomicAdd(&cur[ei[E + e]], 1)] = ei[e];
    }
}

// ---------------------------------------------------------------------------
// Fused attention softmax + aggregation. One warp per node.
// Softmax max via monotonicity: m = leaky02(max(as over sources,self) + ad).
// Pass 2 stages 32 edge weights in per-warp smem, then gather-fma.
// ---------------------------------------------------------------------------
template<int F>
__global__ void __launch_bounds__(256)
attn_agg_kernel(const int* __restrict__ rp,
                const int* __restrict__ csrc,
                const float* __restrict__ as_,
                const float* __restrict__ ad_,
                const float* __restrict__ h,
                const float* __restrict__ bias,
                float* __restrict__ out, int N, int do_leaky)
{
    constexpr int LPN = F / 4;
    __shared__ float sw[8][32];
    __shared__ int   ss[8][32];

    int node = (blockIdx.x * blockDim.x + threadIdx.x) >> 5;
    int lane = threadIdx.x & 31;
    int wrp  = (threadIdx.x >> 5);
    if (node >= N) return;

    int j0 = rp[node], j1 = rp[node + 1];
    float asn = as_[node];
    float add = ad_[node];

    // pass 1: max of as over sources (incl. self)
    float mxs = asn;
    for (int j = j0 + lane; j < j1; j += 32)
        mxs = fmaxf(mxs, __ldg(&as_[csrc[j]]));
#pragma unroll
    for (int o = 16; o; o >>= 1)
        mxs = fmaxf(mxs, __shfl_xor_sync(0xffffffffu, mxs, o));
    float m = leaky02(mxs + add);

    // self term
    float ws = expf(leaky02(asn + add) - m);
    float ax = 0.f, ay = 0.f, az = 0.f, aw = 0.f;
    if (lane < LPN) {
        float4 hv = *(const float4*)(h + (size_t)node * F + lane * 4);
        ax = ws * hv.x; ay = ws * hv.y; az = ws * hv.z; aw = ws * hv.w;
    }

    // pass 2: chunks of 32 edges
    float sum = 0.f;
    for (int c = j0; c < j1; c += 32) {
        int jj = c + lane;
        float w = 0.f;
        int   s = 0;
        if (jj < j1) {
            s = __ldg(&csrc[jj]);
            w = expf(leaky02(__ldg(&as_[s]) + add) - m);
        }
        sum += w;
        sw[wrp][lane] = w;
        ss[wrp][lane] = s;
        __syncwarp();
        int cnt = min(32, j1 - c);
        if (lane < LPN) {
            int k = 0;
            for (; k + 3 < cnt; k += 4) {
                float w0 = sw[wrp][k],     w1 = sw[wrp][k + 1];
                float w2 = sw[wrp][k + 2], w3 = sw[wrp][k + 3];
                int   s0 = ss[wrp][k],     s1 = ss[wrp][k + 1];
                int   s2 = ss[wrp][k + 2], s3 = ss[wrp][k + 3];
                float4 v0 = *(const float4*)(h + (size_t)s0 * F + lane * 4);
                float4 v1 = *(const float4*)(h + (size_t)s1 * F + lane * 4);
                float4 v2 = *(const float4*)(h + (size_t)s2 * F + lane * 4);
                float4 v3 = *(const float4*)(h + (size_t)s3 * F + lane * 4);
                ax = fmaf(w0, v0.x, fmaf(w1, v1.x, fmaf(w2, v2.x, fmaf(w3, v3.x, ax))));
                ay = fmaf(w0, v0.y, fmaf(w1, v1.y, fmaf(w2, v2.y, fmaf(w3, v3.y, ay))));
                az = fmaf(w0, v0.z, fmaf(w1, v1.z, fmaf(w2, v2.z, fmaf(w3, v3.z, az))));
                aw = fmaf(w0, v0.w, fmaf(w1, v1.w, fmaf(w2, v2.w, fmaf(w3, v3.w, aw))));
            }
            for (; k < cnt; k++) {
                float wk = sw[wrp][k];
                int   sk = ss[wrp][k];
                float4 v = *(const float4*)(h + (size_t)sk * F + lane * 4);
                ax = fmaf(wk, v.x, ax);
                ay = fmaf(wk, v.y, ay);
                az = fmaf(wk, v.z, az);
                aw = fmaf(wk, v.w, aw);
            }
        }
        __syncwarp();
    }
#pragma unroll
    for (int o = 16; o; o >>= 1)
        sum += __shfl_xor_sync(0xffffffffu, sum, o);

    if (lane < LPN) {
        float inv = 1.f / (sum + ws);
        float4 b = *(const float4*)(bias + lane * 4);
        float4 o;
        o.x = ax * inv + b.x;
        o.y = ay * inv + b.y;
        o.z = az * inv + b.z;
        o.w = aw * inv + b.w;
        if (do_leaky) {
            o.x = o.x > 0.f ? o.x : 0.1f * o.x;
            o.y = o.y > 0.f ? o.y : 0.1f * o.y;
            o.z = o.z > 0.f ? o.z : 0.1f * o.z;
            o.w = o.w > 0.f ? o.w : 0.1f * o.w;
        }
        *(float4*)(out + (size_t)node * F + lane * 4) = o;
    }
}

__global__ void transpose_S_kernel(const float* __restrict__ S, float* __restrict__ ST)
{
    int i = blockIdx.x * blockDim.x + threadIdx.x;
    if (i < 64 * 512) {
        int k = i / 512, n = i % 512;
        ST[i] = S[n * 64 + k];
    }
}

// ---------------------------------------------------------------------------
// Host
// ---------------------------------------------------------------------------
static inline int cdiv(int a, int b) { return (a + b - 1) / b; }

extern "C" void kernel_launch(void* const* d_in, const int* in_sizes, int n_in,
                              void* d_out, int out_size)
{
    const float* x   = (const float*)d_in[0];
    const int*   ei  = (const int*)d_in[1];   // int32 (JAX x64 disabled)
    const float* W1  = (const float*)d_in[2];
    const float* a1s = (const float*)d_in[3];
    const float* a1d = (const float*)d_in[4];
    const float* b1  = (const float*)d_in[5];
    const float* W2  = (const float*)d_in[6];
    const float* a2s = (const float*)d_in[7];
    const float* a2d = (const float*)d_in[8];
    const float* b2  = (const float*)d_in[9];
    const float* W3  = (const float*)d_in[10];
    const float* a3s = (const float*)d_in[11];
    const float* a3d = (const float*)d_in[12];
    const float* b3  = (const float*)d_in[13];
    const float* S   = (const float*)d_in[14];

    int N = in_sizes[0] / 128;
    int E = in_sizes[1] / 2;

    float *hb, *actb, *pas, *pad_, *pst;
    int *pcsrc, *prp, *pcur, *pcnt;
    cudaGetSymbolAddress((void**)&hb,    g_hbuf);
    cudaGetSymbolAddress((void**)&actb,  g_actbuf);
    cudaGetSymbolAddress((void**)&pas,   g_as);
    cudaGetSymbolAddress((void**)&pad_,  g_ad);
    cudaGetSymbolAddress((void**)&pst,   g_ST);
    cudaGetSymbolAddress((void**)&pcsrc, g_csrc);
    cudaGetSymbolAddress((void**)&prp,   g_rp);
    cudaGetSymbolAddress((void**)&pcur,  g_cur);
    cudaGetSymbolAddress((void**)&pcnt,  g_cnt);

    // --- CSR build ---
    zero_cnt_kernel<<<cdiv(N,256), 256>>>(pcnt, N);
    hist_kernel<<<cdiv(cdiv(E,4),256), 256>>>(ei, pcnt, E);
    scan_kernel<<<1, 1024>>>(pcnt, prp, pcur, N);
    scatter_kernel<<<cdiv(cdiv(E,4),256), 256>>>(ei, pcur, pcsrc, E);

    transpose_S_kernel<<<cdiv(64*512,256), 256>>>(S, pst);

    int gm = cdiv(N, 128);
    int gw = cdiv(N * 32, 256);

    // --- layer 1 ---
    mma_gemm_kernel<128,128,64,32,true><<<dim3(gm,1), 256>>>(
        x, W1, hb, a1s, a1d, pas, pad_, N, 128, 128);
    attn_agg_kernel<128><<<gw, 256>>>(prp, pcsrc, pas, pad_, hb, b1, actb, N, 1);

    // --- layer 2 ---
    mma_gemm_kernel<128,128,64,32,true><<<dim3(gm,1), 256>>>(
        actb, W2, hb, a2s, a2d, pas, pad_, N, 128, 128);
    attn_agg_kernel<128><<<gw, 256>>>(prp, pcsrc, pas, pad_, hb, b2, actb, N, 1);

    // --- layer 3 (F=64, no inter-layer activation) ---
    mma_gemm_kernel<128,64,32,32,true><<<dim3(gm,1), 256>>>(
        actb, W3, hb, a3s, a3d, pas, pad_, N, 64, 128);
    attn_agg_kernel<64><<<gw, 256>>>(prp, pcsrc, pas, pad_, hb, b3, actb, N, 0);

    // --- final projection: [N,64] @ [64,512] ---
    mma_gemm_kernel<128,128,64,32,false><<<dim3(gm,4), 256>>>(
        actb, pst, (float*)d_out, nullptr, nullptr, nullptr, nullptr, N, 512, 64);
}

// round 11
// speedup vs baseline: 1.4623x; 1.0118x over previous
#include <cuda_runtime.h>
#include <cuda_bf16.h>
#include <cstdint>

// ---------------------------------------------------------------------------
// GraphPooling: 3-layer GAT (single head) + final projection.
// Round 11: GEMM ILP fix — term-major mma issue order (dependence chains
//           3 -> 16 apart) + BK=32 tiles (half the syncs), dynamic smem.
//           Edge phase / CSR unchanged from round 10.
// ---------------------------------------------------------------------------

#define NMAX 50000
#define EMAX 800000
#define FMAX 128

__device__ float g_hbuf  [NMAX * FMAX];
__device__ float g_actbuf[NMAX * FMAX];
__device__ float g_as   [NMAX];
__device__ float g_ad   [NMAX];
__device__ int   g_csrc [EMAX];
__device__ int   g_rp   [NMAX + 1];
__device__ int   g_cur  [NMAX];
__device__ int   g_cnt  [NMAX];
__device__ float g_ST   [64 * 512];

__device__ __forceinline__ float leaky02(float v) { return v > 0.f ? v : 0.2f * v; }

__device__ __forceinline__ uint32_t pack_bf16x2(float f0, float f1) {
    __nv_bfloat162 h = __floats2bfloat162_rn(f0, f1);
    return *reinterpret_cast<uint32_t*>(&h);
}

__device__ __forceinline__ void split_bf(float v, float& hi, float& lo) {
    __nv_bfloat16 h = __float2bfloat16_rn(v);
    hi = __bfloat162float(h);
    lo = v - hi;
}

__device__ __forceinline__ void mma_bf16(float c[4],
                                         uint32_t a0, uint32_t a1, uint32_t a2, uint32_t a3,
                                         uint32_t b0, uint32_t b1) {
    asm("mma.sync.aligned.m16n8k16.row.col.f32.bf16.bf16.f32 "
        "{%0,%1,%2,%3}, {%4,%5,%6,%7}, {%8,%9}, {%0,%1,%2,%3};"
        : "+f"(c[0]), "+f"(c[1]), "+f"(c[2]), "+f"(c[3])
        : "r"(a0), "r"(a1), "r"(a2), "r"(a3), "r"(b0), "r"(b1));
}

// ---------------------------------------------------------------------------
// Tensor GEMM (3xBF16, m16n8k16, BK=32): C[M,Ncols] = A[M,K] @ B[K,Ncols].
// 2-stage smem double buffer + register prefetch. K % 32 == 0.
// Dynamic smem: As_hi | As_lo | Bs_hi | Bs_lo | red_s | red_d  (uint32 words)
// If ALPHA: also emits oas/oad row dots (needs BN == Ncols, grid.y == 1).
// ---------------------------------------------------------------------------
template<int BM, int BN, int WM, int WN, bool ALPHA>
__global__ void __launch_bounds__(256)
mma_gemm_kernel(const float* __restrict__ A, const float* __restrict__ B,
                float* __restrict__ C,
                const float* __restrict__ avs, const float* __restrict__ avd,
                float* __restrict__ oas, float* __restrict__ oad,
                int M, int Ncols, int K)
{
    constexpr int BK = 32;
    constexpr int WARPS_N = BN / WN;
    static_assert((BM / WM) * (BN / WN) == 8, "8 warps");
    constexpr int MT = WM / 16;
    constexpr int NT = WN / 8;
    constexpr int ASS = BK / 2 + 4;                 // 20 words per A row
    constexpr int BSS = BN + 8;                     // words per B k-pair row
    constexpr int A_PER = (BM * (BK / 4)) / 256;    // float4 loads / thread (4)
    constexpr int B_PAIRS = ((BK / 2) * (BN / 4)) / 256;  // k-pair items / thread

    extern __shared__ uint32_t sm[];
    uint32_t* As_hi = sm;                                   // 2*BM*ASS
    uint32_t* As_lo = As_hi + 2 * BM * ASS;
    uint32_t* Bs_hi = As_lo + 2 * BM * ASS;                 // 2*(BK/2)*BSS
    uint32_t* Bs_lo = Bs_hi + 2 * (BK / 2) * BSS;
    float*    red_s = (float*)(Bs_lo + 2 * (BK / 2) * BSS); // BM
    float*    red_d = red_s + BM;

    const int tid  = threadIdx.x;
    const int lane = tid & 31;
    const int warp = tid >> 5;
    const int wm   = (warp / WARPS_N) * WM;
    const int wn   = (warp % WARPS_N) * WN;
    const int m0   = blockIdx.x * BM;
    const int n0   = blockIdx.y * BN;
    const int gid  = lane >> 2;
    const int tig  = lane & 3;

    if (ALPHA) {
        for (int i = tid; i < BM; i += 256) { red_s[i] = 0.f; red_d[i] = 0.f; }
    }

    float c[MT][NT][4];
#pragma unroll
    for (int i = 0; i < MT; i++)
#pragma unroll
        for (int j = 0; j < NT; j++) {
            c[i][j][0] = 0.f; c[i][j][1] = 0.f; c[i][j][2] = 0.f; c[i][j][3] = 0.f;
        }

    const int a_row = tid / (BK / 4);     // + i*(256/(BK/4)) per item
    const int a_kq  = tid % (BK / 4);
    const int b_kp  = tid / (BN / 4);     // k-pair row, + i*(256/(BN/4))
    const int b_c4  = tid % (BN / 4);

    float4 areg[A_PER];
    float4 breg[B_PAIRS][2];

    auto load_tile = [&](int k0) {
#pragma unroll
        for (int i = 0; i < A_PER; i++) {
            int row = a_row + i * (256 / (BK / 4));
            int gr  = m0 + row;
            areg[i] = make_float4(0.f, 0.f, 0.f, 0.f);
            if (gr < M) areg[i] = *(const float4*)(A + (size_t)gr * K + k0 + a_kq * 4);
        }
#pragma unroll
        for (int i = 0; i < B_PAIRS; i++) {
            int kp = b_kp + i * (256 / (BN / 4));
            int gk = k0 + 2 * kp;
            breg[i][0] = *(const float4*)(B + (size_t)gk * Ncols + n0 + b_c4 * 4);
            breg[i][1] = *(const float4*)(B + (size_t)(gk + 1) * Ncols + n0 + b_c4 * 4);
        }
    };

    auto store_tile = [&](int st) {
#pragma unroll
        for (int i = 0; i < A_PER; i++) {
            int row = a_row + i * (256 / (BK / 4));
            float4 v = areg[i];
            float h0, l0, h1, l1, h2, l2, h3, l3;
            split_bf(v.x, h0, l0); split_bf(v.y, h1, l1);
            split_bf(v.z, h2, l2); split_bf(v.w, h3, l3);
            uint32_t* hp = &As_hi[(st * BM + row) * ASS + a_kq * 2];
            uint32_t* lp = &As_lo[(st * BM + row) * ASS + a_kq * 2];
            *(uint2*)hp = make_uint2(pack_bf16x2(h0, h1), pack_bf16x2(h2, h3));
            *(uint2*)lp = make_uint2(pack_bf16x2(l0, l1), pack_bf16x2(l2, l3));
        }
#pragma unroll
        for (int i = 0; i < B_PAIRS; i++) {
            int kp = b_kp + i * (256 / (BN / 4));
            float4 v0 = breg[i][0], v1 = breg[i][1];
            float h0a, l0a, h1a, l1a, h2a, l2a, h3a, l3a;
            float h0b, l0b, h1b, l1b, h2b, l2b, h3b, l3b;
            split_bf(v0.x, h0a, l0a); split_bf(v0.y, h1a, l1a);
            split_bf(v0.z, h2a, l2a); split_bf(v0.w, h3a, l3a);
            split_bf(v1.x, h0b, l0b); split_bf(v1.y, h1b, l1b);
            split_bf(v1.z, h2b, l2b); split_bf(v1.w, h3b, l3b);
            uint32_t* hp = &Bs_hi[(st * (BK / 2) + kp) * BSS + b_c4 * 4];
            uint32_t* lp = &Bs_lo[(st * (BK / 2) + kp) * BSS + b_c4 * 4];
            *(uint4*)hp = make_uint4(pack_bf16x2(h0a, h0b), pack_bf16x2(h1a, h1b),
                                     pack_bf16x2(h2a, h2b), pack_bf16x2(h3a, h3b));
            *(uint4*)lp = make_uint4(pack_bf16x2(l0a, l0b), pack_bf16x2(l1a, l1b),
                                     pack_bf16x2(l2a, l2b), pack_bf16x2(l3a, l3b));
        }
    };

    load_tile(0);
    store_tile(0);
    __syncthreads();

    const int T = K / BK;
    for (int t = 0; t < T; t++) {
        int buf = t & 1;
        if (t + 1 < T) load_tile((t + 1) * BK);

#pragma unroll
        for (int ks2 = 0; ks2 < BK / 16; ks2++) {
            // ---- load all fragments for this k-chunk ----
            uint32_t ah[MT][4], al[MT][4];
#pragma unroll
            for (int mt = 0; mt < MT; mt++) {
                int r = (buf * BM + wm + mt * 16 + gid) * ASS + ks2 * 8;
                ah[mt][0] = As_hi[r           + tig    ];
                ah[mt][1] = As_hi[r + 8 * ASS + tig    ];
                ah[mt][2] = As_hi[r           + tig + 4];
                ah[mt][3] = As_hi[r + 8 * ASS + tig + 4];
                al[mt][0] = As_lo[r           + tig    ];
                al[mt][1] = As_lo[r + 8 * ASS + tig    ];
                al[mt][2] = As_lo[r           + tig + 4];
                al[mt][3] = As_lo[r + 8 * ASS + tig + 4];
            }
            uint32_t bh[NT][2], bl[NT][2];
#pragma unroll
            for (int nt = 0; nt < NT; nt++) {
                int cc  = wn + nt * 8 + gid;
                int rb0 = (buf * (BK / 2) + ks2 * 8 + tig)     * BSS + cc;
                int rb1 = (buf * (BK / 2) + ks2 * 8 + tig + 4) * BSS + cc;
                bh[nt][0] = Bs_hi[rb0]; bh[nt][1] = Bs_hi[rb1];
                bl[nt][0] = Bs_lo[rb0]; bl[nt][1] = Bs_lo[rb1];
            }
            // ---- term-major issue: 16 independent accumulators per term ----
#pragma unroll
            for (int nt = 0; nt < NT; nt++)
#pragma unroll
                for (int mt = 0; mt < MT; mt++)
                    mma_bf16(c[mt][nt], ah[mt][0], ah[mt][1], ah[mt][2], ah[mt][3],
                             bh[nt][0], bh[nt][1]);
#pragma unroll
            for (int nt = 0; nt < NT; nt++)
#pragma unroll
                for (int mt = 0; mt < MT; mt++)
                    mma_bf16(c[mt][nt], al[mt][0], al[mt][1], al[mt][2], al[mt][3],
                             bh[nt][0], bh[nt][1]);
#pragma unroll
            for (int nt = 0; nt < NT; nt++)
#pragma unroll
                for (int mt = 0; mt < MT; mt++)
                    mma_bf16(c[mt][nt], ah[mt][0], ah[mt][1], ah[mt][2], ah[mt][3],
                             bl[nt][0], bl[nt][1]);
        }

        if (t + 1 < T) {
            store_tile(buf ^ 1);
            __syncthreads();
        }
    }

    // ---- epilogue: store C (+ fused alpha dots) ----
#pragma unroll
    for (int mt = 0; mt < MT; mt++) {
        int r0l = wm + mt * 16 + gid;
        int r1l = r0l + 8;
        int gr0 = m0 + r0l;
        int gr1 = m0 + r1l;
        float ps0 = 0.f, pd0 = 0.f, ps1 = 0.f, pd1 = 0.f;
#pragma unroll
        for (int nt = 0; nt < NT; nt++) {
            int cb = wn + nt * 8 + tig * 2;
            if (gr0 < M) {
                float2 v = make_float2(c[mt][nt][0], c[mt][nt][1]);
                *(float2*)(C + (size_t)gr0 * Ncols + n0 + cb) = v;
            }
            if (gr1 < M) {
                float2 v = make_float2(c[mt][nt][2], c[mt][nt][3]);
                *(float2*)(C + (size_t)gr1 * Ncols + n0 + cb) = v;
            }
            if (ALPHA) {
                float s0 = __ldg(&avs[cb]), s1 = __ldg(&avs[cb + 1]);
                float d0 = __ldg(&avd[cb]), d1 = __ldg(&avd[cb + 1]);
                ps0 = fmaf(c[mt][nt][0], s0, fmaf(c[mt][nt][1], s1, ps0));
                pd0 = fmaf(c[mt][nt][0], d0, fmaf(c[mt][nt][1], d1, pd0));
                ps1 = fmaf(c[mt][nt][2], s0, fmaf(c[mt][nt][3], s1, ps1));
                pd1 = fmaf(c[mt][nt][2], d0, fmaf(c[mt][nt][3], d1, pd1));
            }
        }
        if (ALPHA) {
#pragma unroll
            for (int off = 1; off < 4; off <<= 1) {
                ps0 += __shfl_xor_sync(0xffffffffu, ps0, off);
                pd0 += __shfl_xor_sync(0xffffffffu, pd0, off);
                ps1 += __shfl_xor_sync(0xffffffffu, ps1, off);
                pd1 += __shfl_xor_sync(0xffffffffu, pd1, off);
            }
            if (tig == 0) {
                atomicAdd(&red_s[r0l], ps0);
                atomicAdd(&red_d[r0l], pd0);
                atomicAdd(&red_s[r1l], ps1);
                atomicAdd(&red_d[r1l], pd1);
            }
        }
    }
    if (ALPHA) {
        __syncthreads();
        for (int i = tid; i < BM; i += 256) {
            int gr = m0 + i;
            if (gr < M) { oas[gr] = red_s[i]; oad[gr] = red_d[i]; }
        }
    }
}

// dynamic smem bytes for an instantiation (BK = 32)
static inline int mma_smem_bytes(int BM, int BN) {
    int BK = 32;
    int ASS = BK / 2 + 4, BSS = BN + 8;
    return (2 * BM * ASS * 2 + 2 * (BK / 2) * BSS * 2 + 2 * BM) * 4;
}

// ---------------------------------------------------------------------------
// CSR build (vectorized)
// ---------------------------------------------------------------------------
__global__ void zero_cnt_kernel(int* __restrict__ cnt, int N)
{
    int i = blockIdx.x * blockDim.x + threadIdx.x;
    if (i < N) cnt[i] = 0;
}

__global__ void hist_kernel(const int* __restrict__ ei, int* __restrict__ cnt, int E)
{
    int i = (blockIdx.x * blockDim.x + threadIdx.x) * 4;
    if (i + 3 < E) {
        int4 d = *(const int4*)(ei + E + i);
        atomicAdd(&cnt[d.x], 1);
        atomicAdd(&cnt[d.y], 1);
        atomicAdd(&cnt[d.z], 1);
        atomicAdd(&cnt[d.w], 1);
    } else {
        for (int e = i; e < E; e++) atomicAdd(&cnt[ei[E + e]], 1);
    }
}

__global__ void __launch_bounds__(1024)
scan_kernel(const int* __restrict__ cnt, int* __restrict__ rp,
            int* __restrict__ cur, int N)
{
    __shared__ int sh[1024];
    int t = threadIdx.x;
    int IT = (N + 1023) / 1024;
    int base = t * IT;

    int sum = 0;
    for (int k = 0; k < IT; k++) {
        int idx = base + k;
        if (idx < N) sum += cnt[idx];
    }
    sh[t] = sum;
    __syncthreads();
    for (int off = 1; off < 1024; off <<= 1) {
        int v = (t >= off) ? sh[t - off] : 0;
        __syncthreads();
        sh[t] += v;
        __syncthreads();
    }
    int run = sh[t] - sum;
    for (int k = 0; k < IT; k++) {
        int idx = base + k;
        if (idx < N) {
            rp[idx]  = run;
            cur[idx] = run;
            run += cnt[idx];
        }
    }
    if (t == 1023) rp[N] = sh[1023];
}

__global__ void scatter_kernel(const int* __restrict__ ei, int* __restrict__ cur,
                               int* __restrict__ csrc, int E)
{
    int i = (blockIdx.x * blockDim.x + threadIdx.x) * 4;
    if (i + 3 < E) {
        int4 s = *(const int4*)(ei + i);
        int4 d = *(const int4*)(ei + E + i);
        csrc[atomicAdd(&cur[d.x], 1)] = s.x;
        csrc[atomicAdd(&cur[d.y], 1)] = s.y;
        csrc[atomicAdd(&cur[d.z], 1)] = s.z;
        csrc[atomicAdd(&cur[d.w], 1)] = s.w;
    } else {
        for (int e = i; e < E; e++)
            csrc[atomicAdd(&cur[ei[E + e]], 1)] = ei[e];
    }
}

// ---------------------------------------------------------------------------
// Fused attention softmax + aggregation. One warp per node.
// ---------------------------------------------------------------------------
template<int F>
__global__ void __launch_bounds__(256)
attn_agg_kernel(const int* __restrict__ rp,
                const int* __restrict__ csrc,
                const float* __restrict__ as_,
                const float* __restrict__ ad_,
                const float* __restrict__ h,
                const float* __restrict__ bias,
                float* __restrict__ out, int N, int do_leaky)
{
    constexpr int LPN = F / 4;
    __shared__ float sw[8][32];
    __shared__ int   ss[8][32];

    int node = (blockIdx.x * blockDim.x + threadIdx.x) >> 5;
    int lane = threadIdx.x & 31;
    int wrp  = (threadIdx.x >> 5);
    if (node >= N) return;

    int j0 = rp[node], j1 = rp[node + 1];
    float asn = as_[node];
    float add = ad_[node];

    float mxs = asn;
    for (int j = j0 + lane; j < j1; j += 32)
        mxs = fmaxf(mxs, __ldg(&as_[csrc[j]]));
#pragma unroll
    for (int o = 16; o; o >>= 1)
        mxs = fmaxf(mxs, __shfl_xor_sync(0xffffffffu, mxs, o));
    float m = leaky02(mxs + add);

    float ws = expf(leaky02(asn + add) - m);
    float ax = 0.f, ay = 0.f, az = 0.f, aw = 0.f;
    if (lane < LPN) {
        float4 hv = *(const float4*)(h + (size_t)node * F + lane * 4);
        ax = ws * hv.x; ay = ws * hv.y; az = ws * hv.z; aw = ws * hv.w;
    }

    float sum = 0.f;
    for (int c = j0; c < j1; c += 32) {
        int jj = c + lane;
        float w = 0.f;
        int   s = 0;
        if (jj < j1) {
            s = __ldg(&csrc[jj]);
            w = expf(leaky02(__ldg(&as_[s]) + add) - m);
        }
        sum += w;
        sw[wrp][lane] = w;
        ss[wrp][lane] = s;
        __syncwarp();
        int cnt = min(32, j1 - c);
        if (lane < LPN) {
            int k = 0;
            for (; k + 3 < cnt; k += 4) {
                float w0 = sw[wrp][k],     w1 = sw[wrp][k + 1];
                float w2 = sw[wrp][k + 2], w3 = sw[wrp][k + 3];
                int   s0 = ss[wrp][k],     s1 = ss[wrp][k + 1];
                int   s2 = ss[wrp][k + 2], s3 = ss[wrp][k + 3];
                float4 v0 = *(const float4*)(h + (size_t)s0 * F + lane * 4);
                float4 v1 = *(const float4*)(h + (size_t)s1 * F + lane * 4);
                float4 v2 = *(const float4*)(h + (size_t)s2 * F + lane * 4);
                float4 v3 = *(const float4*)(h + (size_t)s3 * F + lane * 4);
                ax = fmaf(w0, v0.x, fmaf(w1, v1.x, fmaf(w2, v2.x, fmaf(w3, v3.x, ax))));
                ay = fmaf(w0, v0.y, fmaf(w1, v1.y, fmaf(w2, v2.y, fmaf(w3, v3.y, ay))));
                az = fmaf(w0, v0.z, fmaf(w1, v1.z, fmaf(w2, v2.z, fmaf(w3, v3.z, az))));
                aw = fmaf(w0, v0.w, fmaf(w1, v1.w, fmaf(w2, v2.w, fmaf(w3, v3.w, aw))));
            }
            for (; k < cnt; k++) {
                float wk = sw[wrp][k];
                int   sk = ss[wrp][k];
                float4 v = *(const float4*)(h + (size_t)sk * F + lane * 4);
                ax = fmaf(wk, v.x, ax);
                ay = fmaf(wk, v.y, ay);
                az = fmaf(wk, v.z, az);
                aw = fmaf(wk, v.w, aw);
            }
        }
        __syncwarp();
    }
#pragma unroll
    for (int o = 16; o; o >>= 1)
        sum += __shfl_xor_sync(0xffffffffu, sum, o);

    if (lane < LPN) {
        float inv = 1.f / (sum + ws);
        float4 b = *(const float4*)(bias + lane * 4);
        float4 o;
        o.x = ax * inv + b.x;
        o.y = ay * inv + b.y;
        o.z = az * inv + b.z;
        o.w = aw * inv + b.w;
        if (do_leaky) {
            o.x = o.x > 0.f ? o.x : 0.1f * o.x;
            o.y = o.y > 0.f ? o.y : 0.1f * o.y;
            o.z = o.z > 0.f ? o.z : 0.1f * o.z;
            o.w = o.w > 0.f ? o.w : 0.1f * o.w;
        }
        *(float4*)(out + (size_t)node * F + lane * 4) = o;
    }
}

__global__ void transpose_S_kernel(const float* __restrict__ S, float* __restrict__ ST)
{
    int i = blockIdx.x * blockDim.x + threadIdx.x;
    if (i < 64 * 512) {
        int k = i / 512, n = i % 512;
        ST[i] = S[n * 64 + k];
    }
}

// ---------------------------------------------------------------------------
// Host
// ---------------------------------------------------------------------------
static inline int cdiv(int a, int b) { return (a + b - 1) / b; }

extern "C" void kernel_launch(void* const* d_in, const int* in_sizes, int n_in,
                              void* d_out, int out_size)
{
    const float* x   = (const float*)d_in[0];
    const int*   ei  = (const int*)d_in[1];   // int32 (JAX x64 disabled)
    const float* W1  = (const float*)d_in[2];
    const float* a1s = (const float*)d_in[3];
    const float* a1d = (const float*)d_in[4];
    const float* b1  = (const float*)d_in[5];
    const float* W2  = (const float*)d_in[6];
    const float* a2s = (const float*)d_in[7];
    const float* a2d = (const float*)d_in[8];
    const float* b2  = (const float*)d_in[9];
    const float* W3  = (const float*)d_in[10];
    const float* a3s = (const float*)d_in[11];
    const float* a3d = (const float*)d_in[12];
    const float* b3  = (const float*)d_in[13];
    const float* S   = (const float*)d_in[14];

    int N = in_sizes[0] / 128;
    int E = in_sizes[1] / 2;

    float *hb, *actb, *pas, *pad_, *pst;
    int *pcsrc, *prp, *pcur, *pcnt;
    cudaGetSymbolAddress((void**)&hb,    g_hbuf);
    cudaGetSymbolAddress((void**)&actb,  g_actbuf);
    cudaGetSymbolAddress((void**)&pas,   g_as);
    cudaGetSymbolAddress((void**)&pad_,  g_ad);
    cudaGetSymbolAddress((void**)&pst,   g_ST);
    cudaGetSymbolAddress((void**)&pcsrc, g_csrc);
    cudaGetSymbolAddress((void**)&prp,   g_rp);
    cudaGetSymbolAddress((void**)&pcur,  g_cur);
    cudaGetSymbolAddress((void**)&pcnt,  g_cnt);

    const int smem128 = mma_smem_bytes(128, 128);   // ~77 KB
    const int smem64  = mma_smem_bytes(128, 64);    // ~60 KB
    cudaFuncSetAttribute(mma_gemm_kernel<128,128,64,32,true>,
                         cudaFuncAttributeMaxDynamicSharedMemorySize, smem128);
    cudaFuncSetAttribute(mma_gemm_kernel<128,128,64,32,false>,
                         cudaFuncAttributeMaxDynamicSharedMemorySize, smem128);
    cudaFuncSetAttribute(mma_gemm_kernel<128,64,32,32,true>,
                         cudaFuncAttributeMaxDynamicSharedMemorySize, smem64);

    // --- CSR build ---
    zero_cnt_kernel<<<cdiv(N,256), 256>>>(pcnt, N);
    hist_kernel<<<cdiv(cdiv(E,4),256), 256>>>(ei, pcnt, E);
    scan_kernel<<<1, 1024>>>(pcnt, prp, pcur, N);
    scatter_kernel<<<cdiv(cdiv(E,4),256), 256>>>(ei, pcur, pcsrc, E);

    transpose_S_kernel<<<cdiv(64*512,256), 256>>>(S, pst);

    int gm = cdiv(N, 128);
    int gw = cdiv(N * 32, 256);

    // --- layer 1 ---
    mma_gemm_kernel<128,128,64,32,true><<<dim3(gm,1), 256, smem128>>>(
        x, W1, hb, a1s, a1d, pas, pad_, N, 128, 128);
    attn_agg_kernel<128><<<gw, 256>>>(prp, pcsrc, pas, pad_, hb, b1, actb, N, 1);

    // --- layer 2 ---
    mma_gemm_kernel<128,128,64,32,true><<<dim3(gm,1), 256, smem128>>>(
        actb, W2, hb, a2s, a2d, pas, pad_, N, 128, 128);
    attn_agg_kernel<128><<<gw, 256>>>(prp, pcsrc, pas, pad_, hb, b2, actb, N, 1);

    // --- layer 3 (F=64, no inter-layer activation) ---
    mma_gemm_kernel<128,64,32,32,true><<<dim3(gm,1), 256, smem64>>>(
        actb, W3, hb, a3s, a3d, pas, pad_, N, 64, 128);
    attn_agg_kernel<64><<<gw, 256>>>(prp, pcsrc, pas, pad_, hb, b3, actb, N, 0);

    // --- final projection: [N,64] @ [64,512] ---
    mma_gemm_kernel<128,128,64,32,false><<<dim3(gm,4), 256, smem128>>>(
        actb, pst, (float*)d_out, nullptr, nullptr, nullptr, nullptr, N, 512, 64);
}

// round 12
// speedup vs baseline: 1.4789x; 1.0114x over previous
#include <cuda_runtime.h>
#include <cuda_bf16.h>
#include <cstdint>

// ---------------------------------------------------------------------------
// GraphPooling: 3-layer GAT (single head) + final projection.
// Round 12: fork-join stream overlap — CSR build (+S transpose) runs on a
//           side stream concurrently with layer-1 GEMM in the captured graph.
//           GEMM / edge kernels identical to round 11 (316us config).
// ---------------------------------------------------------------------------

#define NMAX 50000
#define EMAX 800000
#define FMAX 128

__device__ float g_hbuf  [NMAX * FMAX];
__device__ float g_actbuf[NMAX * FMAX];
__device__ float g_as   [NMAX];
__device__ float g_ad   [NMAX];
__device__ int   g_csrc [EMAX];
__device__ int   g_rp   [NMAX + 1];
__device__ int   g_cur  [NMAX];
__device__ int   g_cnt  [NMAX];
__device__ float g_ST   [64 * 512];

__device__ __forceinline__ float leaky02(float v) { return v > 0.f ? v : 0.2f * v; }

__device__ __forceinline__ uint32_t pack_bf16x2(float f0, float f1) {
    __nv_bfloat162 h = __floats2bfloat162_rn(f0, f1);
    return *reinterpret_cast<uint32_t*>(&h);
}

__device__ __forceinline__ void split_bf(float v, float& hi, float& lo) {
    __nv_bfloat16 h = __float2bfloat16_rn(v);
    hi = __bfloat162float(h);
    lo = v - hi;
}

__device__ __forceinline__ void mma_bf16(float c[4],
                                         uint32_t a0, uint32_t a1, uint32_t a2, uint32_t a3,
                                         uint32_t b0, uint32_t b1) {
    asm("mma.sync.aligned.m16n8k16.row.col.f32.bf16.bf16.f32 "
        "{%0,%1,%2,%3}, {%4,%5,%6,%7}, {%8,%9}, {%0,%1,%2,%3};"
        : "+f"(c[0]), "+f"(c[1]), "+f"(c[2]), "+f"(c[3])
        : "r"(a0), "r"(a1), "r"(a2), "r"(a3), "r"(b0), "r"(b1));
}

// ---------------------------------------------------------------------------
// Tensor GEMM (3xBF16, m16n8k16, BK=32): C[M,Ncols] = A[M,K] @ B[K,Ncols].
// ---------------------------------------------------------------------------
template<int BM, int BN, int WM, int WN, bool ALPHA>
__global__ void __launch_bounds__(256)
mma_gemm_kernel(const float* __restrict__ A, const float* __restrict__ B,
                float* __restrict__ C,
                const float* __restrict__ avs, const float* __restrict__ avd,
                float* __restrict__ oas, float* __restrict__ oad,
                int M, int Ncols, int K)
{
    constexpr int BK = 32;
    constexpr int WARPS_N = BN / WN;
    static_assert((BM / WM) * (BN / WN) == 8, "8 warps");
    constexpr int MT = WM / 16;
    constexpr int NT = WN / 8;
    constexpr int ASS = BK / 2 + 4;
    constexpr int BSS = BN + 8;
    constexpr int A_PER = (BM * (BK / 4)) / 256;
    constexpr int B_PAIRS = ((BK / 2) * (BN / 4)) / 256;

    extern __shared__ uint32_t sm[];
    uint32_t* As_hi = sm;
    uint32_t* As_lo = As_hi + 2 * BM * ASS;
    uint32_t* Bs_hi = As_lo + 2 * BM * ASS;
    uint32_t* Bs_lo = Bs_hi + 2 * (BK / 2) * BSS;
    float*    red_s = (float*)(Bs_lo + 2 * (BK / 2) * BSS);
    float*    red_d = red_s + BM;

    const int tid  = threadIdx.x;
    const int lane = tid & 31;
    const int warp = tid >> 5;
    const int wm   = (warp / WARPS_N) * WM;
    const int wn   = (warp % WARPS_N) * WN;
    const int m0   = blockIdx.x * BM;
    const int n0   = blockIdx.y * BN;
    const int gid  = lane >> 2;
    const int tig  = lane & 3;

    if (ALPHA) {
        for (int i = tid; i < BM; i += 256) { red_s[i] = 0.f; red_d[i] = 0.f; }
    }

    float c[MT][NT][4];
#pragma unroll
    for (int i = 0; i < MT; i++)
#pragma unroll
        for (int j = 0; j < NT; j++) {
            c[i][j][0] = 0.f; c[i][j][1] = 0.f; c[i][j][2] = 0.f; c[i][j][3] = 0.f;
        }

    const int a_row = tid / (BK / 4);
    const int a_kq  = tid % (BK / 4);
    const int b_kp  = tid / (BN / 4);
    const int b_c4  = tid % (BN / 4);

    float4 areg[A_PER];
    float4 breg[B_PAIRS][2];

    auto load_tile = [&](int k0) {
#pragma unroll
        for (int i = 0; i < A_PER; i++) {
            int row = a_row + i * (256 / (BK / 4));
            int gr  = m0 + row;
            areg[i] = make_float4(0.f, 0.f, 0.f, 0.f);
            if (gr < M) areg[i] = *(const float4*)(A + (size_t)gr * K + k0 + a_kq * 4);
        }
#pragma unroll
        for (int i = 0; i < B_PAIRS; i++) {
            int kp = b_kp + i * (256 / (BN / 4));
            int gk = k0 + 2 * kp;
            breg[i][0] = *(const float4*)(B + (size_t)gk * Ncols + n0 + b_c4 * 4);
            breg[i][1] = *(const float4*)(B + (size_t)(gk + 1) * Ncols + n0 + b_c4 * 4);
        }
    };

    auto store_tile = [&](int st) {
#pragma unroll
        for (int i = 0; i < A_PER; i++) {
            int row = a_row + i * (256 / (BK / 4));
            float4 v = areg[i];
            float h0, l0, h1, l1, h2, l2, h3, l3;
            split_bf(v.x, h0, l0); split_bf(v.y, h1, l1);
            split_bf(v.z, h2, l2); split_bf(v.w, h3, l3);
            uint32_t* hp = &As_hi[(st * BM + row) * ASS + a_kq * 2];
            uint32_t* lp = &As_lo[(st * BM + row) * ASS + a_kq * 2];
            *(uint2*)hp = make_uint2(pack_bf16x2(h0, h1), pack_bf16x2(h2, h3));
            *(uint2*)lp = make_uint2(pack_bf16x2(l0, l1), pack_bf16x2(l2, l3));
        }
#pragma unroll
        for (int i = 0; i < B_PAIRS; i++) {
            int kp = b_kp + i * (256 / (BN / 4));
            float4 v0 = breg[i][0], v1 = breg[i][1];
            float h0a, l0a, h1a, l1a, h2a, l2a, h3a, l3a;
            float h0b, l0b, h1b, l1b, h2b, l2b, h3b, l3b;
            split_bf(v0.x, h0a, l0a); split_bf(v0.y, h1a, l1a);
            split_bf(v0.z, h2a, l2a); split_bf(v0.w, h3a, l3a);
            split_bf(v1.x, h0b, l0b); split_bf(v1.y, h1b, l1b);
            split_bf(v1.z, h2b, l2b); split_bf(v1.w, h3b, l3b);
            uint32_t* hp = &Bs_hi[(st * (BK / 2) + kp) * BSS + b_c4 * 4];
            uint32_t* lp = &Bs_lo[(st * (BK / 2) + kp) * BSS + b_c4 * 4];
            *(uint4*)hp = make_uint4(pack_bf16x2(h0a, h0b), pack_bf16x2(h1a, h1b),
                                     pack_bf16x2(h2a, h2b), pack_bf16x2(h3a, h3b));
            *(uint4*)lp = make_uint4(pack_bf16x2(l0a, l0b), pack_bf16x2(l1a, l1b),
                                     pack_bf16x2(l2a, l2b), pack_bf16x2(l3a, l3b));
        }
    };

    load_tile(0);
    store_tile(0);
    __syncthreads();

    const int T = K / BK;
    for (int t = 0; t < T; t++) {
        int buf = t & 1;
        if (t + 1 < T) load_tile((t + 1) * BK);

#pragma unroll
        for (int ks2 = 0; ks2 < BK / 16; ks2++) {
            uint32_t ah[MT][4], al[MT][4];
#pragma unroll
            for (int mt = 0; mt < MT; mt++) {
                int r = (buf * BM + wm + mt * 16 + gid) * ASS + ks2 * 8;
                ah[mt][0] = As_hi[r           + tig    ];
                ah[mt][1] = As_hi[r + 8 * ASS + tig    ];
                ah[mt][2] = As_hi[r           + tig + 4];
                ah[mt][3] = As_hi[r + 8 * ASS + tig + 4];
                al[mt][0] = As_lo[r           + tig    ];
                al[mt][1] = As_lo[r + 8 * ASS + tig    ];
                al[mt][2] = As_lo[r           + tig + 4];
                al[mt][3] = As_lo[r + 8 * ASS + tig + 4];
            }
            uint32_t bh[NT][2], bl[NT][2];
#pragma unroll
            for (int nt = 0; nt < NT; nt++) {
                int cc  = wn + nt * 8 + gid;
                int rb0 = (buf * (BK / 2) + ks2 * 8 + tig)     * BSS + cc;
                int rb1 = (buf * (BK / 2) + ks2 * 8 + tig + 4) * BSS + cc;
                bh[nt][0] = Bs_hi[rb0]; bh[nt][1] = Bs_hi[rb1];
                bl[nt][0] = Bs_lo[rb0]; bl[nt][1] = Bs_lo[rb1];
            }
#pragma unroll
            for (int nt = 0; nt < NT; nt++)
#pragma unroll
                for (int mt = 0; mt < MT; mt++)
                    mma_bf16(c[mt][nt], ah[mt][0], ah[mt][1], ah[mt][2], ah[mt][3],
                             bh[nt][0], bh[nt][1]);
#pragma unroll
            for (int nt = 0; nt < NT; nt++)
#pragma unroll
                for (int mt = 0; mt < MT; mt++)
                    mma_bf16(c[mt][nt], al[mt][0], al[mt][1], al[mt][2], al[mt][3],
                             bh[nt][0], bh[nt][1]);
#pragma unroll
            for (int nt = 0; nt < NT; nt++)
#pragma unroll
                for (int mt = 0; mt < MT; mt++)
                    mma_bf16(c[mt][nt], ah[mt][0], ah[mt][1], ah[mt][2], ah[mt][3],
                             bl[nt][0], bl[nt][1]);
        }

        if (t + 1 < T) {
            store_tile(buf ^ 1);
            __syncthreads();
        }
    }

#pragma unroll
    for (int mt = 0; mt < MT; mt++) {
        int r0l = wm + mt * 16 + gid;
        int r1l = r0l + 8;
        int gr0 = m0 + r0l;
        int gr1 = m0 + r1l;
        float ps0 = 0.f, pd0 = 0.f, ps1 = 0.f, pd1 = 0.f;
#pragma unroll
        for (int nt = 0; nt < NT; nt++) {
            int cb = wn + nt * 8 + tig * 2;
            if (gr0 < M) {
                float2 v = make_float2(c[mt][nt][0], c[mt][nt][1]);
                *(float2*)(C + (size_t)gr0 * Ncols + n0 + cb) = v;
            }
            if (gr1 < M) {
                float2 v = make_float2(c[mt][nt][2], c[mt][nt][3]);
                *(float2*)(C + (size_t)gr1 * Ncols + n0 + cb) = v;
            }
            if (ALPHA) {
                float s0 = __ldg(&avs[cb]), s1 = __ldg(&avs[cb + 1]);
                float d0 = __ldg(&avd[cb]), d1 = __ldg(&avd[cb + 1]);
                ps0 = fmaf(c[mt][nt][0], s0, fmaf(c[mt][nt][1], s1, ps0));
                pd0 = fmaf(c[mt][nt][0], d0, fmaf(c[mt][nt][1], d1, pd0));
                ps1 = fmaf(c[mt][nt][2], s0, fmaf(c[mt][nt][3], s1, ps1));
                pd1 = fmaf(c[mt][nt][2], d0, fmaf(c[mt][nt][3], d1, pd1));
            }
        }
        if (ALPHA) {
#pragma unroll
            for (int off = 1; off < 4; off <<= 1) {
                ps0 += __shfl_xor_sync(0xffffffffu, ps0, off);
                pd0 += __shfl_xor_sync(0xffffffffu, pd0, off);
                ps1 += __shfl_xor_sync(0xffffffffu, ps1, off);
                pd1 += __shfl_xor_sync(0xffffffffu, pd1, off);
            }
            if (tig == 0) {
                atomicAdd(&red_s[r0l], ps0);
                atomicAdd(&red_d[r0l], pd0);
                atomicAdd(&red_s[r1l], ps1);
                atomicAdd(&red_d[r1l], pd1);
            }
        }
    }
    if (ALPHA) {
        __syncthreads();
        for (int i = tid; i < BM; i += 256) {
            int gr = m0 + i;
            if (gr < M) { oas[gr] = red_s[i]; oad[gr] = red_d[i]; }
        }
    }
}

static inline int mma_smem_bytes(int BM, int BN) {
    int BK = 32;
    int ASS = BK / 2 + 4, BSS = BN + 8;
    return (2 * BM * ASS * 2 + 2 * (BK / 2) * BSS * 2 + 2 * BM) * 4;
}

// ---------------------------------------------------------------------------
// CSR build (vectorized)
// ---------------------------------------------------------------------------
__global__ void zero_cnt_kernel(int* __restrict__ cnt, int N)
{
    int i = blockIdx.x * blockDim.x + threadIdx.x;
    if (i < N) cnt[i] = 0;
}

__global__ void hist_kernel(const int* __restrict__ ei, int* __restrict__ cnt, int E)
{
    int i = (blockIdx.x * blockDim.x + threadIdx.x) * 4;
    if (i + 3 < E) {
        int4 d = *(const int4*)(ei + E + i);
        atomicAdd(&cnt[d.x], 1);
        atomicAdd(&cnt[d.y], 1);
        atomicAdd(&cnt[d.z], 1);
        atomicAdd(&cnt[d.w], 1);
    } else {
        for (int e = i; e < E; e++) atomicAdd(&cnt[ei[E + e]], 1);
    }
}

__global__ void __launch_bounds__(1024)
scan_kernel(const int* __restrict__ cnt, int* __restrict__ rp,
            int* __restrict__ cur, int N)
{
    __shared__ int sh[1024];
    int t = threadIdx.x;
    int IT = (N + 1023) / 1024;
    int base = t * IT;

    int sum = 0;
    for (int k = 0; k < IT; k++) {
        int idx = base + k;
        if (idx < N) sum += cnt[idx];
    }
    sh[t] = sum;
    __syncthreads();
    for (int off = 1; off < 1024; off <<= 1) {
        int v = (t >= off) ? sh[t - off] : 0;
        __syncthreads();
        sh[t] += v;
        __syncthreads();
    }
    int run = sh[t] - sum;
    for (int k = 0; k < IT; k++) {
        int idx = base + k;
        if (idx < N) {
            rp[idx]  = run;
            cur[idx] = run;
            run += cnt[idx];
        }
    }
    if (t == 1023) rp[N] = sh[1023];
}

__global__ void scatter_kernel(const int* __restrict__ ei, int* __restrict__ cur,
                               int* __restrict__ csrc, int E)
{
    int i = (blockIdx.x * blockDim.x + threadIdx.x) * 4;
    if (i + 3 < E) {
        int4 s = *(const int4*)(ei + i);
        int4 d = *(const int4*)(ei + E + i);
        csrc[atomicAdd(&cur[d.x], 1)] = s.x;
        csrc[atomicAdd(&cur[d.y], 1)] = s.y;
        csrc[atomicAdd(&cur[d.z], 1)] = s.z;
        csrc[atomicAdd(&cur[d.w], 1)] = s.w;
    } else {
        for (int e = i; e < E; e++)
            csrc[atomicAdd(&cur[ei[E + e]], 1)] = ei[e];
    }
}

// ---------------------------------------------------------------------------
// Fused attention softmax + aggregation. One warp per node.
// ---------------------------------------------------------------------------
template<int F>
__global__ void __launch_bounds__(256)
attn_agg_kernel(const int* __restrict__ rp,
                const int* __restrict__ csrc,
                const float* __restrict__ as_,
                const float* __restrict__ ad_,
                const float* __restrict__ h,
                const float* __restrict__ bias,
                float* __restrict__ out, int N, int do_leaky)
{
    constexpr int LPN = F / 4;
    __shared__ float sw[8][32];
    __shared__ int   ss[8][32];

    int node = (blockIdx.x * blockDim.x + threadIdx.x) >> 5;
    int lane = threadIdx.x & 31;
    int wrp  = (threadIdx.x >> 5);
    if (node >= N) return;

    int j0 = rp[node], j1 = rp[node + 1];
    float asn = as_[node];
    float add = ad_[node];

    float mxs = asn;
    for (int j = j0 + lane; j < j1; j += 32)
        mxs = fmaxf(mxs, __ldg(&as_[csrc[j]]));
#pragma unroll
    for (int o = 16; o; o >>= 1)
        mxs = fmaxf(mxs, __shfl_xor_sync(0xffffffffu, mxs, o));
    float m = leaky02(mxs + add);

    float ws = expf(leaky02(asn + add) - m);
    float ax = 0.f, ay = 0.f, az = 0.f, aw = 0.f;
    if (lane < LPN) {
        float4 hv = *(const float4*)(h + (size_t)node * F + lane * 4);
        ax = ws * hv.x; ay = ws * hv.y; az = ws * hv.z; aw = ws * hv.w;
    }

    float sum = 0.f;
    for (int c = j0; c < j1; c += 32) {
        int jj = c + lane;
        float w = 0.f;
        int   s = 0;
        if (jj < j1) {
            s = __ldg(&csrc[jj]);
            w = expf(leaky02(__ldg(&as_[s]) + add) - m);
        }
        sum += w;
        sw[wrp][lane] = w;
        ss[wrp][lane] = s;
        __syncwarp();
        int cnt = min(32, j1 - c);
        if (lane < LPN) {
            int k = 0;
            for (; k + 3 < cnt; k += 4) {
                float w0 = sw[wrp][k],     w1 = sw[wrp][k + 1];
                float w2 = sw[wrp][k + 2], w3 = sw[wrp][k + 3];
                int   s0 = ss[wrp][k],     s1 = ss[wrp][k + 1];
                int   s2 = ss[wrp][k + 2], s3 = ss[wrp][k + 3];
                float4 v0 = *(const float4*)(h + (size_t)s0 * F + lane * 4);
                float4 v1 = *(const float4*)(h + (size_t)s1 * F + lane * 4);
                float4 v2 = *(const float4*)(h + (size_t)s2 * F + lane * 4);
                float4 v3 = *(const float4*)(h + (size_t)s3 * F + lane * 4);
                ax = fmaf(w0, v0.x, fmaf(w1, v1.x, fmaf(w2, v2.x, fmaf(w3, v3.x, ax))));
                ay = fmaf(w0, v0.y, fmaf(w1, v1.y, fmaf(w2, v2.y, fmaf(w3, v3.y, ay))));
                az = fmaf(w0, v0.z, fmaf(w1, v1.z, fmaf(w2, v2.z, fmaf(w3, v3.z, az))));
                aw = fmaf(w0, v0.w, fmaf(w1, v1.w, fmaf(w2, v2.w, fmaf(w3, v3.w, aw))));
            }
            for (; k < cnt; k++) {
                float wk = sw[wrp][k];
                int   sk = ss[wrp][k];
                float4 v = *(const float4*)(h + (size_t)sk * F + lane * 4);
                ax = fmaf(wk, v.x, ax);
                ay = fmaf(wk, v.y, ay);
                az = fmaf(wk, v.z, az);
                aw = fmaf(wk, v.w, aw);
            }
        }
        __syncwarp();
    }
#pragma unroll
    for (int o = 16; o; o >>= 1)
        sum += __shfl_xor_sync(0xffffffffu, sum, o);

    if (lane < LPN) {
        float inv = 1.f / (sum + ws);
        float4 b = *(const float4*)(bias + lane * 4);
        float4 o;
        o.x = ax * inv + b.x;
        o.y = ay * inv + b.y;
        o.z = az * inv + b.z;
        o.w = aw * inv + b.w;
        if (do_leaky) {
            o.x = o.x > 0.f ? o.x : 0.1f * o.x;
            o.y = o.y > 0.f ? o.y : 0.1f * o.y;
            o.z = o.z > 0.f ? o.z : 0.1f * o.z;
            o.w = o.w > 0.f ? o.w : 0.1f * o.w;
        }
        *(float4*)(out + (size_t)node * F + lane * 4) = o;
    }
}

__global__ void transpose_S_kernel(const float* __restrict__ S, float* __restrict__ ST)
{
    int i = blockIdx.x * blockDim.x + threadIdx.x;
    if (i < 64 * 512) {
        int k = i / 512, n = i % 512;
        ST[i] = S[n * 64 + k];
    }
}

// ---------------------------------------------------------------------------
// Host
// ---------------------------------------------------------------------------
static inline int cdiv(int a, int b) { return (a + b - 1) / b; }

extern "C" void kernel_launch(void* const* d_in, const int* in_sizes, int n_in,
                              void* d_out, int out_size)
{
    const float* x   = (const float*)d_in[0];
    const int*   ei  = (const int*)d_in[1];   // int32 (JAX x64 disabled)
    const float* W1  = (const float*)d_in[2];
    const float* a1s = (const float*)d_in[3];
    const float* a1d = (const float*)d_in[4];
    const float* b1  = (const float*)d_in[5];
    const float* W2  = (const float*)d_in[6];
    const float* a2s = (const float*)d_in[7];
    const float* a2d = (const float*)d_in[8];
    const float* b2  = (const float*)d_in[9];
    const float* W3  = (const float*)d_in[10];
    const float* a3s = (const float*)d_in[11];
    const float* a3d = (const float*)d_in[12];
    const float* b3  = (const float*)d_in[13];
    const float* S   = (const float*)d_in[14];

    int N = in_sizes[0] / 128;
    int E = in_sizes[1] / 2;

    float *hb, *actb, *pas, *pad_, *pst;
    int *pcsrc, *prp, *pcur, *pcnt;
    cudaGetSymbolAddress((void**)&hb,    g_hbuf);
    cudaGetSymbolAddress((void**)&actb,  g_actbuf);
    cudaGetSymbolAddress((void**)&pas,   g_as);
    cudaGetSymbolAddress((void**)&pad_,  g_ad);
    cudaGetSymbolAddress((void**)&pst,   g_ST);
    cudaGetSymbolAddress((void**)&pcsrc, g_csrc);
    cudaGetSymbolAddress((void**)&prp,   g_rp);
    cudaGetSymbolAddress((void**)&pcur,  g_cur);
    cudaGetSymbolAddress((void**)&pcnt,  g_cnt);

    const int smem128 = mma_smem_bytes(128, 128);
    const int smem64  = mma_smem_bytes(128, 64);
    cudaFuncSetAttribute(mma_gemm_kernel<128,128,64,32,true>,
                         cudaFuncAttributeMaxDynamicSharedMemorySize, smem128);
    cudaFuncSetAttribute(mma_gemm_kernel<128,128,64,32,false>,
                         cudaFuncAttributeMaxDynamicSharedMemorySize, smem128);
    cudaFuncSetAttribute(mma_gemm_kernel<128,64,32,32,true>,
                         cudaFuncAttributeMaxDynamicSharedMemorySize, smem64);

    // --- fork a side stream for the CSR build (kernel_launch runs only for
    //     the correctness call and the capture call, so creating these per
    //     call is bounded; no device memory is allocated) ---
    cudaStream_t s2;
    cudaStreamCreateWithFlags(&s2, cudaStreamNonBlocking);
    cudaEvent_t evFork, evJoin;
    cudaEventCreateWithFlags(&evFork, cudaEventDisableTiming);
    cudaEventCreateWithFlags(&evJoin, cudaEventDisableTiming);

    cudaEventRecord(evFork, 0);           // on the (captured) default stream
    cudaStreamWaitEvent(s2, evFork, 0);   // s2 joins the capture

    // --- CSR build + S transpose on side stream ---
    zero_cnt_kernel<<<cdiv(N,256), 256, 0, s2>>>(pcnt, N);
    hist_kernel<<<cdiv(cdiv(E,4),256), 256, 0, s2>>>(ei, pcnt, E);
    scan_kernel<<<1, 1024, 0, s2>>>(pcnt, prp, pcur, N);
    scatter_kernel<<<cdiv(cdiv(E,4),256), 256, 0, s2>>>(ei, pcur, pcsrc, E);
    transpose_S_kernel<<<cdiv(64*512,256), 256, 0, s2>>>(S, pst);
    cudaEventRecord(evJoin, s2);

    int gm = cdiv(N, 128);
    int gw = cdiv(N * 32, 256);

    // --- layer 1 GEMM runs concurrently with the CSR build ---
    mma_gemm_kernel<128,128,64,32,true><<<dim3(gm,1), 256, smem128>>>(
        x, W1, hb, a1s, a1d, pas, pad_, N, 128, 128);

    cudaStreamWaitEvent(0, evJoin, 0);    // join before first aggregation

    attn_agg_kernel<128><<<gw, 256>>>(prp, pcsrc, pas, pad_, hb, b1, actb, N, 1);

    // --- layer 2 ---
    mma_gemm_kernel<128,128,64,32,true><<<dim3(gm,1), 256, smem128>>>(
        actb, W2, hb, a2s, a2d, pas, pad_, N, 128, 128);
    attn_agg_kernel<128><<<gw, 256>>>(prp, pcsrc, pas, pad_, hb, b2, actb, N, 1);

    // --- layer 3 (F=64, no inter-layer activation) ---
    mma_gemm_kernel<128,64,32,32,true><<<dim3(gm,1), 256, smem64>>>(
        actb, W3, hb, a3s, a3d, pas, pad_, N, 64, 128);
    attn_agg_kernel<64><<<gw, 256>>>(prp, pcsrc, pas, pad_, hb, b3, actb, N, 0);

    // --- final projection: [N,64] @ [64,512] ---
    mma_gemm_kernel<128,128,64,32,false><<<dim3(gm,4), 256, smem128>>>(
        actb, pst, (float*)d_out, nullptr, nullptr, nullptr, nullptr, N, 512, 64);
}

// round 13
// speedup vs baseline: 1.9168x; 1.2962x over previous
#include <cuda_runtime.h>
#include <cuda_bf16.h>
#include <cstdint>

// ---------------------------------------------------------------------------
// GraphPooling: 3-layer GAT (single head) + final projection.
// Round 13: multi-block 3-phase prefix scan for the CSR row pointers
//           (replaces the single-block scan, ~1 SM -> full chip).
//           Everything else identical to round 12 (312.7us config).
// ---------------------------------------------------------------------------

#define NMAX 50000
#define EMAX 800000
#define FMAX 128
#define SCAN_B 1024
#define NB_MAX 64

__device__ float g_hbuf  [NMAX * FMAX];
__device__ float g_actbuf[NMAX * FMAX];
__device__ float g_as   [NMAX];
__device__ float g_ad   [NMAX];
__device__ int   g_csrc [EMAX];
__device__ int   g_rp   [NMAX + 1];
__device__ int   g_cur  [NMAX];
__device__ int   g_cnt  [NMAX];
__device__ int   g_tscan[NMAX];
__device__ int   g_bsum [NB_MAX];
__device__ float g_ST   [64 * 512];

__device__ __forceinline__ float leaky02(float v) { return v > 0.f ? v : 0.2f * v; }

__device__ __forceinline__ uint32_t pack_bf16x2(float f0, float f1) {
    __nv_bfloat162 h = __floats2bfloat162_rn(f0, f1);
    return *reinterpret_cast<uint32_t*>(&h);
}

__device__ __forceinline__ void split_bf(float v, float& hi, float& lo) {
    __nv_bfloat16 h = __float2bfloat16_rn(v);
    hi = __bfloat162float(h);
    lo = v - hi;
}

__device__ __forceinline__ void mma_bf16(float c[4],
                                         uint32_t a0, uint32_t a1, uint32_t a2, uint32_t a3,
                                         uint32_t b0, uint32_t b1) {
    asm("mma.sync.aligned.m16n8k16.row.col.f32.bf16.bf16.f32 "
        "{%0,%1,%2,%3}, {%4,%5,%6,%7}, {%8,%9}, {%0,%1,%2,%3};"
        : "+f"(c[0]), "+f"(c[1]), "+f"(c[2]), "+f"(c[3])
        : "r"(a0), "r"(a1), "r"(a2), "r"(a3), "r"(b0), "r"(b1));
}

// ---------------------------------------------------------------------------
// Tensor GEMM (3xBF16, m16n8k16, BK=32): C[M,Ncols] = A[M,K] @ B[K,Ncols].
// ---------------------------------------------------------------------------
template<int BM, int BN, int WM, int WN, bool ALPHA>
__global__ void __launch_bounds__(256)
mma_gemm_kernel(const float* __restrict__ A, const float* __restrict__ B,
                float* __restrict__ C,
                const float* __restrict__ avs, const float* __restrict__ avd,
                float* __restrict__ oas, float* __restrict__ oad,
                int M, int Ncols, int K)
{
    constexpr int BK = 32;
    constexpr int WARPS_N = BN / WN;
    static_assert((BM / WM) * (BN / WN) == 8, "8 warps");
    constexpr int MT = WM / 16;
    constexpr int NT = WN / 8;
    constexpr int ASS = BK / 2 + 4;
    constexpr int BSS = BN + 8;
    constexpr int A_PER = (BM * (BK / 4)) / 256;
    constexpr int B_PAIRS = ((BK / 2) * (BN / 4)) / 256;

    extern __shared__ uint32_t sm[];
    uint32_t* As_hi = sm;
    uint32_t* As_lo = As_hi + 2 * BM * ASS;
    uint32_t* Bs_hi = As_lo + 2 * BM * ASS;
    uint32_t* Bs_lo = Bs_hi + 2 * (BK / 2) * BSS;
    float*    red_s = (float*)(Bs_lo + 2 * (BK / 2) * BSS);
    float*    red_d = red_s + BM;

    const int tid  = threadIdx.x;
    const int lane = tid & 31;
    const int warp = tid >> 5;
    const int wm   = (warp / WARPS_N) * WM;
    const int wn   = (warp % WARPS_N) * WN;
    const int m0   = blockIdx.x * BM;
    const int n0   = blockIdx.y * BN;
    const int gid  = lane >> 2;
    const int tig  = lane & 3;

    if (ALPHA) {
        for (int i = tid; i < BM; i += 256) { red_s[i] = 0.f; red_d[i] = 0.f; }
    }

    float c[MT][NT][4];
#pragma unroll
    for (int i = 0; i < MT; i++)
#pragma unroll
        for (int j = 0; j < NT; j++) {
            c[i][j][0] = 0.f; c[i][j][1] = 0.f; c[i][j][2] = 0.f; c[i][j][3] = 0.f;
        }

    const int a_row = tid / (BK / 4);
    const int a_kq  = tid % (BK / 4);
    const int b_kp  = tid / (BN / 4);
    const int b_c4  = tid % (BN / 4);

    float4 areg[A_PER];
    float4 breg[B_PAIRS][2];

    auto load_tile = [&](int k0) {
#pragma unroll
        for (int i = 0; i < A_PER; i++) {
            int row = a_row + i * (256 / (BK / 4));
            int gr  = m0 + row;
            areg[i] = make_float4(0.f, 0.f, 0.f, 0.f);
            if (gr < M) areg[i] = *(const float4*)(A + (size_t)gr * K + k0 + a_kq * 4);
        }
#pragma unroll
        for (int i = 0; i < B_PAIRS; i++) {
            int kp = b_kp + i * (256 / (BN / 4));
            int gk = k0 + 2 * kp;
            breg[i][0] = *(const float4*)(B + (size_t)gk * Ncols + n0 + b_c4 * 4);
            breg[i][1] = *(const float4*)(B + (size_t)(gk + 1) * Ncols + n0 + b_c4 * 4);
        }
    };

    auto store_tile = [&](int st) {
#pragma unroll
        for (int i = 0; i < A_PER; i++) {
            int row = a_row + i * (256 / (BK / 4));
            float4 v = areg[i];
            float h0, l0, h1, l1, h2, l2, h3, l3;
            split_bf(v.x, h0, l0); split_bf(v.y, h1, l1);
            split_bf(v.z, h2, l2); split_bf(v.w, h3, l3);
            uint32_t* hp = &As_hi[(st * BM + row) * ASS + a_kq * 2];
            uint32_t* lp = &As_lo[(st * BM + row) * ASS + a_kq * 2];
            *(uint2*)hp = make_uint2(pack_bf16x2(h0, h1), pack_bf16x2(h2, h3));
            *(uint2*)lp = make_uint2(pack_bf16x2(l0, l1), pack_bf16x2(l2, l3));
        }
#pragma unroll
        for (int i = 0; i < B_PAIRS; i++) {
            int kp = b_kp + i * (256 / (BN / 4));
            float4 v0 = breg[i][0], v1 = breg[i][1];
            float h0a, l0a, h1a, l1a, h2a, l2a, h3a, l3a;
            float h0b, l0b, h1b, l1b, h2b, l2b, h3b, l3b;
            split_bf(v0.x, h0a, l0a); split_bf(v0.y, h1a, l1a);
            split_bf(v0.z, h2a, l2a); split_bf(v0.w, h3a, l3a);
            split_bf(v1.x, h0b, l0b); split_bf(v1.y, h1b, l1b);
            split_bf(v1.z, h2b, l2b); split_bf(v1.w, h3b, l3b);
            uint32_t* hp = &Bs_hi[(st * (BK / 2) + kp) * BSS + b_c4 * 4];
            uint32_t* lp = &Bs_lo[(st * (BK / 2) + kp) * BSS + b_c4 * 4];
            *(uint4*)hp = make_uint4(pack_bf16x2(h0a, h0b), pack_bf16x2(h1a, h1b),
                                     pack_bf16x2(h2a, h2b), pack_bf16x2(h3a, h3b));
            *(uint4*)lp = make_uint4(pack_bf16x2(l0a, l0b), pack_bf16x2(l1a, l1b),
                                     pack_bf16x2(l2a, l2b), pack_bf16x2(l3a, l3b));
        }
    };

    load_tile(0);
    store_tile(0);
    __syncthreads();

    const int T = K / BK;
    for (int t = 0; t < T; t++) {
        int buf = t & 1;
        if (t + 1 < T) load_tile((t + 1) * BK);

#pragma unroll
        for (int ks2 = 0; ks2 < BK / 16; ks2++) {
            uint32_t ah[MT][4], al[MT][4];
#pragma unroll
            for (int mt = 0; mt < MT; mt++) {
                int r = (buf * BM + wm + mt * 16 + gid) * ASS + ks2 * 8;
                ah[mt][0] = As_hi[r           + tig    ];
                ah[mt][1] = As_hi[r + 8 * ASS + tig    ];
                ah[mt][2] = As_hi[r           + tig + 4];
                ah[mt][3] = As_hi[r + 8 * ASS + tig + 4];
                al[mt][0] = As_lo[r           + tig    ];
                al[mt][1] = As_lo[r + 8 * ASS + tig    ];
                al[mt][2] = As_lo[r           + tig + 4];
                al[mt][3] = As_lo[r + 8 * ASS + tig + 4];
            }
            uint32_t bh[NT][2], bl[NT][2];
#pragma unroll
            for (int nt = 0; nt < NT; nt++) {
                int cc  = wn + nt * 8 + gid;
                int rb0 = (buf * (BK / 2) + ks2 * 8 + tig)     * BSS + cc;
                int rb1 = (buf * (BK / 2) + ks2 * 8 + tig + 4) * BSS + cc;
                bh[nt][0] = Bs_hi[rb0]; bh[nt][1] = Bs_hi[rb1];
                bl[nt][0] = Bs_lo[rb0]; bl[nt][1] = Bs_lo[rb1];
            }
#pragma unroll
            for (int nt = 0; nt < NT; nt++)
#pragma unroll
                for (int mt = 0; mt < MT; mt++)
                    mma_bf16(c[mt][nt], ah[mt][0], ah[mt][1], ah[mt][2], ah[mt][3],
                             bh[nt][0], bh[nt][1]);
#pragma unroll
            for (int nt = 0; nt < NT; nt++)
#pragma unroll
                for (int mt = 0; mt < MT; mt++)
                    mma_bf16(c[mt][nt], al[mt][0], al[mt][1], al[mt][2], al[mt][3],
                             bh[nt][0], bh[nt][1]);
#pragma unroll
            for (int nt = 0; nt < NT; nt++)
#pragma unroll
                for (int mt = 0; mt < MT; mt++)
                    mma_bf16(c[mt][nt], ah[mt][0], ah[mt][1], ah[mt][2], ah[mt][3],
                             bl[nt][0], bl[nt][1]);
        }

        if (t + 1 < T) {
            store_tile(buf ^ 1);
            __syncthreads();
        }
    }

#pragma unroll
    for (int mt = 0; mt < MT; mt++) {
        int r0l = wm + mt * 16 + gid;
        int r1l = r0l + 8;
        int gr0 = m0 + r0l;
        int gr1 = m0 + r1l;
        float ps0 = 0.f, pd0 = 0.f, ps1 = 0.f, pd1 = 0.f;
#pragma unroll
        for (int nt = 0; nt < NT; nt++) {
            int cb = wn + nt * 8 + tig * 2;
            if (gr0 < M) {
                float2 v = make_float2(c[mt][nt][0], c[mt][nt][1]);
                *(float2*)(C + (size_t)gr0 * Ncols + n0 + cb) = v;
            }
            if (gr1 < M) {
                float2 v = make_float2(c[mt][nt][2], c[mt][nt][3]);
                *(float2*)(C + (size_t)gr1 * Ncols + n0 + cb) = v;
            }
            if (ALPHA) {
                float s0 = __ldg(&avs[cb]), s1 = __ldg(&avs[cb + 1]);
                float d0 = __ldg(&avd[cb]), d1 = __ldg(&avd[cb + 1]);
                ps0 = fmaf(c[mt][nt][0], s0, fmaf(c[mt][nt][1], s1, ps0));
                pd0 = fmaf(c[mt][nt][0], d0, fmaf(c[mt][nt][1], d1, pd0));
                ps1 = fmaf(c[mt][nt][2], s0, fmaf(c[mt][nt][3], s1, ps1));
                pd1 = fmaf(c[mt][nt][2], d0, fmaf(c[mt][nt][3], d1, pd1));
            }
        }
        if (ALPHA) {
#pragma unroll
            for (int off = 1; off < 4; off <<= 1) {
                ps0 += __shfl_xor_sync(0xffffffffu, ps0, off);
                pd0 += __shfl_xor_sync(0xffffffffu, pd0, off);
                ps1 += __shfl_xor_sync(0xffffffffu, ps1, off);
                pd1 += __shfl_xor_sync(0xffffffffu, pd1, off);
            }
            if (tig == 0) {
                atomicAdd(&red_s[r0l], ps0);
                atomicAdd(&red_d[r0l], pd0);
                atomicAdd(&red_s[r1l], ps1);
                atomicAdd(&red_d[r1l], pd1);
            }
        }
    }
    if (ALPHA) {
        __syncthreads();
        for (int i = tid; i < BM; i += 256) {
            int gr = m0 + i;
            if (gr < M) { oas[gr] = red_s[i]; oad[gr] = red_d[i]; }
        }
    }
}

static inline int mma_smem_bytes(int BM, int BN) {
    int BK = 32;
    int ASS = BK / 2 + 4, BSS = BN + 8;
    return (2 * BM * ASS * 2 + 2 * (BK / 2) * BSS * 2 + 2 * BM) * 4;
}

// ---------------------------------------------------------------------------
// CSR build
// ---------------------------------------------------------------------------
__global__ void zero_cnt_kernel(int* __restrict__ cnt, int N)
{
    int i = blockIdx.x * blockDim.x + threadIdx.x;
    if (i < N) cnt[i] = 0;
}

__global__ void hist_kernel(const int* __restrict__ ei, int* __restrict__ cnt, int E)
{
    int i = (blockIdx.x * blockDim.x + threadIdx.x) * 4;
    if (i + 3 < E) {
        int4 d = *(const int4*)(ei + E + i);
        atomicAdd(&cnt[d.x], 1);
        atomicAdd(&cnt[d.y], 1);
        atomicAdd(&cnt[d.z], 1);
        atomicAdd(&cnt[d.w], 1);
    } else {
        for (int e = i; e < E; e++) atomicAdd(&cnt[ei[E + e]], 1);
    }
}

// ---- 3-phase multi-block exclusive scan of cnt -> rp / cur ----
__global__ void __launch_bounds__(SCAN_B)
scan_phase1(const int* __restrict__ cnt, int* __restrict__ tscan,
            int* __restrict__ bsum, int N)
{
    __shared__ int sh[SCAN_B];
    int t = threadIdx.x;
    int i = blockIdx.x * SCAN_B + t;
    int v = (i < N) ? cnt[i] : 0;
    sh[t] = v;
    __syncthreads();
#pragma unroll
    for (int off = 1; off < SCAN_B; off <<= 1) {
        int u = (t >= off) ? sh[t - off] : 0;
        __syncthreads();
        sh[t] += u;
        __syncthreads();
    }
    if (i < N) tscan[i] = sh[t];                 // inclusive within block
    if (t == SCAN_B - 1) bsum[blockIdx.x] = sh[t];
}

__global__ void __launch_bounds__(NB_MAX)
scan_phase2(int* __restrict__ bsum, int nb)
{
    __shared__ int sh[NB_MAX];
    int t = threadIdx.x;
    int v = (t < nb) ? bsum[t] : 0;
    sh[t] = v;
    __syncthreads();
#pragma unroll
    for (int off = 1; off < NB_MAX; off <<= 1) {
        int u = (t >= off) ? sh[t - off] : 0;
        __syncthreads();
        sh[t] += u;
        __syncthreads();
    }
    if (t < nb) bsum[t] = sh[t] - v;             // exclusive block offsets
}

__global__ void __launch_bounds__(SCAN_B)
scan_phase3(const int* __restrict__ cnt, const int* __restrict__ tscan,
            const int* __restrict__ bsum, int* __restrict__ rp,
            int* __restrict__ cur, int N)
{
    int t = threadIdx.x;
    int i = blockIdx.x * SCAN_B + t;
    if (i < N) {
        int incl = tscan[i] + bsum[blockIdx.x];
        int excl = incl - cnt[i];
        rp[i]  = excl;
        cur[i] = excl;
        if (i == N - 1) rp[N] = incl;
    }
}

__global__ void scatter_kernel(const int* __restrict__ ei, int* __restrict__ cur,
                               int* __restrict__ csrc, int E)
{
    int i = (blockIdx.x * blockDim.x + threadIdx.x) * 4;
    if (i + 3 < E) {
        int4 s = *(const int4*)(ei + i);
        int4 d = *(const int4*)(ei + E + i);
        csrc[atomicAdd(&cur[d.x], 1)] = s.x;
        csrc[atomicAdd(&cur[d.y], 1)] = s.y;
        csrc[atomicAdd(&cur[d.z], 1)] = s.z;
        csrc[atomicAdd(&cur[d.w], 1)] = s.w;
    } else {
        for (int e = i; e < E; e++)
            csrc[atomicAdd(&cur[ei[E + e]], 1)] = ei[e];
    }
}

// ---------------------------------------------------------------------------
// Fused attention softmax + aggregation. One warp per node.
// ---------------------------------------------------------------------------
template<int F>
__global__ void __launch_bounds__(256)
attn_agg_kernel(const int* __restrict__ rp,
                const int* __restrict__ csrc,
                const float* __restrict__ as_,
                const float* __restrict__ ad_,
                const float* __restrict__ h,
                const float* __restrict__ bias,
                float* __restrict__ out, int N, int do_leaky)
{
    constexpr int LPN = F / 4;
    __shared__ float sw[8][32];
    __shared__ int   ss[8][32];

    int node = (blockIdx.x * blockDim.x + threadIdx.x) >> 5;
    int lane = threadIdx.x & 31;
    int wrp  = (threadIdx.x >> 5);
    if (node >= N) return;

    int j0 = rp[node], j1 = rp[node + 1];
    float asn = as_[node];
    float add = ad_[node];

    float mxs = asn;
    for (int j = j0 + lane; j < j1; j += 32)
        mxs = fmaxf(mxs, __ldg(&as_[csrc[j]]));
#pragma unroll
    for (int o = 16; o; o >>= 1)
        mxs = fmaxf(mxs, __shfl_xor_sync(0xffffffffu, mxs, o));
    float m = leaky02(mxs + add);

    float ws = expf(leaky02(asn + add) - m);
    float ax = 0.f, ay = 0.f, az = 0.f, aw = 0.f;
    if (lane < LPN) {
        float4 hv = *(const float4*)(h + (size_t)node * F + lane * 4);
        ax = ws * hv.x; ay = ws * hv.y; az = ws * hv.z; aw = ws * hv.w;
    }

    float sum = 0.f;
    for (int c = j0; c < j1; c += 32) {
        int jj = c + lane;
        float w = 0.f;
        int   s = 0;
        if (jj < j1) {
            s = __ldg(&csrc[jj]);
            w = expf(leaky02(__ldg(&as_[s]) + add) - m);
        }
        sum += w;
        sw[wrp][lane] = w;
        ss[wrp][lane] = s;
        __syncwarp();
        int cnt = min(32, j1 - c);
        if (lane < LPN) {
            int k = 0;
            for (; k + 3 < cnt; k += 4) {
                float w0 = sw[wrp][k],     w1 = sw[wrp][k + 1];
                float w2 = sw[wrp][k + 2], w3 = sw[wrp][k + 3];
                int   s0 = ss[wrp][k],     s1 = ss[wrp][k + 1];
                int   s2 = ss[wrp][k + 2], s3 = ss[wrp][k + 3];
                float4 v0 = *(const float4*)(h + (size_t)s0 * F + lane * 4);
                float4 v1 = *(const float4*)(h + (size_t)s1 * F + lane * 4);
                float4 v2 = *(const float4*)(h + (size_t)s2 * F + lane * 4);
                float4 v3 = *(const float4*)(h + (size_t)s3 * F + lane * 4);
                ax = fmaf(w0, v0.x, fmaf(w1, v1.x, fmaf(w2, v2.x, fmaf(w3, v3.x, ax))));
                ay = fmaf(w0, v0.y, fmaf(w1, v1.y, fmaf(w2, v2.y, fmaf(w3, v3.y, ay))));
                az = fmaf(w0, v0.z, fmaf(w1, v1.z, fmaf(w2, v2.z, fmaf(w3, v3.z, az))));
                aw = fmaf(w0, v0.w, fmaf(w1, v1.w, fmaf(w2, v2.w, fmaf(w3, v3.w, aw))));
            }
            for (; k < cnt; k++) {
                float wk = sw[wrp][k];
                int   sk = ss[wrp][k];
                float4 v = *(const float4*)(h + (size_t)sk * F + lane * 4);
                ax = fmaf(wk, v.x, ax);
                ay = fmaf(wk, v.y, ay);
                az = fmaf(wk, v.z, az);
                aw = fmaf(wk, v.w, aw);
            }
        }
        __syncwarp();
    }
#pragma unroll
    for (int o = 16; o; o >>= 1)
        sum += __shfl_xor_sync(0xffffffffu, sum, o);

    if (lane < LPN) {
        float inv = 1.f / (sum + ws);
        float4 b = *(const float4*)(bias + lane * 4);
        float4 o;
        o.x = ax * inv + b.x;
        o.y = ay * inv + b.y;
        o.z = az * inv + b.z;
        o.w = aw * inv + b.w;
        if (do_leaky) {
            o.x = o.x > 0.f ? o.x : 0.1f * o.x;
            o.y = o.y > 0.f ? o.y : 0.1f * o.y;
            o.z = o.z > 0.f ? o.z : 0.1f * o.z;
            o.w = o.w > 0.f ? o.w : 0.1f * o.w;
        }
        *(float4*)(out + (size_t)node * F + lane * 4) = o;
    }
}

__global__ void transpose_S_kernel(const float* __restrict__ S, float* __restrict__ ST)
{
    int i = blockIdx.x * blockDim.x + threadIdx.x;
    if (i < 64 * 512) {
        int k = i / 512, n = i % 512;
        ST[i] = S[n * 64 + k];
    }
}

// ---------------------------------------------------------------------------
// Host
// ---------------------------------------------------------------------------
static inline int cdiv(int a, int b) { return (a + b - 1) / b; }

extern "C" void kernel_launch(void* const* d_in, const int* in_sizes, int n_in,
                              void* d_out, int out_size)
{
    const float* x   = (const float*)d_in[0];
    const int*   ei  = (const int*)d_in[1];   // int32 (JAX x64 disabled)
    const float* W1  = (const float*)d_in[2];
    const float* a1s = (const float*)d_in[3];
    const float* a1d = (const float*)d_in[4];
    const float* b1  = (const float*)d_in[5];
    const float* W2  = (const float*)d_in[6];
    const float* a2s = (const float*)d_in[7];
    const float* a2d = (const float*)d_in[8];
    const float* b2  = (const float*)d_in[9];
    const float* W3  = (const float*)d_in[10];
    const float* a3s = (const float*)d_in[11];
    const float* a3d = (const float*)d_in[12];
    const float* b3  = (const float*)d_in[13];
    const float* S   = (const float*)d_in[14];

    int N = in_sizes[0] / 128;
    int E = in_sizes[1] / 2;

    float *hb, *actb, *pas, *pad_, *pst;
    int *pcsrc, *prp, *pcur, *pcnt, *ptscan, *pbsum;
    cudaGetSymbolAddress((void**)&hb,     g_hbuf);
    cudaGetSymbolAddress((void**)&actb,   g_actbuf);
    cudaGetSymbolAddress((void**)&pas,    g_as);
    cudaGetSymbolAddress((void**)&pad_,   g_ad);
    cudaGetSymbolAddress((void**)&pst,    g_ST);
    cudaGetSymbolAddress((void**)&pcsrc,  g_csrc);
    cudaGetSymbolAddress((void**)&prp,    g_rp);
    cudaGetSymbolAddress((void**)&pcur,   g_cur);
    cudaGetSymbolAddress((void**)&pcnt,   g_cnt);
    cudaGetSymbolAddress((void**)&ptscan, g_tscan);
    cudaGetSymbolAddress((void**)&pbsum,  g_bsum);

    const int smem128 = mma_smem_bytes(128, 128);
    const int smem64  = mma_smem_bytes(128, 64);
    cudaFuncSetAttribute(mma_gemm_kernel<128,128,64,32,true>,
                         cudaFuncAttributeMaxDynamicSharedMemorySize, smem128);
    cudaFuncSetAttribute(mma_gemm_kernel<128,128,64,32,false>,
                         cudaFuncAttributeMaxDynamicSharedMemorySize, smem128);
    cudaFuncSetAttribute(mma_gemm_kernel<128,64,32,32,true>,
                         cudaFuncAttributeMaxDynamicSharedMemorySize, smem64);

    // --- fork a side stream for the CSR build ---
    cudaStream_t s2;
    cudaStreamCreateWithFlags(&s2, cudaStreamNonBlocking);
    cudaEvent_t evFork, evJoin;
    cudaEventCreateWithFlags(&evFork, cudaEventDisableTiming);
    cudaEventCreateWithFlags(&evJoin, cudaEventDisableTiming);

    cudaEventRecord(evFork, 0);
    cudaStreamWaitEvent(s2, evFork, 0);

    int nb = cdiv(N, SCAN_B);   // <= 49 for N = 50000

    // --- CSR build + S transpose on side stream ---
    zero_cnt_kernel<<<cdiv(N,256), 256, 0, s2>>>(pcnt, N);
    hist_kernel<<<cdiv(cdiv(E,4),256), 256, 0, s2>>>(ei, pcnt, E);
    scan_phase1<<<nb, SCAN_B, 0, s2>>>(pcnt, ptscan, pbsum, N);
    scan_phase2<<<1, NB_MAX, 0, s2>>>(pbsum, nb);
    scan_phase3<<<nb, SCAN_B, 0, s2>>>(pcnt, ptscan, pbsum, prp, pcur, N);
    scatter_kernel<<<cdiv(cdiv(E,4),256), 256, 0, s2>>>(ei, pcur, pcsrc, E);
    transpose_S_kernel<<<cdiv(64*512,256), 256, 0, s2>>>(S, pst);
    cudaEventRecord(evJoin, s2);

    int gm = cdiv(N, 128);
    int gw = cdiv(N * 32, 256);

    // --- layer 1 GEMM runs concurrently with the CSR build ---
    mma_gemm_kernel<128,128,64,32,true><<<dim3(gm,1), 256, smem128>>>(
        x, W1, hb, a1s, a1d, pas, pad_, N, 128, 128);

    cudaStreamWaitEvent(0, evJoin, 0);

    attn_agg_kernel<128><<<gw, 256>>>(prp, pcsrc, pas, pad_, hb, b1, actb, N, 1);

    // --- layer 2 ---
    mma_gemm_kernel<128,128,64,32,true><<<dim3(gm,1), 256, smem128>>>(
        actb, W2, hb, a2s, a2d, pas, pad_, N, 128, 128);
    attn_agg_kernel<128><<<gw, 256>>>(prp, pcsrc, pas, pad_, hb, b2, actb, N, 1);

    // --- layer 3 (F=64, no inter-layer activation) ---
    mma_gemm_kernel<128,64,32,32,true><<<dim3(gm,1), 256, smem64>>>(
        actb, W3, hb, a3s, a3d, pas, pad_, N, 64, 128);
    attn_agg_kernel<64><<<gw, 256>>>(prp, pcsrc, pas, pad_, hb, b3, actb, N, 0);

    // --- final projection: [N,64] @ [64,512] ---
    mma_gemm_kernel<128,128,64,32,false><<<dim3(gm,4), 256, smem128>>>(
        actb, pst, (float*)d_out, nullptr, nullptr, nullptr, nullptr, N, 512, 64);
}

// round 15
// speedup vs baseline: 2.0099x; 1.0485x over previous
#include <cuda_runtime.h>
#include <cuda_bf16.h>
#include <cstdint>

// ---------------------------------------------------------------------------
// GraphPooling: 3-layer GAT (single head) + final projection.
// Round 15: round-14 (global-max softmax shift + subgroup-per-node agg) with
//           the divergence bug fixed: all warp syncs/shuffles in attn_agg use
//           per-subgroup masks (uniform trip count within a subgroup).
// ---------------------------------------------------------------------------

#define NMAX 50000
#define EMAX 800000
#define FMAX 128
#define SCAN_B 1024
#define NB_MAX 64

__device__ float g_hbuf  [NMAX * FMAX];
__device__ float g_actbuf[NMAX * FMAX];
__device__ float g_as   [NMAX];
__device__ float g_ad   [NMAX];
__device__ int   g_csrc [EMAX];
__device__ int   g_rp   [NMAX + 1];
__device__ int   g_cur  [NMAX];
__device__ int   g_cnt  [NMAX];
__device__ int   g_tscan[NMAX];
__device__ int   g_bsum [NB_MAX];
__device__ float g_gmax [4];
__device__ float g_ST   [64 * 512];

__device__ __forceinline__ float leaky02(float v) { return v > 0.f ? v : 0.2f * v; }

__device__ __forceinline__ void atomicMaxFloat(float* addr, float val) {
    if (val >= 0.f) atomicMax((int*)addr, __float_as_int(val));
    else            atomicMin((unsigned int*)addr, __float_as_uint(val));
}

__device__ __forceinline__ uint32_t pack_bf16x2(float f0, float f1) {
    __nv_bfloat162 h = __floats2bfloat162_rn(f0, f1);
    return *reinterpret_cast<uint32_t*>(&h);
}

__device__ __forceinline__ void split_bf(float v, float& hi, float& lo) {
    __nv_bfloat16 h = __float2bfloat16_rn(v);
    hi = __bfloat162float(h);
    lo = v - hi;
}

__device__ __forceinline__ void mma_bf16(float c[4],
                                         uint32_t a0, uint32_t a1, uint32_t a2, uint32_t a3,
                                         uint32_t b0, uint32_t b1) {
    asm("mma.sync.aligned.m16n8k16.row.col.f32.bf16.bf16.f32 "
        "{%0,%1,%2,%3}, {%4,%5,%6,%7}, {%8,%9}, {%0,%1,%2,%3};"
        : "+f"(c[0]), "+f"(c[1]), "+f"(c[2]), "+f"(c[3])
        : "r"(a0), "r"(a1), "r"(a2), "r"(a3), "r"(b0), "r"(b1));
}

// ---------------------------------------------------------------------------
// Tensor GEMM (3xBF16, m16n8k16, BK=32): C[M,Ncols] = A[M,K] @ B[K,Ncols].
// ALPHA: also emits oas/oad row dots and atomics gmax = max(oas).
// ---------------------------------------------------------------------------
template<int BM, int BN, int WM, int WN, bool ALPHA>
__global__ void __launch_bounds__(256)
mma_gemm_kernel(const float* __restrict__ A, const float* __restrict__ B,
                float* __restrict__ C,
                const float* __restrict__ avs, const float* __restrict__ avd,
                float* __restrict__ oas, float* __restrict__ oad,
                float* __restrict__ gmax,
                int M, int Ncols, int K)
{
    constexpr int BK = 32;
    constexpr int WARPS_N = BN / WN;
    static_assert((BM / WM) * (BN / WN) == 8, "8 warps");
    constexpr int MT = WM / 16;
    constexpr int NT = WN / 8;
    constexpr int ASS = BK / 2 + 4;
    constexpr int BSS = BN + 8;
    constexpr int A_PER = (BM * (BK / 4)) / 256;
    constexpr int B_PAIRS = ((BK / 2) * (BN / 4)) / 256;

    extern __shared__ uint32_t sm[];
    uint32_t* As_hi = sm;
    uint32_t* As_lo = As_hi + 2 * BM * ASS;
    uint32_t* Bs_hi = As_lo + 2 * BM * ASS;
    uint32_t* Bs_lo = Bs_hi + 2 * (BK / 2) * BSS;
    float*    red_s = (float*)(Bs_lo + 2 * (BK / 2) * BSS);
    float*    red_d = red_s + BM;

    const int tid  = threadIdx.x;
    const int lane = tid & 31;
    const int warp = tid >> 5;
    const int wm   = (warp / WARPS_N) * WM;
    const int wn   = (warp % WARPS_N) * WN;
    const int m0   = blockIdx.x * BM;
    const int n0   = blockIdx.y * BN;
    const int gid  = lane >> 2;
    const int tig  = lane & 3;

    if (ALPHA) {
        for (int i = tid; i < BM; i += 256) { red_s[i] = 0.f; red_d[i] = 0.f; }
    }

    float c[MT][NT][4];
#pragma unroll
    for (int i = 0; i < MT; i++)
#pragma unroll
        for (int j = 0; j < NT; j++) {
            c[i][j][0] = 0.f; c[i][j][1] = 0.f; c[i][j][2] = 0.f; c[i][j][3] = 0.f;
        }

    const int a_row = tid / (BK / 4);
    const int a_kq  = tid % (BK / 4);
    const int b_kp  = tid / (BN / 4);
    const int b_c4  = tid % (BN / 4);

    float4 areg[A_PER];
    float4 breg[B_PAIRS][2];

    auto load_tile = [&](int k0) {
#pragma unroll
        for (int i = 0; i < A_PER; i++) {
            int row = a_row + i * (256 / (BK / 4));
            int gr  = m0 + row;
            areg[i] = make_float4(0.f, 0.f, 0.f, 0.f);
            if (gr < M) areg[i] = *(const float4*)(A + (size_t)gr * K + k0 + a_kq * 4);
        }
#pragma unroll
        for (int i = 0; i < B_PAIRS; i++) {
            int kp = b_kp + i * (256 / (BN / 4));
            int gk = k0 + 2 * kp;
            breg[i][0] = *(const float4*)(B + (size_t)gk * Ncols + n0 + b_c4 * 4);
            breg[i][1] = *(const float4*)(B + (size_t)(gk + 1) * Ncols + n0 + b_c4 * 4);
        }
    };

    auto store_tile = [&](int st) {
#pragma unroll
        for (int i = 0; i < A_PER; i++) {
            int row = a_row + i * (256 / (BK / 4));
            float4 v = areg[i];
            float h0, l0, h1, l1, h2, l2, h3, l3;
            split_bf(v.x, h0, l0); split_bf(v.y, h1, l1);
            split_bf(v.z, h2, l2); split_bf(v.w, h3, l3);
            uint32_t* hp = &As_hi[(st * BM + row) * ASS + a_kq * 2];
            uint32_t* lp = &As_lo[(st * BM + row) * ASS + a_kq * 2];
            *(uint2*)hp = make_uint2(pack_bf16x2(h0, h1), pack_bf16x2(h2, h3));
            *(uint2*)lp = make_uint2(pack_bf16x2(l0, l1), pack_bf16x2(l2, l3));
        }
#pragma unroll
        for (int i = 0; i < B_PAIRS; i++) {
            int kp = b_kp + i * (256 / (BN / 4));
            float4 v0 = breg[i][0], v1 = breg[i][1];
            float h0a, l0a, h1a, l1a, h2a, l2a, h3a, l3a;
            float h0b, l0b, h1b, l1b, h2b, l2b, h3b, l3b;
            split_bf(v0.x, h0a, l0a); split_bf(v0.y, h1a, l1a);
            split_bf(v0.z, h2a, l2a); split_bf(v0.w, h3a, l3a);
            split_bf(v1.x, h0b, l0b); split_bf(v1.y, h1b, l1b);
            split_bf(v1.z, h2b, l2b); split_bf(v1.w, h3b, l3b);
            uint32_t* hp = &Bs_hi[(st * (BK / 2) + kp) * BSS + b_c4 * 4];
            uint32_t* lp = &Bs_lo[(st * (BK / 2) + kp) * BSS + b_c4 * 4];
            *(uint4*)hp = make_uint4(pack_bf16x2(h0a, h0b), pack_bf16x2(h1a, h1b),
                                     pack_bf16x2(h2a, h2b), pack_bf16x2(h3a, h3b));
            *(uint4*)lp = make_uint4(pack_bf16x2(l0a, l0b), pack_bf16x2(l1a, l1b),
                                     pack_bf16x2(l2a, l2b), pack_bf16x2(l3a, l3b));
        }
    };

    load_tile(0);
    store_tile(0);
    __syncthreads();

    const int T = K / BK;
    for (int t = 0; t < T; t++) {
        int buf = t & 1;
        if (t + 1 < T) load_tile((t + 1) * BK);

#pragma unroll
        for (int ks2 = 0; ks2 < BK / 16; ks2++) {
            uint32_t ah[MT][4], al[MT][4];
#pragma unroll
            for (int mt = 0; mt < MT; mt++) {
                int r = (buf * BM + wm + mt * 16 + gid) * ASS + ks2 * 8;
                ah[mt][0] = As_hi[r           + tig    ];
                ah[mt][1] = As_hi[r + 8 * ASS + tig    ];
                ah[mt][2] = As_hi[r           + tig + 4];
                ah[mt][3] = As_hi[r + 8 * ASS + tig + 4];
                al[mt][0] = As_lo[r           + tig    ];
                al[mt][1] = As_lo[r + 8 * ASS + tig    ];
                al[mt][2] = As_lo[r           + tig + 4];
                al[mt][3] = As_lo[r + 8 * ASS + tig + 4];
            }
            uint32_t bh[NT][2], bl[NT][2];
#pragma unroll
            for (int nt = 0; nt < NT; nt++) {
                int cc  = wn + nt * 8 + gid;
                int rb0 = (buf * (BK / 2) + ks2 * 8 + tig)     * BSS + cc;
                int rb1 = (buf * (BK / 2) + ks2 * 8 + tig + 4) * BSS + cc;
                bh[nt][0] = Bs_hi[rb0]; bh[nt][1] = Bs_hi[rb1];
                bl[nt][0] = Bs_lo[rb0]; bl[nt][1] = Bs_lo[rb1];
            }
#pragma unroll
            for (int nt = 0; nt < NT; nt++)
#pragma unroll
                for (int mt = 0; mt < MT; mt++)
                    mma_bf16(c[mt][nt], ah[mt][0], ah[mt][1], ah[mt][2], ah[mt][3],
                             bh[nt][0], bh[nt][1]);
#pragma unroll
            for (int nt = 0; nt < NT; nt++)
#pragma unroll
                for (int mt = 0; mt < MT; mt++)
                    mma_bf16(c[mt][nt], al[mt][0], al[mt][1], al[mt][2], al[mt][3],
                             bh[nt][0], bh[nt][1]);
#pragma unroll
            for (int nt = 0; nt < NT; nt++)
#pragma unroll
                for (int mt = 0; mt < MT; mt++)
                    mma_bf16(c[mt][nt], ah[mt][0], ah[mt][1], ah[mt][2], ah[mt][3],
                             bl[nt][0], bl[nt][1]);
        }

        if (t + 1 < T) {
            store_tile(buf ^ 1);
            __syncthreads();
        }
    }

#pragma unroll
    for (int mt = 0; mt < MT; mt++) {
        int r0l = wm + mt * 16 + gid;
        int r1l = r0l + 8;
        int gr0 = m0 + r0l;
        int gr1 = m0 + r1l;
        float ps0 = 0.f, pd0 = 0.f, ps1 = 0.f, pd1 = 0.f;
#pragma unroll
        for (int nt = 0; nt < NT; nt++) {
            int cb = wn + nt * 8 + tig * 2;
            if (gr0 < M) {
                float2 v = make_float2(c[mt][nt][0], c[mt][nt][1]);
                *(float2*)(C + (size_t)gr0 * Ncols + n0 + cb) = v;
            }
            if (gr1 < M) {
                float2 v = make_float2(c[mt][nt][2], c[mt][nt][3]);
                *(float2*)(C + (size_t)gr1 * Ncols + n0 + cb) = v;
            }
            if (ALPHA) {
                float s0 = __ldg(&avs[cb]), s1 = __ldg(&avs[cb + 1]);
                float d0 = __ldg(&avd[cb]), d1 = __ldg(&avd[cb + 1]);
                ps0 = fmaf(c[mt][nt][0], s0, fmaf(c[mt][nt][1], s1, ps0));
                pd0 = fmaf(c[mt][nt][0], d0, fmaf(c[mt][nt][1], d1, pd0));
                ps1 = fmaf(c[mt][nt][2], s0, fmaf(c[mt][nt][3], s1, ps1));
                pd1 = fmaf(c[mt][nt][2], d0, fmaf(c[mt][nt][3], d1, pd1));
            }
        }
        if (ALPHA) {
#pragma unroll
            for (int off = 1; off < 4; off <<= 1) {
                ps0 += __shfl_xor_sync(0xffffffffu, ps0, off);
                pd0 += __shfl_xor_sync(0xffffffffu, pd0, off);
                ps1 += __shfl_xor_sync(0xffffffffu, ps1, off);
                pd1 += __shfl_xor_sync(0xffffffffu, pd1, off);
            }
            if (tig == 0) {
                atomicAdd(&red_s[r0l], ps0);
                atomicAdd(&red_d[r0l], pd0);
                atomicAdd(&red_s[r1l], ps1);
                atomicAdd(&red_d[r1l], pd1);
            }
        }
    }
    if (ALPHA) {
        __syncthreads();
        float lmax = -3.4e38f;
        for (int i = tid; i < BM; i += 256) {
            int gr = m0 + i;
            if (gr < M) {
                float vs = red_s[i];
                oas[gr] = vs;
                oad[gr] = red_d[i];
                lmax = fmaxf(lmax, vs);
            }
        }
#pragma unroll
        for (int o = 16; o; o >>= 1)
            lmax = fmaxf(lmax, __shfl_xor_sync(0xffffffffu, lmax, o));
        if ((tid & 31) == 0) atomicMaxFloat(gmax, lmax);
    }
}

static inline int mma_smem_bytes(int BM, int BN) {
    int BK = 32;
    int ASS = BK / 2 + 4, BSS = BN + 8;
    return (2 * BM * ASS * 2 + 2 * (BK / 2) * BSS * 2 + 2 * BM) * 4;
}

// ---------------------------------------------------------------------------
// CSR build
// ---------------------------------------------------------------------------
__global__ void init_gmax_kernel(float* __restrict__ gmax)
{
    if (threadIdx.x < 4) gmax[threadIdx.x] = -__int_as_float(0x7F800000);
}

__global__ void zero_cnt_kernel(int* __restrict__ cnt, int N)
{
    int i = blockIdx.x * blockDim.x + threadIdx.x;
    if (i < N) cnt[i] = 0;
}

__global__ void hist_kernel(const int* __restrict__ ei, int* __restrict__ cnt, int E)
{
    int i = (blockIdx.x * blockDim.x + threadIdx.x) * 4;
    if (i + 3 < E) {
        int4 d = *(const int4*)(ei + E + i);
        atomicAdd(&cnt[d.x], 1);
        atomicAdd(&cnt[d.y], 1);
        atomicAdd(&cnt[d.z], 1);
        atomicAdd(&cnt[d.w], 1);
    } else {
        for (int e = i; e < E; e++) atomicAdd(&cnt[ei[E + e]], 1);
    }
}

__global__ void __launch_bounds__(SCAN_B)
scan_phase1(const int* __restrict__ cnt, int* __restrict__ tscan,
            int* __restrict__ bsum, int N)
{
    __shared__ int sh[SCAN_B];
    int t = threadIdx.x;
    int i = blockIdx.x * SCAN_B + t;
    int v = (i < N) ? cnt[i] : 0;
    sh[t] = v;
    __syncthreads();
#pragma unroll
    for (int off = 1; off < SCAN_B; off <<= 1) {
        int u = (t >= off) ? sh[t - off] : 0;
        __syncthreads();
        sh[t] += u;
        __syncthreads();
    }
    if (i < N) tscan[i] = sh[t];
    if (t == SCAN_B - 1) bsum[blockIdx.x] = sh[t];
}

__global__ void __launch_bounds__(NB_MAX)
scan_phase2(int* __restrict__ bsum, int nb)
{
    __shared__ int sh[NB_MAX];
    int t = threadIdx.x;
    int v = (t < nb) ? bsum[t] : 0;
    sh[t] = v;
    __syncthreads();
#pragma unroll
    for (int off = 1; off < NB_MAX; off <<= 1) {
        int u = (t >= off) ? sh[t - off] : 0;
        __syncthreads();
        sh[t] += u;
        __syncthreads();
    }
    if (t < nb) bsum[t] = sh[t] - v;
}

__global__ void __launch_bounds__(SCAN_B)
scan_phase3(const int* __restrict__ cnt, const int* __restrict__ tscan,
            const int* __restrict__ bsum, int* __restrict__ rp,
            int* __restrict__ cur, int N)
{
    int t = threadIdx.x;
    int i = blockIdx.x * SCAN_B + t;
    if (i < N) {
        int incl = tscan[i] + bsum[blockIdx.x];
        int excl = incl - cnt[i];
        rp[i]  = excl;
        cur[i] = excl;
        if (i == N - 1) rp[N] = incl;
    }
}

__global__ void scatter_kernel(const int* __restrict__ ei, int* __restrict__ cur,
                               int* __restrict__ csrc, int E)
{
    int i = (blockIdx.x * blockDim.x + threadIdx.x) * 4;
    if (i + 3 < E) {
        int4 s = *(const int4*)(ei + i);
        int4 d = *(const int4*)(ei + E + i);
        csrc[atomicAdd(&cur[d.x], 1)] = s.x;
        csrc[atomicAdd(&cur[d.y], 1)] = s.y;
        csrc[atomicAdd(&cur[d.z], 1)] = s.z;
        csrc[atomicAdd(&cur[d.w], 1)] = s.w;
    } else {
        for (int e = i; e < E; e++)
            csrc[atomicAdd(&cur[ei[E + e]], 1)] = ei[e];
    }
}

// ---------------------------------------------------------------------------
// Fused attention softmax + aggregation. SG = F/4 lanes per node.
// All syncs/shuffles use the SUBGROUP mask (uniform trip count inside a
// subgroup; warp-level sync would be divergent for F=64's two nodes/warp).
// ---------------------------------------------------------------------------
template<int F>
__global__ void __launch_bounds__(256)
attn_agg_kernel(const int* __restrict__ rp,
                const int* __restrict__ csrc,
                const float* __restrict__ as_,
                const float* __restrict__ ad_,
                const float* __restrict__ gmaxp,
                const float* __restrict__ h,
                const float* __restrict__ bias,
                float* __restrict__ out, int N, int do_leaky)
{
    constexpr int SG  = F / 4;    // lanes per node == chunk size
    constexpr int NPW = 32 / SG;  // nodes per warp
    __shared__ float sw[8 * NPW][SG];
    __shared__ int   ss[8 * NPW][SG];

    int tidg = blockIdx.x * blockDim.x + threadIdx.x;
    int lane = threadIdx.x & 31;
    int sub  = lane / SG;
    int l    = lane % SG;
    int grp  = (threadIdx.x >> 5) * NPW + sub;
    int node = (tidg >> 5) * NPW + sub;
    if (node >= N) return;

    const unsigned submask = (SG == 32) ? 0xffffffffu
                                        : (((1u << SG) - 1u) << (sub * SG));

    int j0 = rp[node], j1 = rp[node + 1];
    float add = ad_[node];
    float m   = leaky02(__ldg(gmaxp) + add);

    float ws = expf(leaky02(as_[node] + add) - m);
    float4 hv = *(const float4*)(h + (size_t)node * F + l * 4);
    float ax = ws * hv.x, ay = ws * hv.y, az = ws * hv.z, aw = ws * hv.w;

    float sum = 0.f;
    for (int c = j0; c < j1; c += SG) {
        int jj = c + l;
        float w = 0.f;
        int   s = 0;
        if (jj < j1) {
            s = __ldg(&csrc[jj]);
            w = expf(leaky02(__ldg(&as_[s]) + add) - m);
        }
        sum += w;
        sw[grp][l] = w;
        ss[grp][l] = s;
        __syncwarp(submask);
        int cnt = min(SG, j1 - c);
        int k = 0;
        for (; k + 3 < cnt; k += 4) {
            float w0 = sw[grp][k],     w1 = sw[grp][k + 1];
            float w2 = sw[grp][k + 2], w3 = sw[grp][k + 3];
            int   s0 = ss[grp][k],     s1 = ss[grp][k + 1];
            int   s2 = ss[grp][k + 2], s3 = ss[grp][k + 3];
            float4 v0 = *(const float4*)(h + (size_t)s0 * F + l * 4);
            float4 v1 = *(const float4*)(h + (size_t)s1 * F + l * 4);
            float4 v2 = *(const float4*)(h + (size_t)s2 * F + l * 4);
            float4 v3 = *(const float4*)(h + (size_t)s3 * F + l * 4);
            ax = fmaf(w0, v0.x, fmaf(w1, v1.x, fmaf(w2, v2.x, fmaf(w3, v3.x, ax))));
            ay = fmaf(w0, v0.y, fmaf(w1, v1.y, fmaf(w2, v2.y, fmaf(w3, v3.y, ay))));
            az = fmaf(w0, v0.z, fmaf(w1, v1.z, fmaf(w2, v2.z, fmaf(w3, v3.z, az))));
            aw = fmaf(w0, v0.w, fmaf(w1, v1.w, fmaf(w2, v2.w, fmaf(w3, v3.w, aw))));
        }
        for (; k < cnt; k++) {
            float wk = sw[grp][k];
            int   sk = ss[grp][k];
            float4 v = *(const float4*)(h + (size_t)sk * F + l * 4);
            ax = fmaf(wk, v.x, ax);
            ay = fmaf(wk, v.y, ay);
            az = fmaf(wk, v.z, az);
            aw = fmaf(wk, v.w, aw);
        }
        __syncwarp(submask);
    }
#pragma unroll
    for (int o = SG / 2; o; o >>= 1)
        sum += __shfl_xor_sync(submask, sum, o);

    float inv = 1.f / (sum + ws);
    float4 b = *(const float4*)(bias + l * 4);
    float4 o;
    o.x = ax * inv + b.x;
    o.y = ay * inv + b.y;
    o.z = az * inv + b.z;
    o.w = aw * inv + b.w;
    if (do_leaky) {
        o.x = o.x > 0.f ? o.x : 0.1f * o.x;
        o.y = o.y > 0.f ? o.y : 0.1f * o.y;
        o.z = o.z > 0.f ? o.z : 0.1f * o.z;
        o.w = o.w > 0.f ? o.w : 0.1f * o.w;
    }
    *(float4*)(out + (size_t)node * F + l * 4) = o;
}

__global__ void transpose_S_kernel(const float* __restrict__ S, float* __restrict__ ST)
{
    int i = blockIdx.x * blockDim.x + threadIdx.x;
    if (i < 64 * 512) {
        int k = i / 512, n = i % 512;
        ST[i] = S[n * 64 + k];
    }
}

// ---------------------------------------------------------------------------
// Host
// ---------------------------------------------------------------------------
static inline int cdiv(int a, int b) { return (a + b - 1) / b; }

extern "C" void kernel_launch(void* const* d_in, const int* in_sizes, int n_in,
                              void* d_out, int out_size)
{
    const float* x   = (const float*)d_in[0];
    const int*   ei  = (const int*)d_in[1];   // int32 (JAX x64 disabled)
    const float* W1  = (const float*)d_in[2];
    const float* a1s = (const float*)d_in[3];
    const float* a1d = (const float*)d_in[4];
    const float* b1  = (const float*)d_in[5];
    const float* W2  = (const float*)d_in[6];
    const float* a2s = (const float*)d_in[7];
    const float* a2d = (const float*)d_in[8];
    const float* b2  = (const float*)d_in[9];
    const float* W3  = (const float*)d_in[10];
    const float* a3s = (const float*)d_in[11];
    const float* a3d = (const float*)d_in[12];
    const float* b3  = (const float*)d_in[13];
    const float* S   = (const float*)d_in[14];

    int N = in_sizes[0] / 128;
    int E = in_sizes[1] / 2;

    float *hb, *actb, *pas, *pad_, *pst, *pgm;
    int *pcsrc, *prp, *pcur, *pcnt, *ptscan, *pbsum;
    cudaGetSymbolAddress((void**)&hb,     g_hbuf);
    cudaGetSymbolAddress((void**)&actb,   g_actbuf);
    cudaGetSymbolAddress((void**)&pas,    g_as);
    cudaGetSymbolAddress((void**)&pad_,   g_ad);
    cudaGetSymbolAddress((void**)&pst,    g_ST);
    cudaGetSymbolAddress((void**)&pgm,    g_gmax);
    cudaGetSymbolAddress((void**)&pcsrc,  g_csrc);
    cudaGetSymbolAddress((void**)&prp,    g_rp);
    cudaGetSymbolAddress((void**)&pcur,   g_cur);
    cudaGetSymbolAddress((void**)&pcnt,   g_cnt);
    cudaGetSymbolAddress((void**)&ptscan, g_tscan);
    cudaGetSymbolAddress((void**)&pbsum,  g_bsum);

    const int smem128 = mma_smem_bytes(128, 128);
    const int smem64  = mma_smem_bytes(128, 64);
    cudaFuncSetAttribute(mma_gemm_kernel<128,128,64,32,true>,
                         cudaFuncAttributeMaxDynamicSharedMemorySize, smem128);
    cudaFuncSetAttribute(mma_gemm_kernel<128,128,64,32,false>,
                         cudaFuncAttributeMaxDynamicSharedMemorySize, smem128);
    cudaFuncSetAttribute(mma_gemm_kernel<128,64,32,32,true>,
                         cudaFuncAttributeMaxDynamicSharedMemorySize, smem64);

    init_gmax_kernel<<<1, 32>>>(pgm);

    // --- fork a side stream for the CSR build ---
    cudaStream_t s2;
    cudaStreamCreateWithFlags(&s2, cudaStreamNonBlocking);
    cudaEvent_t evFork, evJoin;
    cudaEventCreateWithFlags(&evFork, cudaEventDisableTiming);
    cudaEventCreateWithFlags(&evJoin, cudaEventDisableTiming);

    cudaEventRecord(evFork, 0);
    cudaStreamWaitEvent(s2, evFork, 0);

    int nb = cdiv(N, SCAN_B);

    zero_cnt_kernel<<<cdiv(N,256), 256, 0, s2>>>(pcnt, N);
    hist_kernel<<<cdiv(cdiv(E,4),256), 256, 0, s2>>>(ei, pcnt, E);
    scan_phase1<<<nb, SCAN_B, 0, s2>>>(pcnt, ptscan, pbsum, N);
    scan_phase2<<<1, NB_MAX, 0, s2>>>(pbsum, nb);
    scan_phase3<<<nb, SCAN_B, 0, s2>>>(pcnt, ptscan, pbsum, prp, pcur, N);
    scatter_kernel<<<cdiv(cdiv(E,4),256), 256, 0, s2>>>(ei, pcur, pcsrc, E);
    transpose_S_kernel<<<cdiv(64*512,256), 256, 0, s2>>>(S, pst);
    cudaEventRecord(evJoin, s2);

    int gm   = cdiv(N, 128);
    int gw   = cdiv(N * 32, 256);   // F=128: warp per node
    int gw64 = cdiv(N * 16, 256);   // F=64: half-warp per node

    // --- layer 1 GEMM runs concurrently with the CSR build ---
    mma_gemm_kernel<128,128,64,32,true><<<dim3(gm,1), 256, smem128>>>(
        x, W1, hb, a1s, a1d, pas, pad_, pgm + 0, N, 128, 128);

    cudaStreamWaitEvent(0, evJoin, 0);

    attn_agg_kernel<128><<<gw, 256>>>(prp, pcsrc, pas, pad_, pgm + 0, hb, b1, actb, N, 1);

    // --- layer 2 ---
    mma_gemm_kernel<128,128,64,32,true><<<dim3(gm,1), 256, smem128>>>(
        actb, W2, hb, a2s, a2d, pas, pad_, pgm + 1, N, 128, 128);
    attn_agg_kernel<128><<<gw, 256>>>(prp, pcsrc, pas, pad_, pgm + 1, hb, b2, actb, N, 1);

    // --- layer 3 (F=64, no inter-layer activation) ---
    mma_gemm_kernel<128,64,32,32,true><<<dim3(gm,1), 256, smem64>>>(
        actb, W3, hb, a3s, a3d, pas, pad_, pgm + 2, N, 64, 128);
    attn_agg_kernel<64><<<gw64, 256>>>(prp, pcsrc, pas, pad_, pgm + 2, hb, b3, actb, N, 0);

    // --- final projection: [N,64] @ [64,512] ---
    mma_gemm_kernel<128,128,64,32,false><<<dim3(gm,4), 256, smem128>>>(
        actb, pst, (float*)d_out, nullptr, nullptr, nullptr, nullptr, nullptr,
        N, 512, 64);
}